// round 1
// baseline (speedup 1.0000x reference)
#include <cuda_runtime.h>

#define D_MODEL 1024
#define NH 16
#define HD 64
#define BB 4
#define SS 1024
#define MROWS (BB * SS)   // 4096

// ---- scratch (device globals: allocation-free per harness rules) ----
__device__ float g_q[(size_t)BB * NH * SS * HD];          // 16 MB
__device__ float g_k[(size_t)BB * NH * SS * HD];          // 16 MB
__device__ float g_v[(size_t)BB * NH * SS * HD];          // 16 MB
__device__ float g_s[(size_t)BB * NH * SS * SS];          // 268 MB scores

// ============================================================================
// Kernel 1: fused QKV projection.  out = in @ W^T + b, written head-major.
// 128x128 tile, 256 threads, 8x8 microtile, TK=16.
// ============================================================================
__global__ __launch_bounds__(256) void proj_kernel(
    const float* __restrict__ x, const float* __restrict__ y,
    const float* __restrict__ z,
    const float* __restrict__ wq, const float* __restrict__ bq,
    const float* __restrict__ wk, const float* __restrict__ bk,
    const float* __restrict__ wv, const float* __restrict__ bv)
{
    const int which = blockIdx.z;
    const float* A    = which == 0 ? x  : (which == 1 ? y  : z);
    const float* W    = which == 0 ? wq : (which == 1 ? wk : wv);
    const float* bias = which == 0 ? bq : (which == 1 ? bk : bv);
    float* out        = which == 0 ? g_q : (which == 1 ? g_k : g_v);

    __shared__ float As[16][128];
    __shared__ float Bs[16][128];

    const int tid = threadIdx.x;
    const int ty = tid >> 4, tx = tid & 15;
    const int m0 = blockIdx.y * 128;
    const int n0 = blockIdx.x * 128;

    float acc[8][8];
#pragma unroll
    for (int i = 0; i < 8; i++)
#pragma unroll
        for (int j = 0; j < 8; j++) acc[i][j] = 0.f;

    for (int k0 = 0; k0 < D_MODEL; k0 += 16) {
#pragma unroll
        for (int l = 0; l < 2; l++) {
            int idx = tid + l * 256;      // 0..511
            int r = idx >> 2;             // 0..127
            int kc = (idx & 3) * 4;       // 0,4,8,12
            float4 a4 = *(const float4*)(A + (size_t)(m0 + r) * D_MODEL + k0 + kc);
            As[kc + 0][r] = a4.x; As[kc + 1][r] = a4.y;
            As[kc + 2][r] = a4.z; As[kc + 3][r] = a4.w;
            float4 b4 = *(const float4*)(W + (size_t)(n0 + r) * D_MODEL + k0 + kc);
            Bs[kc + 0][r] = b4.x; Bs[kc + 1][r] = b4.y;
            Bs[kc + 2][r] = b4.z; Bs[kc + 3][r] = b4.w;
        }
        __syncthreads();
#pragma unroll
        for (int k = 0; k < 16; k++) {
            float a[8], b[8];
            *(float4*)&a[0] = *(const float4*)&As[k][ty * 8];
            *(float4*)&a[4] = *(const float4*)&As[k][ty * 8 + 4];
            *(float4*)&b[0] = *(const float4*)&Bs[k][tx * 8];
            *(float4*)&b[4] = *(const float4*)&Bs[k][tx * 8 + 4];
#pragma unroll
            for (int i = 0; i < 8; i++)
#pragma unroll
                for (int j = 0; j < 8; j++) acc[i][j] += a[i] * b[j];
        }
        __syncthreads();
    }

    // write with bias into [B, H, S, HD]
#pragma unroll
    for (int i = 0; i < 8; i++) {
        const int gm = m0 + ty * 8 + i;
        const int b = gm >> 10, s = gm & 1023;
#pragma unroll
        for (int j = 0; j < 8; j++) {
            const int gn = n0 + tx * 8 + j;
            const int h = gn >> 6, d = gn & 63;
            out[(((size_t)(b * NH + h)) * SS + s) * HD + d] = acc[i][j] + bias[gn];
        }
    }
}

// ============================================================================
// Kernel 2: per-head scores = (Q @ K^T) * (1/32).  128x128 tile, K-dim = 64.
// ============================================================================
__global__ __launch_bounds__(256) void qk_kernel()
{
    const int bh = blockIdx.z;
    const float* Q = g_q + (size_t)bh * SS * HD;
    const float* K = g_k + (size_t)bh * SS * HD;
    float* Sp = g_s + (size_t)bh * SS * SS;

    __shared__ float As[16][128];
    __shared__ float Bs[16][128];

    const int tid = threadIdx.x;
    const int ty = tid >> 4, tx = tid & 15;
    const int m0 = blockIdx.y * 128;
    const int n0 = blockIdx.x * 128;

    float acc[8][8];
#pragma unroll
    for (int i = 0; i < 8; i++)
#pragma unroll
        for (int j = 0; j < 8; j++) acc[i][j] = 0.f;

    for (int k0 = 0; k0 < HD; k0 += 16) {
#pragma unroll
        for (int l = 0; l < 2; l++) {
            int idx = tid + l * 256;
            int r = idx >> 2;
            int kc = (idx & 3) * 4;
            float4 a4 = *(const float4*)(Q + (size_t)(m0 + r) * HD + k0 + kc);
            As[kc + 0][r] = a4.x; As[kc + 1][r] = a4.y;
            As[kc + 2][r] = a4.z; As[kc + 3][r] = a4.w;
            float4 b4 = *(const float4*)(K + (size_t)(n0 + r) * HD + k0 + kc);
            Bs[kc + 0][r] = b4.x; Bs[kc + 1][r] = b4.y;
            Bs[kc + 2][r] = b4.z; Bs[kc + 3][r] = b4.w;
        }
        __syncthreads();
#pragma unroll
        for (int k = 0; k < 16; k++) {
            float a[8], b[8];
            *(float4*)&a[0] = *(const float4*)&As[k][ty * 8];
            *(float4*)&a[4] = *(const float4*)&As[k][ty * 8 + 4];
            *(float4*)&b[0] = *(const float4*)&Bs[k][tx * 8];
            *(float4*)&b[4] = *(const float4*)&Bs[k][tx * 8 + 4];
#pragma unroll
            for (int i = 0; i < 8; i++)
#pragma unroll
                for (int j = 0; j < 8; j++) acc[i][j] += a[i] * b[j];
        }
        __syncthreads();
    }

    const float scale = 0.03125f;  // 1/sqrt(1024)
#pragma unroll
    for (int i = 0; i < 8; i++) {
        const int gm = m0 + ty * 8 + i;
        float* row = Sp + (size_t)gm * SS + n0 + tx * 8;
        float4 o0 = make_float4(acc[i][0] * scale, acc[i][1] * scale,
                                acc[i][2] * scale, acc[i][3] * scale);
        float4 o1 = make_float4(acc[i][4] * scale, acc[i][5] * scale,
                                acc[i][6] * scale, acc[i][7] * scale);
        *(float4*)(row)     = o0;
        *(float4*)(row + 4) = o1;
    }
}

// ============================================================================
// Kernel 3: row softmax, then += mask (mask added AFTER softmax, per ref).
// One block (256 threads) per row of 1024.
// ============================================================================
__global__ __launch_bounds__(256) void softmax_kernel(const float* __restrict__ mask)
{
    const size_t row = blockIdx.x;          // 0..65535
    float* p = g_s + row * SS;
    const int tid = threadIdx.x;

    float4 v = *(const float4*)(p + tid * 4);

    __shared__ float red[8];

    float lm = fmaxf(fmaxf(v.x, v.y), fmaxf(v.z, v.w));
#pragma unroll
    for (int o = 16; o > 0; o >>= 1) lm = fmaxf(lm, __shfl_xor_sync(0xffffffffu, lm, o));
    if ((tid & 31) == 0) red[tid >> 5] = lm;
    __syncthreads();
    float rmax = red[0];
#pragma unroll
    for (int i = 1; i < 8; i++) rmax = fmaxf(rmax, red[i]);
    __syncthreads();

    v.x = __expf(v.x - rmax);
    v.y = __expf(v.y - rmax);
    v.z = __expf(v.z - rmax);
    v.w = __expf(v.w - rmax);

    float ls = v.x + v.y + v.z + v.w;
#pragma unroll
    for (int o = 16; o > 0; o >>= 1) ls += __shfl_xor_sync(0xffffffffu, ls, o);
    if ((tid & 31) == 0) red[tid >> 5] = ls;
    __syncthreads();
    float total = 0.f;
#pragma unroll
    for (int i = 0; i < 8; i++) total += red[i];
    const float inv = 1.0f / total;

    const int q = (int)(row & (SS - 1));
    float4 mv = *(const float4*)(mask + (size_t)q * SS + tid * 4);
    float4 o;
    o.x = v.x * inv + mv.x;
    o.y = v.y * inv + mv.y;
    o.z = v.z * inv + mv.z;
    o.w = v.w * inv + mv.w;
    *(float4*)(p + tid * 4) = o;
}

// ============================================================================
// Kernel 4: per-head out = P @ V, written into final [B, S, D] layout.
// 128x64 tile, 256 threads, 8x4 microtile, TK=16.
// ============================================================================
__global__ __launch_bounds__(256) void pv_kernel(float* __restrict__ out)
{
    const int bh = blockIdx.y;
    const int b = bh >> 4, h = bh & 15;
    const float* P = g_s + (size_t)bh * SS * SS;
    const float* V = g_v + (size_t)bh * SS * HD;

    __shared__ float As[16][128];   // P tile transposed: As[k][m]
    __shared__ float Bs[16][64];    // V tile direct

    const int tid = threadIdx.x;
    const int ty = tid >> 4, tx = tid & 15;
    const int m0 = blockIdx.x * 128;

    float acc[8][4];
#pragma unroll
    for (int i = 0; i < 8; i++)
#pragma unroll
        for (int j = 0; j < 4; j++) acc[i][j] = 0.f;

    for (int k0 = 0; k0 < SS; k0 += 16) {
#pragma unroll
        for (int l = 0; l < 2; l++) {
            int idx = tid + l * 256;
            int r = idx >> 2;
            int kc = (idx & 3) * 4;
            float4 a4 = *(const float4*)(P + (size_t)(m0 + r) * SS + k0 + kc);
            As[kc + 0][r] = a4.x; As[kc + 1][r] = a4.y;
            As[kc + 2][r] = a4.z; As[kc + 3][r] = a4.w;
        }
        {
            int r = tid >> 4;              // 0..15
            int c4 = (tid & 15) * 4;       // 0..60
            *(float4*)&Bs[r][c4] = *(const float4*)(V + (size_t)(k0 + r) * HD + c4);
        }
        __syncthreads();
#pragma unroll
        for (int k = 0; k < 16; k++) {
            float a[8], bb[4];
            *(float4*)&a[0] = *(const float4*)&As[k][ty * 8];
            *(float4*)&a[4] = *(const float4*)&As[k][ty * 8 + 4];
            *(float4*)&bb[0] = *(const float4*)&Bs[k][tx * 4];
#pragma unroll
            for (int i = 0; i < 8; i++)
#pragma unroll
                for (int j = 0; j < 4; j++) acc[i][j] += a[i] * bb[j];
        }
        __syncthreads();
    }

#pragma unroll
    for (int i = 0; i < 8; i++) {
        const int s = m0 + ty * 8 + i;
        float4 o4 = make_float4(acc[i][0], acc[i][1], acc[i][2], acc[i][3]);
        *(float4*)(out + ((size_t)b * SS + s) * D_MODEL + h * HD + tx * 4) = o4;
    }
}

// ============================================================================
extern "C" void kernel_launch(void* const* d_in, const int* in_sizes, int n_in,
                              void* d_out, int out_size)
{
    const float* x    = (const float*)d_in[0];
    const float* y    = (const float*)d_in[1];
    const float* z    = (const float*)d_in[2];
    const float* mask = (const float*)d_in[3];
    const float* wq   = (const float*)d_in[4];
    const float* bq   = (const float*)d_in[5];
    const float* wk   = (const float*)d_in[6];
    const float* bk   = (const float*)d_in[7];
    const float* wv   = (const float*)d_in[8];
    const float* bv   = (const float*)d_in[9];
    float* out = (float*)d_out;

    dim3 g1(D_MODEL / 128, MROWS / 128, 3);
    proj_kernel<<<g1, 256>>>(x, y, z, wq, bq, wk, bk, wv, bv);

    dim3 g2(SS / 128, SS / 128, BB * NH);
    qk_kernel<<<g2, 256>>>();

    softmax_kernel<<<BB * NH * SS, 256>>>(mask);

    dim3 g4(SS / 128, BB * NH);
    pv_kernel<<<g4, 256>>>(out);
}

// round 2
// speedup vs baseline: 2.3195x; 2.3195x over previous
#include <cuda_runtime.h>
#include <cstdint>

#define D_MODEL 1024
#define NH 16
#define HD 64
#define BB 4
#define SS 1024
#define MROWS (BB * SS)   // 4096

// ---- scratch (device globals: allocation-free per harness rules) ----
__device__ float g_q[(size_t)BB * NH * SS * HD];          // 16 MB
__device__ float g_k[(size_t)BB * NH * SS * HD];          // 16 MB
__device__ float g_v[(size_t)BB * NH * SS * HD];          // 16 MB
__device__ float g_s[(size_t)BB * NH * SS * SS];          // 268 MB scores

// ---------------------------------------------------------------------------
// helpers
// ---------------------------------------------------------------------------
__device__ __forceinline__ uint32_t f2tf32(float x) {
    uint32_t r;
    asm("cvt.rna.tf32.f32 %0, %1;" : "=r"(r) : "f"(x));
    return r;
}

__device__ __forceinline__ void mma_tf32(float c[4], const uint32_t a[4], const uint32_t b[2]) {
    asm("mma.sync.aligned.m16n8k8.row.col.f32.tf32.tf32.f32 "
        "{%0,%1,%2,%3}, {%4,%5,%6,%7}, {%8,%9}, {%0,%1,%2,%3};"
        : "+f"(c[0]), "+f"(c[1]), "+f"(c[2]), "+f"(c[3])
        : "r"(a[0]), "r"(a[1]), "r"(a[2]), "r"(a[3]), "r"(b[0]), "r"(b[1]));
}

// ===========================================================================
// Kernel 1: fused QKV projection with tf32 MMA.
// C[M=4096,N=1024] = A[M,K=1024] @ W^T + bias, written head-major [B,H,S,hd].
// Block tile 128x128x32, 8 warps, warp tile 64x32.
// ===========================================================================
__global__ __launch_bounds__(256) void proj_mma(
    const float* __restrict__ x, const float* __restrict__ y,
    const float* __restrict__ z,
    const float* __restrict__ wq, const float* __restrict__ bq,
    const float* __restrict__ wk, const float* __restrict__ bk,
    const float* __restrict__ wv, const float* __restrict__ bv)
{
    const int which = blockIdx.z;
    const float* A    = which == 0 ? x  : (which == 1 ? y  : z);
    const float* W    = which == 0 ? wq : (which == 1 ? wk : wv);
    const float* bias = which == 0 ? bq : (which == 1 ? bk : bv);
    float* out        = which == 0 ? g_q : (which == 1 ? g_k : g_v);

    __shared__ uint32_t As[128 * 36];   // [m][k] ld=36 (tf32 bits)
    __shared__ uint32_t Bs[128 * 36];   // [n][k] ld=36

    const int tid  = threadIdx.x;
    const int lane = tid & 31;
    const int wid  = tid >> 5;
    const int wm   = wid >> 2;          // 0..1 -> 64 rows each
    const int wn   = wid & 3;           // 0..3 -> 32 cols each
    const int m0   = blockIdx.y * 128;
    const int n0   = blockIdx.x * 128;
    const int lr   = lane >> 2;         // 0..7
    const int lc   = lane & 3;          // 0..3

    float acc[4][4][4];
#pragma unroll
    for (int i = 0; i < 4; i++)
#pragma unroll
        for (int j = 0; j < 4; j++)
#pragma unroll
            for (int r = 0; r < 4; r++) acc[i][j][r] = 0.f;

    for (int k0 = 0; k0 < D_MODEL; k0 += 32) {
#pragma unroll
        for (int i = 0; i < 4; i++) {
            int idx = tid + i * 256;
            int r = idx >> 3;
            int c = (idx & 7) << 2;
            float4 a4 = *(const float4*)(A + (size_t)(m0 + r) * D_MODEL + k0 + c);
            uint32_t* sa = &As[r * 36 + c];
            sa[0] = f2tf32(a4.x); sa[1] = f2tf32(a4.y);
            sa[2] = f2tf32(a4.z); sa[3] = f2tf32(a4.w);
            float4 b4 = *(const float4*)(W + (size_t)(n0 + r) * D_MODEL + k0 + c);
            uint32_t* sb = &Bs[r * 36 + c];
            sb[0] = f2tf32(b4.x); sb[1] = f2tf32(b4.y);
            sb[2] = f2tf32(b4.z); sb[3] = f2tf32(b4.w);
        }
        __syncthreads();
#pragma unroll
        for (int ks = 0; ks < 32; ks += 8) {
            uint32_t af[4][4], bf[4][2];
#pragma unroll
            for (int ms = 0; ms < 4; ms++) {
                const uint32_t* p = &As[(wm * 64 + ms * 16 + lr) * 36 + ks + lc];
                af[ms][0] = p[0];
                af[ms][1] = p[8 * 36];
                af[ms][2] = p[4];
                af[ms][3] = p[8 * 36 + 4];
            }
#pragma unroll
            for (int ns = 0; ns < 4; ns++) {
                const uint32_t* p = &Bs[(wn * 32 + ns * 8 + lr) * 36 + ks + lc];
                bf[ns][0] = p[0];
                bf[ns][1] = p[4];
            }
#pragma unroll
            for (int ms = 0; ms < 4; ms++)
#pragma unroll
                for (int ns = 0; ns < 4; ns++)
                    mma_tf32(acc[ms][ns], af[ms], bf[ns]);
        }
        __syncthreads();
    }

    // epilogue: bias + write head-major [B,H,S,hd]
#pragma unroll
    for (int ms = 0; ms < 4; ms++) {
#pragma unroll
        for (int ns = 0; ns < 4; ns++) {
            int gm = m0 + wm * 64 + ms * 16 + lr;
            int gn = n0 + wn * 32 + ns * 8 + (lc << 1);
            float bx = bias[gn], by = bias[gn + 1];
            int h = gn >> 6, d = gn & 63;
            {
                int b = gm >> 10, s = gm & 1023;
                float2 v = make_float2(acc[ms][ns][0] + bx, acc[ms][ns][1] + by);
                *(float2*)(out + (((size_t)(b * NH + h)) * SS + s) * HD + d) = v;
            }
            {
                int gm2 = gm + 8;
                int b = gm2 >> 10, s = gm2 & 1023;
                float2 v = make_float2(acc[ms][ns][2] + bx, acc[ms][ns][3] + by);
                *(float2*)(out + (((size_t)(b * NH + h)) * SS + s) * HD + d) = v;
            }
        }
    }
}

// ===========================================================================
// Kernel 2: scores = (Q @ K^T) * (1/32), tf32 MMA. Per head M=N=1024, K=64.
// ===========================================================================
__global__ __launch_bounds__(256) void qk_mma()
{
    const int bh = blockIdx.z;
    const float* Q = g_q + (size_t)bh * SS * HD;
    const float* K = g_k + (size_t)bh * SS * HD;
    float* Sp = g_s + (size_t)bh * SS * SS;

    __shared__ uint32_t As[128 * 36];
    __shared__ uint32_t Bs[128 * 36];

    const int tid  = threadIdx.x;
    const int lane = tid & 31;
    const int wid  = tid >> 5;
    const int wm   = wid >> 2;
    const int wn   = wid & 3;
    const int m0   = blockIdx.y * 128;
    const int n0   = blockIdx.x * 128;
    const int lr   = lane >> 2;
    const int lc   = lane & 3;

    float acc[4][4][4];
#pragma unroll
    for (int i = 0; i < 4; i++)
#pragma unroll
        for (int j = 0; j < 4; j++)
#pragma unroll
            for (int r = 0; r < 4; r++) acc[i][j][r] = 0.f;

    for (int k0 = 0; k0 < HD; k0 += 32) {
#pragma unroll
        for (int i = 0; i < 4; i++) {
            int idx = tid + i * 256;
            int r = idx >> 3;
            int c = (idx & 7) << 2;
            float4 a4 = *(const float4*)(Q + (size_t)(m0 + r) * HD + k0 + c);
            uint32_t* sa = &As[r * 36 + c];
            sa[0] = f2tf32(a4.x); sa[1] = f2tf32(a4.y);
            sa[2] = f2tf32(a4.z); sa[3] = f2tf32(a4.w);
            float4 b4 = *(const float4*)(K + (size_t)(n0 + r) * HD + k0 + c);
            uint32_t* sb = &Bs[r * 36 + c];
            sb[0] = f2tf32(b4.x); sb[1] = f2tf32(b4.y);
            sb[2] = f2tf32(b4.z); sb[3] = f2tf32(b4.w);
        }
        __syncthreads();
#pragma unroll
        for (int ks = 0; ks < 32; ks += 8) {
            uint32_t af[4][4], bf[4][2];
#pragma unroll
            for (int ms = 0; ms < 4; ms++) {
                const uint32_t* p = &As[(wm * 64 + ms * 16 + lr) * 36 + ks + lc];
                af[ms][0] = p[0];
                af[ms][1] = p[8 * 36];
                af[ms][2] = p[4];
                af[ms][3] = p[8 * 36 + 4];
            }
#pragma unroll
            for (int ns = 0; ns < 4; ns++) {
                const uint32_t* p = &Bs[(wn * 32 + ns * 8 + lr) * 36 + ks + lc];
                bf[ns][0] = p[0];
                bf[ns][1] = p[4];
            }
#pragma unroll
            for (int ms = 0; ms < 4; ms++)
#pragma unroll
                for (int ns = 0; ns < 4; ns++)
                    mma_tf32(acc[ms][ns], af[ms], bf[ns]);
        }
        __syncthreads();
    }

    const float scale = 0.03125f;  // 1/sqrt(1024)
#pragma unroll
    for (int ms = 0; ms < 4; ms++) {
#pragma unroll
        for (int ns = 0; ns < 4; ns++) {
            int gm = m0 + wm * 64 + ms * 16 + lr;
            int gn = n0 + wn * 32 + ns * 8 + (lc << 1);
            float2 v0 = make_float2(acc[ms][ns][0] * scale, acc[ms][ns][1] * scale);
            float2 v1 = make_float2(acc[ms][ns][2] * scale, acc[ms][ns][3] * scale);
            *(float2*)(Sp + (size_t)gm * SS + gn) = v0;
            *(float2*)(Sp + (size_t)(gm + 8) * SS + gn) = v1;
        }
    }
}

// ===========================================================================
// Kernel 3: row softmax, then += mask (mask added AFTER softmax, per ref).
// ===========================================================================
__global__ __launch_bounds__(256) void softmax_kernel(const float* __restrict__ mask)
{
    const size_t row = blockIdx.x;          // 0..65535
    float* p = g_s + row * SS;
    const int tid = threadIdx.x;

    float4 v = *(const float4*)(p + tid * 4);

    __shared__ float red[8];

    float lm = fmaxf(fmaxf(v.x, v.y), fmaxf(v.z, v.w));
#pragma unroll
    for (int o = 16; o > 0; o >>= 1) lm = fmaxf(lm, __shfl_xor_sync(0xffffffffu, lm, o));
    if ((tid & 31) == 0) red[tid >> 5] = lm;
    __syncthreads();
    float rmax = red[0];
#pragma unroll
    for (int i = 1; i < 8; i++) rmax = fmaxf(rmax, red[i]);
    __syncthreads();

    v.x = __expf(v.x - rmax);
    v.y = __expf(v.y - rmax);
    v.z = __expf(v.z - rmax);
    v.w = __expf(v.w - rmax);

    float ls = v.x + v.y + v.z + v.w;
#pragma unroll
    for (int o = 16; o > 0; o >>= 1) ls += __shfl_xor_sync(0xffffffffu, ls, o);
    if ((tid & 31) == 0) red[tid >> 5] = ls;
    __syncthreads();
    float total = 0.f;
#pragma unroll
    for (int i = 0; i < 8; i++) total += red[i];
    const float inv = 1.0f / total;

    const int q = (int)(row & (SS - 1));
    float4 mv = *(const float4*)(mask + (size_t)q * SS + tid * 4);
    float4 o;
    o.x = v.x * inv + mv.x;
    o.y = v.y * inv + mv.y;
    o.z = v.z * inv + mv.z;
    o.w = v.w * inv + mv.w;
    *(float4*)(p + tid * 4) = o;
}

// ===========================================================================
// Kernel 4: out = P @ V per head, tf32 MMA. Block tile 128x64x32, warp 32x32.
// ===========================================================================
__global__ __launch_bounds__(256) void pv_mma(float* __restrict__ out)
{
    const int bh = blockIdx.y;
    const int b = bh >> 4, h = bh & 15;
    const float* P = g_s + (size_t)bh * SS * SS;
    const float* V = g_v + (size_t)bh * SS * HD;

    __shared__ uint32_t As[128 * 36];   // P tile [m][k] ld=36
    __shared__ uint32_t Vs[32 * 72];    // V tile [k][n] ld=72

    const int tid  = threadIdx.x;
    const int lane = tid & 31;
    const int wid  = tid >> 5;
    const int wm   = wid >> 1;          // 0..3 -> 32 rows each
    const int wn   = wid & 1;           // 0..1 -> 32 cols each
    const int m0   = blockIdx.x * 128;
    const int lr   = lane >> 2;
    const int lc   = lane & 3;

    float acc[2][4][4];
#pragma unroll
    for (int i = 0; i < 2; i++)
#pragma unroll
        for (int j = 0; j < 4; j++)
#pragma unroll
            for (int r = 0; r < 4; r++) acc[i][j][r] = 0.f;

    for (int k0 = 0; k0 < SS; k0 += 32) {
#pragma unroll
        for (int i = 0; i < 4; i++) {
            int idx = tid + i * 256;
            int r = idx >> 3;
            int c = (idx & 7) << 2;
            float4 a4 = *(const float4*)(P + (size_t)(m0 + r) * SS + k0 + c);
            uint32_t* sa = &As[r * 36 + c];
            sa[0] = f2tf32(a4.x); sa[1] = f2tf32(a4.y);
            sa[2] = f2tf32(a4.z); sa[3] = f2tf32(a4.w);
        }
#pragma unroll
        for (int i = 0; i < 2; i++) {
            int idx = tid + i * 256;       // 0..511
            int k = idx >> 4;              // 0..31
            int n = (idx & 15) << 2;       // 0..60
            float4 b4 = *(const float4*)(V + (size_t)(k0 + k) * HD + n);
            uint32_t* sb = &Vs[k * 72 + n];
            sb[0] = f2tf32(b4.x); sb[1] = f2tf32(b4.y);
            sb[2] = f2tf32(b4.z); sb[3] = f2tf32(b4.w);
        }
        __syncthreads();
#pragma unroll
        for (int ks = 0; ks < 32; ks += 8) {
            uint32_t af[2][4], bf[4][2];
#pragma unroll
            for (int ms = 0; ms < 2; ms++) {
                const uint32_t* p = &As[(wm * 32 + ms * 16 + lr) * 36 + ks + lc];
                af[ms][0] = p[0];
                af[ms][1] = p[8 * 36];
                af[ms][2] = p[4];
                af[ms][3] = p[8 * 36 + 4];
            }
#pragma unroll
            for (int ns = 0; ns < 4; ns++) {
                const uint32_t* p = &Vs[(ks + lc) * 72 + wn * 32 + ns * 8 + lr];
                bf[ns][0] = p[0];
                bf[ns][1] = p[4 * 72];
            }
#pragma unroll
            for (int ms = 0; ms < 2; ms++)
#pragma unroll
                for (int ns = 0; ns < 4; ns++)
                    mma_tf32(acc[ms][ns], af[ms], bf[ns]);
        }
        __syncthreads();
    }

#pragma unroll
    for (int ms = 0; ms < 2; ms++) {
#pragma unroll
        for (int ns = 0; ns < 4; ns++) {
            int gm = m0 + wm * 32 + ms * 16 + lr;
            int gn = wn * 32 + ns * 8 + (lc << 1);   // col within head (0..63)
            float2 v0 = make_float2(acc[ms][ns][0], acc[ms][ns][1]);
            float2 v1 = make_float2(acc[ms][ns][2], acc[ms][ns][3]);
            *(float2*)(out + ((size_t)b * SS + gm) * D_MODEL + h * HD + gn) = v0;
            *(float2*)(out + ((size_t)b * SS + gm + 8) * D_MODEL + h * HD + gn) = v1;
        }
    }
}

// ===========================================================================
extern "C" void kernel_launch(void* const* d_in, const int* in_sizes, int n_in,
                              void* d_out, int out_size)
{
    const float* x    = (const float*)d_in[0];
    const float* y    = (const float*)d_in[1];
    const float* z    = (const float*)d_in[2];
    const float* mask = (const float*)d_in[3];
    const float* wq   = (const float*)d_in[4];
    const float* bq   = (const float*)d_in[5];
    const float* wk   = (const float*)d_in[6];
    const float* bk   = (const float*)d_in[7];
    const float* wv   = (const float*)d_in[8];
    const float* bv   = (const float*)d_in[9];
    float* out = (float*)d_out;

    dim3 g1(D_MODEL / 128, MROWS / 128, 3);
    proj_mma<<<g1, 256>>>(x, y, z, wq, bq, wk, bk, wv, bv);

    dim3 g2(SS / 128, SS / 128, BB * NH);
    qk_mma<<<g2, 256>>>();

    softmax_kernel<<<BB * NH * SS, 256>>>(mask);

    dim3 g4(SS / 128, BB * NH);
    pv_mma<<<g4, 256>>>(out);
}

// round 3
// speedup vs baseline: 2.4786x; 1.0686x over previous
#include <cuda_runtime.h>
#include <cstdint>

#define D_MODEL 1024
#define NH 16
#define HD 64
#define BB 4
#define SS 1024
#define MROWS (BB * SS)   // 4096

// ---- scratch ----
__device__ float g_q[(size_t)BB * NH * SS * HD];          // 16 MB
__device__ float g_k[(size_t)BB * NH * SS * HD];          // 16 MB
__device__ float g_v[(size_t)BB * NH * SS * HD];          // 16 MB

// ---------------------------------------------------------------------------
__device__ __forceinline__ uint32_t f2tf32(float x) {
    uint32_t r;
    asm("cvt.rna.tf32.f32 %0, %1;" : "=r"(r) : "f"(x));
    return r;
}

__device__ __forceinline__ void mma_tf32(float c[4], const uint32_t a[4], const uint32_t b[2]) {
    asm("mma.sync.aligned.m16n8k8.row.col.f32.tf32.tf32.f32 "
        "{%0,%1,%2,%3}, {%4,%5,%6,%7}, {%8,%9}, {%0,%1,%2,%3};"
        : "+f"(c[0]), "+f"(c[1]), "+f"(c[2]), "+f"(c[3])
        : "r"(a[0]), "r"(a[1]), "r"(a[2]), "r"(a[3]), "r"(b[0]), "r"(b[1]));
}

// ===========================================================================
// Kernel 1: fused QKV projection with tf32 MMA (unchanged from R2).
// ===========================================================================
__global__ __launch_bounds__(256) void proj_mma(
    const float* __restrict__ x, const float* __restrict__ y,
    const float* __restrict__ z,
    const float* __restrict__ wq, const float* __restrict__ bq,
    const float* __restrict__ wk, const float* __restrict__ bk,
    const float* __restrict__ wv, const float* __restrict__ bv)
{
    const int which = blockIdx.z;
    const float* A    = which == 0 ? x  : (which == 1 ? y  : z);
    const float* W    = which == 0 ? wq : (which == 1 ? wk : wv);
    const float* bias = which == 0 ? bq : (which == 1 ? bk : bv);
    float* out        = which == 0 ? g_q : (which == 1 ? g_k : g_v);

    __shared__ uint32_t As[128 * 36];
    __shared__ uint32_t Bs[128 * 36];

    const int tid  = threadIdx.x;
    const int lane = tid & 31;
    const int wid  = tid >> 5;
    const int wm   = wid >> 2;
    const int wn   = wid & 3;
    const int m0   = blockIdx.y * 128;
    const int n0   = blockIdx.x * 128;
    const int lr   = lane >> 2;
    const int lc   = lane & 3;

    float acc[4][4][4];
#pragma unroll
    for (int i = 0; i < 4; i++)
#pragma unroll
        for (int j = 0; j < 4; j++)
#pragma unroll
            for (int r = 0; r < 4; r++) acc[i][j][r] = 0.f;

    for (int k0 = 0; k0 < D_MODEL; k0 += 32) {
#pragma unroll
        for (int i = 0; i < 4; i++) {
            int idx = tid + i * 256;
            int r = idx >> 3;
            int c = (idx & 7) << 2;
            float4 a4 = *(const float4*)(A + (size_t)(m0 + r) * D_MODEL + k0 + c);
            uint32_t* sa = &As[r * 36 + c];
            sa[0] = f2tf32(a4.x); sa[1] = f2tf32(a4.y);
            sa[2] = f2tf32(a4.z); sa[3] = f2tf32(a4.w);
            float4 b4 = *(const float4*)(W + (size_t)(n0 + r) * D_MODEL + k0 + c);
            uint32_t* sb = &Bs[r * 36 + c];
            sb[0] = f2tf32(b4.x); sb[1] = f2tf32(b4.y);
            sb[2] = f2tf32(b4.z); sb[3] = f2tf32(b4.w);
        }
        __syncthreads();
#pragma unroll
        for (int ks = 0; ks < 32; ks += 8) {
            uint32_t af[4][4], bf[4][2];
#pragma unroll
            for (int ms = 0; ms < 4; ms++) {
                const uint32_t* p = &As[(wm * 64 + ms * 16 + lr) * 36 + ks + lc];
                af[ms][0] = p[0];
                af[ms][1] = p[8 * 36];
                af[ms][2] = p[4];
                af[ms][3] = p[8 * 36 + 4];
            }
#pragma unroll
            for (int ns = 0; ns < 4; ns++) {
                const uint32_t* p = &Bs[(wn * 32 + ns * 8 + lr) * 36 + ks + lc];
                bf[ns][0] = p[0];
                bf[ns][1] = p[4];
            }
#pragma unroll
            for (int ms = 0; ms < 4; ms++)
#pragma unroll
                for (int ns = 0; ns < 4; ns++)
                    mma_tf32(acc[ms][ns], af[ms], bf[ns]);
        }
        __syncthreads();
    }

#pragma unroll
    for (int ms = 0; ms < 4; ms++) {
#pragma unroll
        for (int ns = 0; ns < 4; ns++) {
            int gm = m0 + wm * 64 + ms * 16 + lr;
            int gn = n0 + wn * 32 + ns * 8 + (lc << 1);
            float bx = bias[gn], by = bias[gn + 1];
            int h = gn >> 6, d = gn & 63;
            {
                int b = gm >> 10, s = gm & 1023;
                float2 v = make_float2(acc[ms][ns][0] + bx, acc[ms][ns][1] + by);
                *(float2*)(out + (((size_t)(b * NH + h)) * SS + s) * HD + d) = v;
            }
            {
                int gm2 = gm + 8;
                int b = gm2 >> 10, s = gm2 & 1023;
                float2 v = make_float2(acc[ms][ns][2] + bx, acc[ms][ns][3] + by);
                *(float2*)(out + (((size_t)(b * NH + h)) * SS + s) * HD + d) = v;
            }
        }
    }
}

// ===========================================================================
// Kernel 2: fused flash attention (QK^T * scale -> online softmax -> @V).
// One block per (bh, 128-row q tile). 8 warps; warp owns 16 q rows.
// out = softmax(QK^T/32) @ V   (mask term added by mv_mma afterwards)
// ===========================================================================
#define KS_LD 68
#define VS_LD 72
#define PS_LD 132
#define SMEM_FLASH ((128 * KS_LD + 128 * VS_LD + 128 * PS_LD) * 4)

__global__ __launch_bounds__(256, 1) void flash_kernel(float* __restrict__ out)
{
    extern __shared__ uint32_t sm[];
    uint32_t* Ks = sm;                            // [key n][k]   ld 68
    uint32_t* Vs = sm + 128 * KS_LD;              // [key k][col] ld 72
    uint32_t* Ps = sm + 128 * (KS_LD + VS_LD);    // [row][key]   ld 132 (also Q staging)

    const int tid  = threadIdx.x;
    const int lane = tid & 31;
    const int wm   = tid >> 5;        // warp 0..7 -> rows wm*16..
    const int lr   = lane >> 2;       // 0..7
    const int lc   = lane & 3;        // 0..3

    const int qt = blockIdx.x;        // 0..7
    const int bh = blockIdx.y;        // 0..63
    const int b  = bh >> 4, h = bh & 15;

    const float* Qg = g_q + (size_t)bh * SS * HD + (size_t)qt * 128 * HD;
    const float* Kg = g_k + (size_t)bh * SS * HD;
    const float* Vg = g_v + (size_t)bh * SS * HD;

    // ---- prologue: stage Q tile -> Ps, load Q fragments into registers ----
#pragma unroll
    for (int i = 0; i < 8; i++) {
        int idx = i * 256 + tid;
        int r = idx >> 4;
        int c = (idx & 15) << 2;
        float4 a4 = *(const float4*)(Qg + (size_t)r * HD + c);
        uint32_t* p = &Ps[r * PS_LD + c];
        p[0] = f2tf32(a4.x); p[1] = f2tf32(a4.y);
        p[2] = f2tf32(a4.z); p[3] = f2tf32(a4.w);
    }
    __syncthreads();

    uint32_t qf[8][4];
#pragma unroll
    for (int ks = 0; ks < 8; ks++) {
        const uint32_t* p = &Ps[(wm * 16 + lr) * PS_LD + ks * 8 + lc];
        qf[ks][0] = p[0];
        qf[ks][1] = p[8 * PS_LD];
        qf[ks][2] = p[4];
        qf[ks][3] = p[8 * PS_LD + 4];
    }

    // ---- state ----
    float m0 = -1e30f, m1 = -1e30f;
    float l0 = 0.f, l1 = 0.f;
    float oacc[8][4];
#pragma unroll
    for (int i = 0; i < 8; i++)
#pragma unroll
        for (int r = 0; r < 4; r++) oacc[i][r] = 0.f;

    const float scale = 0.03125f;

    for (int kt = 0; kt < 8; kt++) {
        __syncthreads();   // protect Ks/Vs (and Ps on kt==0 vs qf loads)
        // ---- stage K and V tiles ----
#pragma unroll
        for (int i = 0; i < 8; i++) {
            int idx = i * 256 + tid;
            int r = idx >> 4;
            int c = (idx & 15) << 2;
            float4 k4 = *(const float4*)(Kg + (size_t)(kt * 128 + r) * HD + c);
            uint32_t* pk = &Ks[r * KS_LD + c];
            pk[0] = f2tf32(k4.x); pk[1] = f2tf32(k4.y);
            pk[2] = f2tf32(k4.z); pk[3] = f2tf32(k4.w);
            float4 v4 = *(const float4*)(Vg + (size_t)(kt * 128 + r) * HD + c);
            uint32_t* pv = &Vs[r * VS_LD + c];
            pv[0] = f2tf32(v4.x); pv[1] = f2tf32(v4.y);
            pv[2] = f2tf32(v4.z); pv[3] = f2tf32(v4.w);
        }
        __syncthreads();

        // ---- QK^T: scores 16 rows x 128 keys per warp ----
        float sacc[16][4];
#pragma unroll
        for (int nt = 0; nt < 16; nt++)
#pragma unroll
            for (int r = 0; r < 4; r++) sacc[nt][r] = 0.f;

#pragma unroll
        for (int ks = 0; ks < 8; ks++) {
#pragma unroll
            for (int nt = 0; nt < 16; nt++) {
                uint32_t bf[2];
                const uint32_t* p = &Ks[(nt * 8 + lr) * KS_LD + ks * 8 + lc];
                bf[0] = p[0];
                bf[1] = p[4];
                mma_tf32(sacc[nt], qf[ks], bf);
            }
        }

        // ---- online softmax ----
        float rm0 = -1e30f, rm1 = -1e30f;
#pragma unroll
        for (int nt = 0; nt < 16; nt++) {
            rm0 = fmaxf(rm0, fmaxf(sacc[nt][0], sacc[nt][1]));
            rm1 = fmaxf(rm1, fmaxf(sacc[nt][2], sacc[nt][3]));
        }
#pragma unroll
        for (int o = 1; o <= 2; o <<= 1) {
            rm0 = fmaxf(rm0, __shfl_xor_sync(0xffffffffu, rm0, o));
            rm1 = fmaxf(rm1, __shfl_xor_sync(0xffffffffu, rm1, o));
        }
        float mn0 = fmaxf(m0, rm0 * scale);
        float mn1 = fmaxf(m1, rm1 * scale);
        float a0 = __expf(m0 - mn0);
        float a1 = __expf(m1 - mn1);
        m0 = mn0; m1 = mn1;

        float ps0 = 0.f, ps1 = 0.f;
        const int row = wm * 16 + lr;
#pragma unroll
        for (int nt = 0; nt < 16; nt++) {
            float p0 = __expf(fmaf(sacc[nt][0], scale, -mn0));
            float p1 = __expf(fmaf(sacc[nt][1], scale, -mn0));
            float p2 = __expf(fmaf(sacc[nt][2], scale, -mn1));
            float p3 = __expf(fmaf(sacc[nt][3], scale, -mn1));
            ps0 += p0 + p1;
            ps1 += p2 + p3;
            uint32_t* pp = &Ps[row * PS_LD + nt * 8 + (lc << 1)];
            pp[0] = f2tf32(p0);
            pp[1] = f2tf32(p1);
            pp[8 * PS_LD] = f2tf32(p2);
            pp[8 * PS_LD + 1] = f2tf32(p3);
        }
#pragma unroll
        for (int o = 1; o <= 2; o <<= 1) {
            ps0 += __shfl_xor_sync(0xffffffffu, ps0, o);
            ps1 += __shfl_xor_sync(0xffffffffu, ps1, o);
        }
        l0 = l0 * a0 + ps0;
        l1 = l1 * a1 + ps1;

        // rescale O
#pragma unroll
        for (int i = 0; i < 8; i++) {
            oacc[i][0] *= a0; oacc[i][1] *= a0;
            oacc[i][2] *= a1; oacc[i][3] *= a1;
        }
        __syncwarp();   // P rows are warp-private: warp-level sync suffices

        // ---- P @ V ----
#pragma unroll
        for (int ks2 = 0; ks2 < 16; ks2++) {
            uint32_t pa[4];
            const uint32_t* pp = &Ps[row * PS_LD + ks2 * 8 + lc];
            pa[0] = pp[0];
            pa[1] = pp[8 * PS_LD];
            pa[2] = pp[4];
            pa[3] = pp[8 * PS_LD + 4];
#pragma unroll
            for (int nt2 = 0; nt2 < 8; nt2++) {
                uint32_t vb[2];
                vb[0] = Vs[(ks2 * 8 + lc) * VS_LD + nt2 * 8 + lr];
                vb[1] = Vs[(ks2 * 8 + lc + 4) * VS_LD + nt2 * 8 + lr];
                mma_tf32(oacc[nt2], pa, vb);
            }
        }
        __syncwarp();   // done reading Ps before next iteration overwrites
    }

    // ---- epilogue: normalize and write ----
    const float inv0 = 1.0f / l0;
    const float inv1 = 1.0f / l1;
    const int row = qt * 128 + wm * 16 + lr;
#pragma unroll
    for (int nt2 = 0; nt2 < 8; nt2++) {
        int gn = h * HD + nt2 * 8 + (lc << 1);
        float2 v0 = make_float2(oacc[nt2][0] * inv0, oacc[nt2][1] * inv0);
        float2 v1 = make_float2(oacc[nt2][2] * inv1, oacc[nt2][3] * inv1);
        *(float2*)(out + ((size_t)b * SS + row) * D_MODEL + gn) = v0;
        *(float2*)(out + ((size_t)b * SS + row + 8) * D_MODEL + gn) = v1;
    }
}

// ===========================================================================
// Kernel 3: out += mask @ V per head (post-softmax mask, by linearity).
// Block tile 128x64xk1024, warp 32x32 (pv_mma structure).
// ===========================================================================
__global__ __launch_bounds__(256) void mv_mma(const float* __restrict__ mask,
                                              float* __restrict__ out)
{
    const int bh = blockIdx.y;
    const int b = bh >> 4, h = bh & 15;
    const float* V = g_v + (size_t)bh * SS * HD;

    __shared__ uint32_t As[128 * 36];
    __shared__ uint32_t Vs[32 * 72];

    const int tid  = threadIdx.x;
    const int lane = tid & 31;
    const int wid  = tid >> 5;
    const int wm   = wid >> 1;
    const int wn   = wid & 1;
    const int m0   = blockIdx.x * 128;
    const int lr   = lane >> 2;
    const int lc   = lane & 3;

    float acc[2][4][4];
#pragma unroll
    for (int i = 0; i < 2; i++)
#pragma unroll
        for (int j = 0; j < 4; j++)
#pragma unroll
            for (int r = 0; r < 4; r++) acc[i][j][r] = 0.f;

    for (int k0 = 0; k0 < SS; k0 += 32) {
#pragma unroll
        for (int i = 0; i < 4; i++) {
            int idx = tid + i * 256;
            int r = idx >> 3;
            int c = (idx & 7) << 2;
            float4 a4 = *(const float4*)(mask + (size_t)(m0 + r) * SS + k0 + c);
            uint32_t* sa = &As[r * 36 + c];
            sa[0] = f2tf32(a4.x); sa[1] = f2tf32(a4.y);
            sa[2] = f2tf32(a4.z); sa[3] = f2tf32(a4.w);
        }
#pragma unroll
        for (int i = 0; i < 2; i++) {
            int idx = tid + i * 256;
            int k = idx >> 4;
            int n = (idx & 15) << 2;
            float4 b4 = *(const float4*)(V + (size_t)(k0 + k) * HD + n);
            uint32_t* sb = &Vs[k * 72 + n];
            sb[0] = f2tf32(b4.x); sb[1] = f2tf32(b4.y);
            sb[2] = f2tf32(b4.z); sb[3] = f2tf32(b4.w);
        }
        __syncthreads();
#pragma unroll
        for (int ks = 0; ks < 32; ks += 8) {
            uint32_t af[2][4], bf[4][2];
#pragma unroll
            for (int ms = 0; ms < 2; ms++) {
                const uint32_t* p = &As[(wm * 32 + ms * 16 + lr) * 36 + ks + lc];
                af[ms][0] = p[0];
                af[ms][1] = p[8 * 36];
                af[ms][2] = p[4];
                af[ms][3] = p[8 * 36 + 4];
            }
#pragma unroll
            for (int ns = 0; ns < 4; ns++) {
                const uint32_t* p = &Vs[(ks + lc) * 72 + wn * 32 + ns * 8 + lr];
                bf[ns][0] = p[0];
                bf[ns][1] = p[4 * 72];
            }
#pragma unroll
            for (int ms = 0; ms < 2; ms++)
#pragma unroll
                for (int ns = 0; ns < 4; ns++)
                    mma_tf32(acc[ms][ns], af[ms], bf[ns]);
        }
        __syncthreads();
    }

#pragma unroll
    for (int ms = 0; ms < 2; ms++) {
#pragma unroll
        for (int ns = 0; ns < 4; ns++) {
            int gm = m0 + wm * 32 + ms * 16 + lr;
            int gn = wn * 32 + ns * 8 + (lc << 1);
            float2* p0 = (float2*)(out + ((size_t)b * SS + gm) * D_MODEL + h * HD + gn);
            float2* p1 = (float2*)(out + ((size_t)b * SS + gm + 8) * D_MODEL + h * HD + gn);
            float2 o0 = *p0, o1 = *p1;
            o0.x += acc[ms][ns][0]; o0.y += acc[ms][ns][1];
            o1.x += acc[ms][ns][2]; o1.y += acc[ms][ns][3];
            *p0 = o0; *p1 = o1;
        }
    }
}

// ===========================================================================
extern "C" void kernel_launch(void* const* d_in, const int* in_sizes, int n_in,
                              void* d_out, int out_size)
{
    const float* x    = (const float*)d_in[0];
    const float* y    = (const float*)d_in[1];
    const float* z    = (const float*)d_in[2];
    const float* mask = (const float*)d_in[3];
    const float* wq   = (const float*)d_in[4];
    const float* bq   = (const float*)d_in[5];
    const float* wk   = (const float*)d_in[6];
    const float* bk   = (const float*)d_in[7];
    const float* wv   = (const float*)d_in[8];
    const float* bv   = (const float*)d_in[9];
    float* out = (float*)d_out;

    cudaFuncSetAttribute(flash_kernel,
                         cudaFuncAttributeMaxDynamicSharedMemorySize, SMEM_FLASH);

    dim3 g1(D_MODEL / 128, MROWS / 128, 3);
    proj_mma<<<g1, 256>>>(x, y, z, wq, bq, wk, bk, wv, bv);

    dim3 g2(SS / 128, BB * NH);
    flash_kernel<<<g2, 256, SMEM_FLASH>>>(out);

    dim3 g3(SS / 128, BB * NH);
    mv_mma<<<g3, 256>>>(mask, out);
}

// round 4
// speedup vs baseline: 2.7914x; 1.1262x over previous
#include <cuda_runtime.h>
#include <cstdint>

#define D_MODEL 1024
#define NH 16
#define HD 64
#define BB 4
#define SS 1024
#define MROWS (BB * SS)   // 4096

// ---- scratch ----
__device__ float g_q[(size_t)BB * NH * SS * HD];
__device__ float g_k[(size_t)BB * NH * SS * HD];
__device__ float g_v[(size_t)BB * NH * SS * HD];

// ---------------------------------------------------------------------------
__device__ __forceinline__ uint32_t f2tf32(float x) {
    uint32_t r;
    asm("cvt.rna.tf32.f32 %0, %1;" : "=r"(r) : "f"(x));
    return r;
}

__device__ __forceinline__ void mma_tf32(float c[4], const uint32_t a[4], const uint32_t b[2]) {
    asm("mma.sync.aligned.m16n8k8.row.col.f32.tf32.tf32.f32 "
        "{%0,%1,%2,%3}, {%4,%5,%6,%7}, {%8,%9}, {%0,%1,%2,%3};"
        : "+f"(c[0]), "+f"(c[1]), "+f"(c[2]), "+f"(c[3])
        : "r"(a[0]), "r"(a[1]), "r"(a[2]), "r"(a[3]), "r"(b[0]), "r"(b[1]));
}

__device__ __forceinline__ void cpa16(void* dst, const void* src) {
    uint32_t d = (uint32_t)__cvta_generic_to_shared(dst);
    asm volatile("cp.async.cg.shared.global [%0], [%1], 16;\n" :: "r"(d), "l"(src));
}
#define CP_COMMIT() asm volatile("cp.async.commit_group;\n" ::)
#define CP_WAIT(n)  asm volatile("cp.async.wait_group %0;\n" :: "n"(n))

// ===========================================================================
// Kernel 1: fused QKV projection, tf32 MMA, 2-stage cp.async pipeline.
// smem: raw fp32, cvt.rna at fragment load (same numerics as staging cvt).
// ===========================================================================
#define PJ_LD 36
#define SMEM_PROJ (2 * 2 * 128 * PJ_LD * 4)   // 73728 B

__global__ __launch_bounds__(256) void proj_mma(
    const float* __restrict__ x, const float* __restrict__ y,
    const float* __restrict__ z,
    const float* __restrict__ wq, const float* __restrict__ bq,
    const float* __restrict__ wk, const float* __restrict__ bk,
    const float* __restrict__ wv, const float* __restrict__ bv)
{
    extern __shared__ float smp[];
    float* As = smp;                    // [2][128][36]
    float* Bs = smp + 2 * 128 * PJ_LD;  // [2][128][36]

    const int which = blockIdx.z;
    const float* A    = which == 0 ? x  : (which == 1 ? y  : z);
    const float* W    = which == 0 ? wq : (which == 1 ? wk : wv);
    const float* bias = which == 0 ? bq : (which == 1 ? bk : bv);
    float* out        = which == 0 ? g_q : (which == 1 ? g_k : g_v);

    const int tid  = threadIdx.x;
    const int lane = tid & 31;
    const int wid  = tid >> 5;
    const int wm   = wid >> 2;
    const int wn   = wid & 3;
    const int m0   = blockIdx.y * 128;
    const int n0   = blockIdx.x * 128;
    const int lr   = lane >> 2;
    const int lc   = lane & 3;

    float acc[4][4][4];
#pragma unroll
    for (int i = 0; i < 4; i++)
#pragma unroll
        for (int j = 0; j < 4; j++)
#pragma unroll
            for (int r = 0; r < 4; r++) acc[i][j][r] = 0.f;

    // staging lambda via macro-ish inline
    auto stage = [&](int buf, int k0) {
#pragma unroll
        for (int i = 0; i < 4; i++) {
            int idx = tid + i * 256;
            int r = idx >> 3;
            int c = (idx & 7) << 2;
            cpa16(&As[buf * 128 * PJ_LD + r * PJ_LD + c],
                  A + (size_t)(m0 + r) * D_MODEL + k0 + c);
            cpa16(&Bs[buf * 128 * PJ_LD + r * PJ_LD + c],
                  W + (size_t)(n0 + r) * D_MODEL + k0 + c);
        }
    };

    stage(0, 0);
    CP_COMMIT();

    for (int ch = 0; ch < 32; ch++) {
        if (ch + 1 < 32) { stage((ch + 1) & 1, (ch + 1) * 32); CP_COMMIT(); }
        if (ch + 1 < 32) { CP_WAIT(1); } else { CP_WAIT(0); }
        __syncthreads();

        const float* Ab = &As[(ch & 1) * 128 * PJ_LD];
        const float* Bb = &Bs[(ch & 1) * 128 * PJ_LD];
#pragma unroll
        for (int ks = 0; ks < 32; ks += 8) {
            uint32_t af[4][4], bf[4][2];
#pragma unroll
            for (int ms = 0; ms < 4; ms++) {
                const float* p = &Ab[(wm * 64 + ms * 16 + lr) * PJ_LD + ks + lc];
                af[ms][0] = f2tf32(p[0]);
                af[ms][1] = f2tf32(p[8 * PJ_LD]);
                af[ms][2] = f2tf32(p[4]);
                af[ms][3] = f2tf32(p[8 * PJ_LD + 4]);
            }
#pragma unroll
            for (int ns = 0; ns < 4; ns++) {
                const float* p = &Bb[(wn * 32 + ns * 8 + lr) * PJ_LD + ks + lc];
                bf[ns][0] = f2tf32(p[0]);
                bf[ns][1] = f2tf32(p[4]);
            }
#pragma unroll
            for (int ms = 0; ms < 4; ms++)
#pragma unroll
                for (int ns = 0; ns < 4; ns++)
                    mma_tf32(acc[ms][ns], af[ms], bf[ns]);
        }
        __syncthreads();
    }

#pragma unroll
    for (int ms = 0; ms < 4; ms++) {
#pragma unroll
        for (int ns = 0; ns < 4; ns++) {
            int gm = m0 + wm * 64 + ms * 16 + lr;
            int gn = n0 + wn * 32 + ns * 8 + (lc << 1);
            float bx = bias[gn], by = bias[gn + 1];
            int h = gn >> 6, d = gn & 63;
            {
                int b = gm >> 10, s = gm & 1023;
                float2 v = make_float2(acc[ms][ns][0] + bx, acc[ms][ns][1] + by);
                *(float2*)(out + (((size_t)(b * NH + h)) * SS + s) * HD + d) = v;
            }
            {
                int gm2 = gm + 8;
                int b = gm2 >> 10, s = gm2 & 1023;
                float2 v = make_float2(acc[ms][ns][2] + bx, acc[ms][ns][3] + by);
                *(float2*)(out + (((size_t)(b * NH + h)) * SS + s) * HD + d) = v;
            }
        }
    }
}

// ===========================================================================
// Kernel 2: fused flash attention + mask@V.
//   out = softmax(QK^T/32) @ V + mask @ V
// One block per (bh, 128-row q tile). 8 warps, 16 q-rows each.
// K/V double-buffered via cp.async; mask A-fragments read straight from gmem.
// ===========================================================================
#define KS_LD 68
#define VS_LD 72
#define PS_LD 132
#define KS_SZ (128 * KS_LD)
#define VS_SZ (128 * VS_LD)
#define SMEM_FLASH ((2 * KS_SZ + 2 * VS_SZ + 128 * PS_LD) * 4)  // 210944 B

__global__ __launch_bounds__(256, 1) void flash_kernel(const float* __restrict__ mask,
                                                       float* __restrict__ out)
{
    extern __shared__ float smf[];
    float* Ks = smf;                       // [2][128][68] raw fp32
    float* Vs = smf + 2 * KS_SZ;           // [2][128][72] raw fp32
    uint32_t* Ps = (uint32_t*)(smf + 2 * KS_SZ + 2 * VS_SZ);  // [128][132] tf32

    const int tid  = threadIdx.x;
    const int lane = tid & 31;
    const int wm   = tid >> 5;
    const int lr   = lane >> 2;
    const int lc   = lane & 3;

    const int qt = blockIdx.x;
    const int bh = blockIdx.y;
    const int b  = bh >> 4, h = bh & 15;

    const float* Qg = g_q + (size_t)bh * SS * HD + (size_t)qt * 128 * HD;
    const float* Kg = g_k + (size_t)bh * SS * HD;
    const float* Vg = g_v + (size_t)bh * SS * HD;
    const float* Mg = mask + (size_t)(qt * 128 + wm * 16 + lr) * SS;

    auto stageKV = [&](int kt, int buf) {
#pragma unroll
        for (int i = 0; i < 8; i++) {
            int idx = i * 256 + tid;
            int r = idx >> 4;
            int c = (idx & 15) << 2;
            cpa16(&Ks[buf * KS_SZ + r * KS_LD + c], Kg + (size_t)(kt * 128 + r) * HD + c);
            cpa16(&Vs[buf * VS_SZ + r * VS_LD + c], Vg + (size_t)(kt * 128 + r) * HD + c);
        }
    };

    // ---- prologue: kick off K/V tile 0, stage Q -> Ps, load Q fragments ----
    stageKV(0, 0);
    CP_COMMIT();

#pragma unroll
    for (int i = 0; i < 8; i++) {
        int idx = i * 256 + tid;
        int r = idx >> 4;
        int c = (idx & 15) << 2;
        float4 a4 = *(const float4*)(Qg + (size_t)r * HD + c);
        uint32_t* p = &Ps[r * PS_LD + c];
        p[0] = f2tf32(a4.x); p[1] = f2tf32(a4.y);
        p[2] = f2tf32(a4.z); p[3] = f2tf32(a4.w);
    }
    __syncthreads();

    uint32_t qf[8][4];
#pragma unroll
    for (int ks = 0; ks < 8; ks++) {
        const uint32_t* p = &Ps[(wm * 16 + lr) * PS_LD + ks * 8 + lc];
        qf[ks][0] = p[0];
        qf[ks][1] = p[8 * PS_LD];
        qf[ks][2] = p[4];
        qf[ks][3] = p[8 * PS_LD + 4];
    }

    // ---- state ----
    float m0 = -1e30f, m1 = -1e30f;
    float l0 = 0.f, l1 = 0.f;
    float oacc[8][4], macc[8][4];
#pragma unroll
    for (int i = 0; i < 8; i++)
#pragma unroll
        for (int r = 0; r < 4; r++) { oacc[i][r] = 0.f; macc[i][r] = 0.f; }

    const float scale = 0.03125f;
    const int row = wm * 16 + lr;

    for (int kt = 0; kt < 8; kt++) {
        if (kt + 1 < 8) { stageKV(kt + 1, (kt + 1) & 1); CP_COMMIT(); }
        if (kt + 1 < 8) { CP_WAIT(1); } else { CP_WAIT(0); }
        __syncthreads();

        const float* Ksb = &Ks[(kt & 1) * KS_SZ];
        const float* Vsb = &Vs[(kt & 1) * VS_SZ];

        // ---- QK^T ----
        float sacc[16][4];
#pragma unroll
        for (int nt = 0; nt < 16; nt++)
#pragma unroll
            for (int r = 0; r < 4; r++) sacc[nt][r] = 0.f;

#pragma unroll
        for (int ks = 0; ks < 8; ks++) {
#pragma unroll
            for (int nt = 0; nt < 16; nt++) {
                uint32_t bf[2];
                const float* p = &Ksb[(nt * 8 + lr) * KS_LD + ks * 8 + lc];
                bf[0] = f2tf32(p[0]);
                bf[1] = f2tf32(p[4]);
                mma_tf32(sacc[nt], qf[ks], bf);
            }
        }

        // ---- online softmax ----
        float rm0 = -1e30f, rm1 = -1e30f;
#pragma unroll
        for (int nt = 0; nt < 16; nt++) {
            rm0 = fmaxf(rm0, fmaxf(sacc[nt][0], sacc[nt][1]));
            rm1 = fmaxf(rm1, fmaxf(sacc[nt][2], sacc[nt][3]));
        }
#pragma unroll
        for (int o = 1; o <= 2; o <<= 1) {
            rm0 = fmaxf(rm0, __shfl_xor_sync(0xffffffffu, rm0, o));
            rm1 = fmaxf(rm1, __shfl_xor_sync(0xffffffffu, rm1, o));
        }
        float mn0 = fmaxf(m0, rm0 * scale);
        float mn1 = fmaxf(m1, rm1 * scale);
        float a0 = __expf(m0 - mn0);
        float a1 = __expf(m1 - mn1);
        m0 = mn0; m1 = mn1;

        float ps0 = 0.f, ps1 = 0.f;
#pragma unroll
        for (int nt = 0; nt < 16; nt++) {
            float p0 = __expf(fmaf(sacc[nt][0], scale, -mn0));
            float p1 = __expf(fmaf(sacc[nt][1], scale, -mn0));
            float p2 = __expf(fmaf(sacc[nt][2], scale, -mn1));
            float p3 = __expf(fmaf(sacc[nt][3], scale, -mn1));
            ps0 += p0 + p1;
            ps1 += p2 + p3;
            uint32_t* pp = &Ps[row * PS_LD + nt * 8 + (lc << 1)];
            pp[0] = f2tf32(p0);
            pp[1] = f2tf32(p1);
            pp[8 * PS_LD] = f2tf32(p2);
            pp[8 * PS_LD + 1] = f2tf32(p3);
        }
#pragma unroll
        for (int o = 1; o <= 2; o <<= 1) {
            ps0 += __shfl_xor_sync(0xffffffffu, ps0, o);
            ps1 += __shfl_xor_sync(0xffffffffu, ps1, o);
        }
        l0 = l0 * a0 + ps0;
        l1 = l1 * a1 + ps1;

#pragma unroll
        for (int i = 0; i < 8; i++) {
            oacc[i][0] *= a0; oacc[i][1] *= a0;
            oacc[i][2] *= a1; oacc[i][3] *= a1;
        }
        __syncwarp();

        // ---- (P @ V) and (mask @ V) sharing B fragments ----
#pragma unroll
        for (int ks2 = 0; ks2 < 16; ks2++) {
            uint32_t pa[4], ma[4];
            const uint32_t* pp = &Ps[row * PS_LD + ks2 * 8 + lc];
            pa[0] = pp[0];
            pa[1] = pp[8 * PS_LD];
            pa[2] = pp[4];
            pa[3] = pp[8 * PS_LD + 4];
            const float* mp = Mg + kt * 128 + ks2 * 8 + lc;
            ma[0] = f2tf32(mp[0]);
            ma[1] = f2tf32(mp[8 * SS]);
            ma[2] = f2tf32(mp[4]);
            ma[3] = f2tf32(mp[8 * SS + 4]);
#pragma unroll
            for (int nt2 = 0; nt2 < 8; nt2++) {
                uint32_t vb[2];
                vb[0] = f2tf32(Vsb[(ks2 * 8 + lc) * VS_LD + nt2 * 8 + lr]);
                vb[1] = f2tf32(Vsb[(ks2 * 8 + lc + 4) * VS_LD + nt2 * 8 + lr]);
                mma_tf32(oacc[nt2], pa, vb);
                mma_tf32(macc[nt2], ma, vb);
            }
        }
        __syncthreads();   // all reads of Ks/Vs[kt&1] done before next overwrite
    }

    // ---- epilogue ----
    const float inv0 = 1.0f / l0;
    const float inv1 = 1.0f / l1;
    const int grow = qt * 128 + wm * 16 + lr;
#pragma unroll
    for (int nt2 = 0; nt2 < 8; nt2++) {
        int gn = h * HD + nt2 * 8 + (lc << 1);
        float2 v0 = make_float2(oacc[nt2][0] * inv0 + macc[nt2][0],
                                oacc[nt2][1] * inv0 + macc[nt2][1]);
        float2 v1 = make_float2(oacc[nt2][2] * inv1 + macc[nt2][2],
                                oacc[nt2][3] * inv1 + macc[nt2][3]);
        *(float2*)(out + ((size_t)b * SS + grow) * D_MODEL + gn) = v0;
        *(float2*)(out + ((size_t)b * SS + grow + 8) * D_MODEL + gn) = v1;
    }
}

// ===========================================================================
extern "C" void kernel_launch(void* const* d_in, const int* in_sizes, int n_in,
                              void* d_out, int out_size)
{
    const float* x    = (const float*)d_in[0];
    const float* y    = (const float*)d_in[1];
    const float* z    = (const float*)d_in[2];
    const float* mask = (const float*)d_in[3];
    const float* wq   = (const float*)d_in[4];
    const float* bq   = (const float*)d_in[5];
    const float* wk   = (const float*)d_in[6];
    const float* bk   = (const float*)d_in[7];
    const float* wv   = (const float*)d_in[8];
    const float* bv   = (const float*)d_in[9];
    float* out = (float*)d_out;

    cudaFuncSetAttribute(proj_mma,
                         cudaFuncAttributeMaxDynamicSharedMemorySize, SMEM_PROJ);
    cudaFuncSetAttribute(flash_kernel,
                         cudaFuncAttributeMaxDynamicSharedMemorySize, SMEM_FLASH);

    dim3 g1(D_MODEL / 128, MROWS / 128, 3);
    proj_mma<<<g1, 256, SMEM_PROJ>>>(x, y, z, wq, bq, wk, bk, wv, bv);

    dim3 g2(SS / 128, BB * NH);
    flash_kernel<<<g2, 256, SMEM_FLASH>>>(mask, out);
}

// round 5
// speedup vs baseline: 2.8166x; 1.0090x over previous
#include <cuda_runtime.h>
#include <cstdint>

#define D_MODEL 1024
#define NH 16
#define HD 64
#define BB 4
#define SS 1024
#define MROWS (BB * SS)   // 4096

// ---- scratch (tf32 bit patterns stored as uint32) ----
__device__ uint32_t g_q[(size_t)BB * NH * SS * HD];
__device__ uint32_t g_k[(size_t)BB * NH * SS * HD];
__device__ uint32_t g_v[(size_t)BB * NH * SS * HD];
__device__ uint32_t g_xc[(size_t)MROWS * D_MODEL];
__device__ uint32_t g_yc[(size_t)MROWS * D_MODEL];
__device__ uint32_t g_zc[(size_t)MROWS * D_MODEL];
__device__ uint32_t g_wqc[(size_t)D_MODEL * D_MODEL];
__device__ uint32_t g_wkc[(size_t)D_MODEL * D_MODEL];
__device__ uint32_t g_wvc[(size_t)D_MODEL * D_MODEL];
__device__ uint32_t g_mc[(size_t)SS * SS];

// ---------------------------------------------------------------------------
__device__ __forceinline__ uint32_t f2tf32(float x) {
    uint32_t r;
    asm("cvt.rna.tf32.f32 %0, %1;" : "=r"(r) : "f"(x));
    return r;
}

__device__ __forceinline__ void mma_tf32(float c[4], const uint32_t a[4], const uint32_t b[2]) {
    asm("mma.sync.aligned.m16n8k8.row.col.f32.tf32.tf32.f32 "
        "{%0,%1,%2,%3}, {%4,%5,%6,%7}, {%8,%9}, {%0,%1,%2,%3};"
        : "+f"(c[0]), "+f"(c[1]), "+f"(c[2]), "+f"(c[3])
        : "r"(a[0]), "r"(a[1]), "r"(a[2]), "r"(a[3]), "r"(b[0]), "r"(b[1]));
}

__device__ __forceinline__ void cpa16(void* dst, const void* src) {
    uint32_t d = (uint32_t)__cvta_generic_to_shared(dst);
    asm volatile("cp.async.cg.shared.global [%0], [%1], 16;\n" :: "r"(d), "l"(src));
}
#define CP_COMMIT() asm volatile("cp.async.commit_group;\n" ::)
#define CP_WAIT(n)  asm volatile("cp.async.wait_group %0;\n" :: "n"(n))

// ===========================================================================
// Kernel 0: bulk fp32 -> tf32 conversion of all inputs.
// grid.y selects tensor; grid.x strides elements (float4 per thread).
// ===========================================================================
__global__ __launch_bounds__(256) void cvt_kernel(
    const float* __restrict__ x, const float* __restrict__ y,
    const float* __restrict__ z, const float* __restrict__ wq,
    const float* __restrict__ wk, const float* __restrict__ wv,
    const float* __restrict__ mask)
{
    const float* src;
    uint32_t* dst;
    size_t n;
    switch (blockIdx.y) {
        case 0: src = x;    dst = g_xc;  n = (size_t)MROWS * D_MODEL; break;
        case 1: src = y;    dst = g_yc;  n = (size_t)MROWS * D_MODEL; break;
        case 2: src = z;    dst = g_zc;  n = (size_t)MROWS * D_MODEL; break;
        case 3: src = wq;   dst = g_wqc; n = (size_t)D_MODEL * D_MODEL; break;
        case 4: src = wk;   dst = g_wkc; n = (size_t)D_MODEL * D_MODEL; break;
        case 5: src = wv;   dst = g_wvc; n = (size_t)D_MODEL * D_MODEL; break;
        default: src = mask; dst = g_mc; n = (size_t)SS * SS; break;
    }
    size_t i = ((size_t)blockIdx.x * 256 + threadIdx.x) * 4;
    if (i >= n) return;
    float4 v = *(const float4*)(src + i);
    uint4 o;
    o.x = f2tf32(v.x); o.y = f2tf32(v.y);
    o.z = f2tf32(v.z); o.w = f2tf32(v.w);
    *(uint4*)(dst + i) = o;
}

// ===========================================================================
// Kernel 1: fused QKV projection, tf32 in / tf32 out, cp.async pipeline.
// Zero cvt in the inner loop.
// ===========================================================================
#define PJ_LD 36
#define SMEM_PROJ (2 * 2 * 128 * PJ_LD * 4)   // 73728 B

__global__ __launch_bounds__(256) void proj_mma(
    const float* __restrict__ bq, const float* __restrict__ bk,
    const float* __restrict__ bv)
{
    extern __shared__ uint32_t smp[];
    uint32_t* As = smp;
    uint32_t* Bs = smp + 2 * 128 * PJ_LD;

    const int which = blockIdx.z;
    const uint32_t* A  = which == 0 ? g_xc  : (which == 1 ? g_yc  : g_zc);
    const uint32_t* W  = which == 0 ? g_wqc : (which == 1 ? g_wkc : g_wvc);
    const float* bias  = which == 0 ? bq    : (which == 1 ? bk    : bv);
    uint32_t* out      = which == 0 ? g_q   : (which == 1 ? g_k   : g_v);

    const int tid  = threadIdx.x;
    const int lane = tid & 31;
    const int wid  = tid >> 5;
    const int wm   = wid >> 2;
    const int wn   = wid & 3;
    const int m0   = blockIdx.y * 128;
    const int n0   = blockIdx.x * 128;
    const int lr   = lane >> 2;
    const int lc   = lane & 3;

    float acc[4][4][4];
#pragma unroll
    for (int i = 0; i < 4; i++)
#pragma unroll
        for (int j = 0; j < 4; j++)
#pragma unroll
            for (int r = 0; r < 4; r++) acc[i][j][r] = 0.f;

    auto stage = [&](int buf, int k0) {
#pragma unroll
        for (int i = 0; i < 4; i++) {
            int idx = tid + i * 256;
            int r = idx >> 3;
            int c = (idx & 7) << 2;
            cpa16(&As[buf * 128 * PJ_LD + r * PJ_LD + c],
                  A + (size_t)(m0 + r) * D_MODEL + k0 + c);
            cpa16(&Bs[buf * 128 * PJ_LD + r * PJ_LD + c],
                  W + (size_t)(n0 + r) * D_MODEL + k0 + c);
        }
    };

    stage(0, 0);
    CP_COMMIT();

    for (int ch = 0; ch < 32; ch++) {
        if (ch + 1 < 32) { stage((ch + 1) & 1, (ch + 1) * 32); CP_COMMIT(); }
        if (ch + 1 < 32) { CP_WAIT(1); } else { CP_WAIT(0); }
        __syncthreads();

        const uint32_t* Ab = &As[(ch & 1) * 128 * PJ_LD];
        const uint32_t* Bb = &Bs[(ch & 1) * 128 * PJ_LD];
#pragma unroll
        for (int ks = 0; ks < 32; ks += 8) {
            uint32_t af[4][4], bf[4][2];
#pragma unroll
            for (int ms = 0; ms < 4; ms++) {
                const uint32_t* p = &Ab[(wm * 64 + ms * 16 + lr) * PJ_LD + ks + lc];
                af[ms][0] = p[0];
                af[ms][1] = p[8 * PJ_LD];
                af[ms][2] = p[4];
                af[ms][3] = p[8 * PJ_LD + 4];
            }
#pragma unroll
            for (int ns = 0; ns < 4; ns++) {
                const uint32_t* p = &Bb[(wn * 32 + ns * 8 + lr) * PJ_LD + ks + lc];
                bf[ns][0] = p[0];
                bf[ns][1] = p[4];
            }
#pragma unroll
            for (int ms = 0; ms < 4; ms++)
#pragma unroll
                for (int ns = 0; ns < 4; ns++)
                    mma_tf32(acc[ms][ns], af[ms], bf[ns]);
        }
        __syncthreads();
    }

#pragma unroll
    for (int ms = 0; ms < 4; ms++) {
#pragma unroll
        for (int ns = 0; ns < 4; ns++) {
            int gm = m0 + wm * 64 + ms * 16 + lr;
            int gn = n0 + wn * 32 + ns * 8 + (lc << 1);
            float bx = bias[gn], by = bias[gn + 1];
            int h = gn >> 6, d = gn & 63;
            {
                int b = gm >> 10, s = gm & 1023;
                uint2 v = make_uint2(f2tf32(acc[ms][ns][0] + bx),
                                     f2tf32(acc[ms][ns][1] + by));
                *(uint2*)(out + (((size_t)(b * NH + h)) * SS + s) * HD + d) = v;
            }
            {
                int gm2 = gm + 8;
                int b = gm2 >> 10, s = gm2 & 1023;
                uint2 v = make_uint2(f2tf32(acc[ms][ns][2] + bx),
                                     f2tf32(acc[ms][ns][3] + by));
                *(uint2*)(out + (((size_t)(b * NH + h)) * SS + s) * HD + d) = v;
            }
        }
    }
}

// ===========================================================================
// Kernel 2: fused flash attention + mask@V, all operands pre-converted tf32.
//   out = softmax(QK^T/32) @ V + mask @ V
// ===========================================================================
#define KS_LD 68
#define VS_LD 72
#define PS_LD 132
#define KS_SZ (128 * KS_LD)
#define VS_SZ (128 * VS_LD)
#define SMEM_FLASH ((2 * KS_SZ + 2 * VS_SZ + 128 * PS_LD) * 4)  // 210944 B

__global__ __launch_bounds__(256, 1) void flash_kernel(float* __restrict__ out)
{
    extern __shared__ uint32_t smf[];
    uint32_t* Ks = smf;
    uint32_t* Vs = smf + 2 * KS_SZ;
    uint32_t* Ps = smf + 2 * KS_SZ + 2 * VS_SZ;

    const int tid  = threadIdx.x;
    const int lane = tid & 31;
    const int wm   = tid >> 5;
    const int lr   = lane >> 2;
    const int lc   = lane & 3;

    const int qt = blockIdx.x;
    const int bh = blockIdx.y;
    const int b  = bh >> 4, h = bh & 15;

    const uint32_t* Qg = g_q + (size_t)bh * SS * HD + (size_t)qt * 128 * HD;
    const uint32_t* Kg = g_k + (size_t)bh * SS * HD;
    const uint32_t* Vg = g_v + (size_t)bh * SS * HD;
    const uint32_t* Mg = g_mc + (size_t)(qt * 128 + wm * 16 + lr) * SS;

    auto stageKV = [&](int kt, int buf) {
#pragma unroll
        for (int i = 0; i < 8; i++) {
            int idx = i * 256 + tid;
            int r = idx >> 4;
            int c = (idx & 15) << 2;
            cpa16(&Ks[buf * KS_SZ + r * KS_LD + c], Kg + (size_t)(kt * 128 + r) * HD + c);
            cpa16(&Vs[buf * VS_SZ + r * VS_LD + c], Vg + (size_t)(kt * 128 + r) * HD + c);
        }
    };

    // ---- prologue: kick K/V tile 0 + Q staging via cp.async ----
    stageKV(0, 0);
#pragma unroll
    for (int i = 0; i < 2; i++) {
        int idx = i * 256 + tid;
        int r = idx >> 2;               // 0..127
        int c = (idx & 3) << 4;         // 0,16,32,48
#pragma unroll
        for (int cc = 0; cc < 16; cc += 4)
            cpa16(&Ps[r * PS_LD + c + cc], Qg + (size_t)r * HD + c + cc);
    }
    CP_COMMIT();
    CP_WAIT(0);
    __syncthreads();

    uint32_t qf[8][4];
#pragma unroll
    for (int ks = 0; ks < 8; ks++) {
        const uint32_t* p = &Ps[(wm * 16 + lr) * PS_LD + ks * 8 + lc];
        qf[ks][0] = p[0];
        qf[ks][1] = p[8 * PS_LD];
        qf[ks][2] = p[4];
        qf[ks][3] = p[8 * PS_LD + 4];
    }
    __syncthreads();

    // re-kick tile 0 group bookkeeping: tile 0 already loaded; commit an empty
    // group so wait-depth logic below stays uniform.
    CP_COMMIT();

    float m0 = -1e30f, m1 = -1e30f;
    float l0 = 0.f, l1 = 0.f;
    float oacc[8][4], macc[8][4];
#pragma unroll
    for (int i = 0; i < 8; i++)
#pragma unroll
        for (int r = 0; r < 4; r++) { oacc[i][r] = 0.f; macc[i][r] = 0.f; }

    const float scale = 0.03125f;
    const int row = wm * 16 + lr;

    for (int kt = 0; kt < 8; kt++) {
        if (kt + 1 < 8) { stageKV(kt + 1, (kt + 1) & 1); CP_COMMIT(); }
        if (kt + 1 < 8) { CP_WAIT(1); } else { CP_WAIT(0); }
        __syncthreads();

        const uint32_t* Ksb = &Ks[(kt & 1) * KS_SZ];
        const uint32_t* Vsb = &Vs[(kt & 1) * VS_SZ];

        // ---- QK^T ----
        float sacc[16][4];
#pragma unroll
        for (int nt = 0; nt < 16; nt++)
#pragma unroll
            for (int r = 0; r < 4; r++) sacc[nt][r] = 0.f;

#pragma unroll
        for (int ks = 0; ks < 8; ks++) {
#pragma unroll
            for (int nt = 0; nt < 16; nt++) {
                uint32_t bf[2];
                const uint32_t* p = &Ksb[(nt * 8 + lr) * KS_LD + ks * 8 + lc];
                bf[0] = p[0];
                bf[1] = p[4];
                mma_tf32(sacc[nt], qf[ks], bf);
            }
        }

        // ---- online softmax ----
        float rm0 = -1e30f, rm1 = -1e30f;
#pragma unroll
        for (int nt = 0; nt < 16; nt++) {
            rm0 = fmaxf(rm0, fmaxf(sacc[nt][0], sacc[nt][1]));
            rm1 = fmaxf(rm1, fmaxf(sacc[nt][2], sacc[nt][3]));
        }
#pragma unroll
        for (int o = 1; o <= 2; o <<= 1) {
            rm0 = fmaxf(rm0, __shfl_xor_sync(0xffffffffu, rm0, o));
            rm1 = fmaxf(rm1, __shfl_xor_sync(0xffffffffu, rm1, o));
        }
        float mn0 = fmaxf(m0, rm0 * scale);
        float mn1 = fmaxf(m1, rm1 * scale);
        float a0 = __expf(m0 - mn0);
        float a1 = __expf(m1 - mn1);
        m0 = mn0; m1 = mn1;

        float ps0 = 0.f, ps1 = 0.f;
#pragma unroll
        for (int nt = 0; nt < 16; nt++) {
            float p0 = __expf(fmaf(sacc[nt][0], scale, -mn0));
            float p1 = __expf(fmaf(sacc[nt][1], scale, -mn0));
            float p2 = __expf(fmaf(sacc[nt][2], scale, -mn1));
            float p3 = __expf(fmaf(sacc[nt][3], scale, -mn1));
            ps0 += p0 + p1;
            ps1 += p2 + p3;
            uint32_t* pp = &Ps[row * PS_LD + nt * 8 + (lc << 1)];
            pp[0] = f2tf32(p0);
            pp[1] = f2tf32(p1);
            pp[8 * PS_LD] = f2tf32(p2);
            pp[8 * PS_LD + 1] = f2tf32(p3);
        }
#pragma unroll
        for (int o = 1; o <= 2; o <<= 1) {
            ps0 += __shfl_xor_sync(0xffffffffu, ps0, o);
            ps1 += __shfl_xor_sync(0xffffffffu, ps1, o);
        }
        l0 = l0 * a0 + ps0;
        l1 = l1 * a1 + ps1;

#pragma unroll
        for (int i = 0; i < 8; i++) {
            oacc[i][0] *= a0; oacc[i][1] *= a0;
            oacc[i][2] *= a1; oacc[i][3] *= a1;
        }
        __syncwarp();

        // ---- (P @ V) and (mask @ V) sharing B fragments ----
#pragma unroll
        for (int ks2 = 0; ks2 < 16; ks2++) {
            uint32_t pa[4], ma[4];
            const uint32_t* pp = &Ps[row * PS_LD + ks2 * 8 + lc];
            pa[0] = pp[0];
            pa[1] = pp[8 * PS_LD];
            pa[2] = pp[4];
            pa[3] = pp[8 * PS_LD + 4];
            const uint32_t* mp = Mg + kt * 128 + ks2 * 8 + lc;
            ma[0] = mp[0];
            ma[1] = mp[8 * SS];
            ma[2] = mp[4];
            ma[3] = mp[8 * SS + 4];
#pragma unroll
            for (int nt2 = 0; nt2 < 8; nt2++) {
                uint32_t vb[2];
                vb[0] = Vsb[(ks2 * 8 + lc) * VS_LD + nt2 * 8 + lr];
                vb[1] = Vsb[(ks2 * 8 + lc + 4) * VS_LD + nt2 * 8 + lr];
                mma_tf32(oacc[nt2], pa, vb);
                mma_tf32(macc[nt2], ma, vb);
            }
        }
        __syncthreads();
    }

    // ---- epilogue ----
    const float inv0 = 1.0f / l0;
    const float inv1 = 1.0f / l1;
    const int grow = qt * 128 + wm * 16 + lr;
#pragma unroll
    for (int nt2 = 0; nt2 < 8; nt2++) {
        int gn = h * HD + nt2 * 8 + (lc << 1);
        float2 v0 = make_float2(oacc[nt2][0] * inv0 + macc[nt2][0],
                                oacc[nt2][1] * inv0 + macc[nt2][1]);
        float2 v1 = make_float2(oacc[nt2][2] * inv1 + macc[nt2][2],
                                oacc[nt2][3] * inv1 + macc[nt2][3]);
        *(float2*)(out + ((size_t)b * SS + grow) * D_MODEL + gn) = v0;
        *(float2*)(out + ((size_t)b * SS + grow + 8) * D_MODEL + gn) = v1;
    }
}

// ===========================================================================
extern "C" void kernel_launch(void* const* d_in, const int* in_sizes, int n_in,
                              void* d_out, int out_size)
{
    const float* x    = (const float*)d_in[0];
    const float* y    = (const float*)d_in[1];
    const float* z    = (const float*)d_in[2];
    const float* mask = (const float*)d_in[3];
    const float* wq   = (const float*)d_in[4];
    const float* bq   = (const float*)d_in[5];
    const float* wk   = (const float*)d_in[6];
    const float* bk   = (const float*)d_in[7];
    const float* wv   = (const float*)d_in[8];
    const float* bv   = (const float*)d_in[9];
    float* out = (float*)d_out;

    cudaFuncSetAttribute(proj_mma,
                         cudaFuncAttributeMaxDynamicSharedMemorySize, SMEM_PROJ);
    cudaFuncSetAttribute(flash_kernel,
                         cudaFuncAttributeMaxDynamicSharedMemorySize, SMEM_FLASH);

    dim3 g0((MROWS * D_MODEL) / (256 * 4), 7);
    cvt_kernel<<<g0, 256>>>(x, y, z, wq, wk, wv, mask);

    dim3 g1(D_MODEL / 128, MROWS / 128, 3);
    proj_mma<<<g1, 256, SMEM_PROJ>>>(bq, bk, bv);

    dim3 g2(SS / 128, BB * NH);
    flash_kernel<<<g2, 256, SMEM_FLASH>>>(out);
}

// round 6
// speedup vs baseline: 3.2188x; 1.1428x over previous
#include <cuda_runtime.h>
#include <cstdint>

#define D_MODEL 1024
#define NH 16
#define HD 64
#define BB 4
#define SS 1024
#define MROWS (BB * SS)   // 4096

// ---- scratch (tf32 bit patterns stored as uint32 / uint2 pairs) ----
__device__ uint32_t g_q[(size_t)BB * NH * SS * HD];     // plain [bh][s][d]
__device__ uint32_t g_k[(size_t)BB * NH * SS * HD];     // plain [bh][s][d]
__device__ uint32_t g_v[(size_t)BB * NH * SS * HD];     // plain [bh][s][d]
__device__ uint2    g_kp[(size_t)BB * NH * SS * (HD / 2)];     // [bh*s][32 pairs along d]
__device__ uint2    g_vtp[(size_t)BB * NH * HD * (SS / 2)];    // [bh*d][512 pairs along s]
__device__ uint2    g_xc[(size_t)MROWS * (D_MODEL / 2)];       // pair-packed along k
__device__ uint2    g_yc[(size_t)MROWS * (D_MODEL / 2)];
__device__ uint2    g_zc[(size_t)MROWS * (D_MODEL / 2)];
__device__ uint2    g_wqc[(size_t)D_MODEL * (D_MODEL / 2)];
__device__ uint2    g_wkc[(size_t)D_MODEL * (D_MODEL / 2)];
__device__ uint2    g_wvc[(size_t)D_MODEL * (D_MODEL / 2)];
__device__ uint2    g_mc[(size_t)SS * (SS / 2)];               // mask pair-packed

// ---------------------------------------------------------------------------
__device__ __forceinline__ uint32_t f2tf32(float x) {
    uint32_t r;
    asm("cvt.rna.tf32.f32 %0, %1;" : "=r"(r) : "f"(x));
    return r;
}

__device__ __forceinline__ void mma_tf32(float c[4], const uint32_t a[4], const uint32_t b[2]) {
    asm("mma.sync.aligned.m16n8k8.row.col.f32.tf32.tf32.f32 "
        "{%0,%1,%2,%3}, {%4,%5,%6,%7}, {%8,%9}, {%0,%1,%2,%3};"
        : "+f"(c[0]), "+f"(c[1]), "+f"(c[2]), "+f"(c[3])
        : "r"(a[0]), "r"(a[1]), "r"(a[2]), "r"(a[3]), "r"(b[0]), "r"(b[1]));
}

__device__ __forceinline__ void cpa16(void* dst, const void* src) {
    uint32_t d = (uint32_t)__cvta_generic_to_shared(dst);
    asm volatile("cp.async.cg.shared.global [%0], [%1], 16;\n" :: "r"(d), "l"(src));
}
#define CP_COMMIT() asm volatile("cp.async.commit_group;\n" ::)
#define CP_WAIT(n)  asm volatile("cp.async.wait_group %0;\n" :: "n"(n))

// ===========================================================================
// Kernel 0: fp32 -> tf32 conversion, pair-packed output.
// Pair layout per row of 1024: pair (g*4+j) = { v[g*8+j], v[g*8+j+4] }.
// One thread handles one 8-group (2 float4 reads -> 2 uint4 writes).
// ===========================================================================
__global__ __launch_bounds__(256) void cvt_kernel(
    const float* __restrict__ x, const float* __restrict__ y,
    const float* __restrict__ z, const float* __restrict__ wq,
    const float* __restrict__ wk, const float* __restrict__ wv,
    const float* __restrict__ mask)
{
    const float* src;
    uint2* dst;
    size_t ngroups;   // rows * 128
    switch (blockIdx.y) {
        case 0: src = x;    dst = g_xc;  ngroups = (size_t)MROWS * 128;   break;
        case 1: src = y;    dst = g_yc;  ngroups = (size_t)MROWS * 128;   break;
        case 2: src = z;    dst = g_zc;  ngroups = (size_t)MROWS * 128;   break;
        case 3: src = wq;   dst = g_wqc; ngroups = (size_t)D_MODEL * 128; break;
        case 4: src = wk;   dst = g_wkc; ngroups = (size_t)D_MODEL * 128; break;
        case 5: src = wv;   dst = g_wvc; ngroups = (size_t)D_MODEL * 128; break;
        default: src = mask; dst = g_mc; ngroups = (size_t)SS * 128;      break;
    }
    size_t gid = (size_t)blockIdx.x * 256 + threadIdx.x;
    if (gid >= ngroups) return;
    size_t row = gid >> 7;
    int g = (int)(gid & 127);
    const float4* s4 = (const float4*)(src + row * 1024 + g * 8);
    float4 a = s4[0], b = s4[1];
    uint4 u0, u1;
    u0.x = f2tf32(a.x); u0.y = f2tf32(b.x);
    u0.z = f2tf32(a.y); u0.w = f2tf32(b.y);
    u1.x = f2tf32(a.z); u1.y = f2tf32(b.z);
    u1.z = f2tf32(a.w); u1.w = f2tf32(b.w);
    uint4* d4 = (uint4*)(dst + row * 512 + g * 4);
    d4[0] = u0;
    d4[1] = u1;
}

// ===========================================================================
// Kernel 1: fused QKV projection, pair-packed tf32 operands, cp.async pipe.
// Fragment loads are LDS.64. Output Q/K/V plain tf32 [bh][s][d].
// ===========================================================================
#define PJ_LD2 20   // uint2 row stride (16 used + 4 pad; 20 % 16 == 4)
#define SMEM_PROJ (2 * 2 * 128 * PJ_LD2 * 8)   // 81920 B

__global__ __launch_bounds__(256) void proj_mma(
    const float* __restrict__ bq, const float* __restrict__ bk,
    const float* __restrict__ bv)
{
    extern __shared__ uint2 smp2[];
    uint2* Asp = smp2;                      // [2][128][20]
    uint2* Bsp = smp2 + 2 * 128 * PJ_LD2;   // [2][128][20]

    const int which = blockIdx.z;
    const uint2* A    = which == 0 ? g_xc  : (which == 1 ? g_yc  : g_zc);
    const uint2* W    = which == 0 ? g_wqc : (which == 1 ? g_wkc : g_wvc);
    const float* bias = which == 0 ? bq    : (which == 1 ? bk    : bv);
    uint32_t* out     = which == 0 ? g_q   : (which == 1 ? g_k   : g_v);

    const int tid  = threadIdx.x;
    const int lane = tid & 31;
    const int wid  = tid >> 5;
    const int wm   = wid >> 2;
    const int wn   = wid & 3;
    const int m0   = blockIdx.y * 128;
    const int n0   = blockIdx.x * 128;
    const int lr   = lane >> 2;
    const int lc   = lane & 3;

    float acc[4][4][4];
#pragma unroll
    for (int i = 0; i < 4; i++)
#pragma unroll
        for (int j = 0; j < 4; j++)
#pragma unroll
            for (int r = 0; r < 4; r++) acc[i][j][r] = 0.f;

    auto stage = [&](int buf, int ch) {
        // chunk ch covers 16 uint2 pairs per row, offset ch*16
#pragma unroll
        for (int i = 0; i < 4; i++) {
            int idx = tid + i * 256;          // 0..1023
            int r = idx >> 3;                 // 0..127
            int c = (idx & 7) << 1;           // uint2 offset 0..14
            cpa16(&Asp[buf * 128 * PJ_LD2 + r * PJ_LD2 + c],
                  A + (size_t)(m0 + r) * 512 + ch * 16 + c);
            cpa16(&Bsp[buf * 128 * PJ_LD2 + r * PJ_LD2 + c],
                  W + (size_t)(n0 + r) * 512 + ch * 16 + c);
        }
    };

    stage(0, 0);
    CP_COMMIT();

    for (int ch = 0; ch < 32; ch++) {
        if (ch + 1 < 32) { stage((ch + 1) & 1, ch + 1); CP_COMMIT(); }
        if (ch + 1 < 32) { CP_WAIT(1); } else { CP_WAIT(0); }
        __syncthreads();

        const uint2* Ab = &Asp[(ch & 1) * 128 * PJ_LD2];
        const uint2* Bb = &Bsp[(ch & 1) * 128 * PJ_LD2];
#pragma unroll
        for (int g = 0; g < 4; g++) {     // ks = g*8
            uint32_t af[4][4], bf[4][2];
#pragma unroll
            for (int ms = 0; ms < 4; ms++) {
                uint2 q0 = Ab[(wm * 64 + ms * 16 + lr) * PJ_LD2 + g * 4 + lc];
                uint2 q1 = Ab[(wm * 64 + ms * 16 + lr + 8) * PJ_LD2 + g * 4 + lc];
                af[ms][0] = q0.x; af[ms][1] = q1.x;
                af[ms][2] = q0.y; af[ms][3] = q1.y;
            }
#pragma unroll
            for (int ns = 0; ns < 4; ns++) {
                uint2 q = Bb[(wn * 32 + ns * 8 + lr) * PJ_LD2 + g * 4 + lc];
                bf[ns][0] = q.x; bf[ns][1] = q.y;
            }
#pragma unroll
            for (int ms = 0; ms < 4; ms++)
#pragma unroll
                for (int ns = 0; ns < 4; ns++)
                    mma_tf32(acc[ms][ns], af[ms], bf[ns]);
        }
        __syncthreads();
    }

#pragma unroll
    for (int ms = 0; ms < 4; ms++) {
#pragma unroll
        for (int ns = 0; ns < 4; ns++) {
            int gm = m0 + wm * 64 + ms * 16 + lr;
            int gn = n0 + wn * 32 + ns * 8 + (lc << 1);
            float bx = bias[gn], by = bias[gn + 1];
            int h = gn >> 6, d = gn & 63;
            {
                int b = gm >> 10, s = gm & 1023;
                uint2 v = make_uint2(f2tf32(acc[ms][ns][0] + bx),
                                     f2tf32(acc[ms][ns][1] + by));
                *(uint2*)(out + (((size_t)(b * NH + h)) * SS + s) * HD + d) = v;
            }
            {
                int gm2 = gm + 8;
                int b = gm2 >> 10, s = gm2 & 1023;
                uint2 v = make_uint2(f2tf32(acc[ms][ns][2] + bx),
                                     f2tf32(acc[ms][ns][3] + by));
                *(uint2*)(out + (((size_t)(b * NH + h)) * SS + s) * HD + d) = v;
            }
        }
    }
}

// ===========================================================================
// Kernel 1b: repack K -> pairs along d:  g_kp[row][g*4+j] = {K[d=g*8+j], K[d+4]}
// ===========================================================================
__global__ __launch_bounds__(256) void kpack_kernel()
{
    size_t p = (size_t)blockIdx.x * 256 + threadIdx.x;   // 0 .. 64*1024*32-1
    size_t row = p >> 5;
    int i = (int)(p & 31);
    int g = i >> 2, j = i & 3;
    uint32_t a = g_k[row * 64 + g * 8 + j];
    uint32_t b = g_k[row * 64 + g * 8 + j + 4];
    g_kp[p] = make_uint2(a, b);
}

// ===========================================================================
// Kernel 1c: repack V -> transposed + pairs along s:
//   g_vtp[(bh*64+d)*512 + st*64 + g*4+j] = {V[s=st*128+g*8+j][d], V[s+4][d]}
// One block per (s-tile, head): smem transpose keeps gmem coalesced both ways.
// ===========================================================================
__global__ __launch_bounds__(256) void vpack_kernel()
{
    __shared__ uint32_t vt[128 * 65];
    const int st = blockIdx.x;     // 0..7
    const int bh = blockIdx.y;     // 0..63
    const int tid = threadIdx.x;

    const uint32_t* src = g_v + ((size_t)bh * SS + st * 128) * HD;
#pragma unroll
    for (int i = 0; i < 8; i++) {
        int idx = i * 256 + tid;       // 0..2047
        int r = idx >> 4;              // 0..127
        int c = (idx & 15) << 2;       // 0..60
        uint4 v = *(const uint4*)(src + (size_t)r * HD + c);
        vt[r * 65 + c + 0] = v.x;
        vt[r * 65 + c + 1] = v.y;
        vt[r * 65 + c + 2] = v.z;
        vt[r * 65 + c + 3] = v.w;
    }
    __syncthreads();

#pragma unroll
    for (int i = 0; i < 16; i++) {
        int idx = i * 256 + tid;       // 0..4095
        int d = idx >> 6;              // 0..63
        int i6 = idx & 63;             // pair within tile
        int g = i6 >> 2, j = i6 & 3;
        int s = g * 8 + j;
        uint2 o = make_uint2(vt[s * 65 + d], vt[(s + 4) * 65 + d]);
        g_vtp[((size_t)bh * 64 + d) * 512 + st * 64 + i6] = o;
    }
}

// ===========================================================================
// Kernel 2: fused flash attention + mask@V, pair-packed K/V/mask operands.
//   out = softmax(QK^T/32) @ V + mask @ V
// ===========================================================================
#define KS_LD2 36   // uint2 stride (32 used; 36 % 16 == 4)
#define VS_LD2 68   // uint2 stride (64 used; 68 % 16 == 4)
#define PS_LD 132
#define KS_SZ2 (128 * KS_LD2)
#define VS_SZ2 (64 * VS_LD2)
#define SMEM_FLASH (2 * KS_SZ2 * 8 + 2 * VS_SZ2 * 8 + 128 * PS_LD * 4)  // 210944 B

__global__ __launch_bounds__(256, 1) void flash_kernel(float* __restrict__ out)
{
    extern __shared__ uint2 smf2[];
    uint2* Ksp = smf2;                        // [2][128][36]
    uint2* Vsp = smf2 + 2 * KS_SZ2;           // [2][64][68]
    uint32_t* Ps = (uint32_t*)(smf2 + 2 * KS_SZ2 + 2 * VS_SZ2);  // [128][132]

    const int tid  = threadIdx.x;
    const int lane = tid & 31;
    const int wm   = tid >> 5;
    const int lr   = lane >> 2;
    const int lc   = lane & 3;

    const int qt = blockIdx.x;
    const int bh = blockIdx.y;
    const int b  = bh >> 4, h = bh & 15;

    const uint32_t* Qg = g_q + (size_t)bh * SS * HD + (size_t)qt * 128 * HD;
    const uint2* Kgp = g_kp + (size_t)bh * SS * 32;
    const uint2* Vgp = g_vtp + (size_t)bh * 64 * 512;
    const uint2* Mgp = g_mc + (size_t)(qt * 128 + wm * 16 + lr) * 512;

    auto stageKV = [&](int kt, int buf) {
#pragma unroll
        for (int i = 0; i < 8; i++) {
            int idx = i * 256 + tid;          // 0..2047
            {   // K: 128 rows x 16 cpa16
                int r = idx >> 4;
                int c = (idx & 15) << 1;      // uint2 offset
                cpa16(&Ksp[buf * KS_SZ2 + r * KS_LD2 + c],
                      Kgp + (size_t)(kt * 128 + r) * 32 + c);
            }
            {   // V: 64 rows x 32 cpa16
                int r = idx >> 5;
                int c = (idx & 31) << 1;
                cpa16(&Vsp[buf * VS_SZ2 + r * VS_LD2 + c],
                      Vgp + (size_t)r * 512 + kt * 64 + c);
            }
        }
    };

    // ---- prologue: K/V tile 0 + Q staging (plain) in one cp.async group ----
    stageKV(0, 0);
#pragma unroll
    for (int i = 0; i < 2; i++) {
        int idx = i * 256 + tid;
        int r = idx >> 2;               // 0..127
        int c = (idx & 3) << 4;         // 0,16,32,48
#pragma unroll
        for (int cc = 0; cc < 16; cc += 4)
            cpa16(&Ps[r * PS_LD + c + cc], Qg + (size_t)r * HD + c + cc);
    }
    CP_COMMIT();
    CP_WAIT(0);
    __syncthreads();

    uint32_t qf[8][4];
#pragma unroll
    for (int ks = 0; ks < 8; ks++) {
        const uint32_t* p = &Ps[(wm * 16 + lr) * PS_LD + ks * 8 + lc];
        qf[ks][0] = p[0];
        qf[ks][1] = p[8 * PS_LD];
        qf[ks][2] = p[4];
        qf[ks][3] = p[8 * PS_LD + 4];
    }
    __syncthreads();

    float m0 = -1e30f, m1 = -1e30f;
    float l0 = 0.f, l1 = 0.f;
    float oacc[8][4], macc[8][4];
#pragma unroll
    for (int i = 0; i < 8; i++)
#pragma unroll
        for (int r = 0; r < 4; r++) { oacc[i][r] = 0.f; macc[i][r] = 0.f; }

    const float scale = 0.03125f;
    const int row = wm * 16 + lr;

    for (int kt = 0; kt < 8; kt++) {
        if (kt + 1 < 8) { stageKV(kt + 1, (kt + 1) & 1); CP_COMMIT(); }
        if (kt + 1 < 8) { CP_WAIT(1); } else { CP_WAIT(0); }
        __syncthreads();

        const uint2* Ksb = &Ksp[(kt & 1) * KS_SZ2];
        const uint2* Vsb = &Vsp[(kt & 1) * VS_SZ2];

        // ---- QK^T ----
        float sacc[16][4];
#pragma unroll
        for (int nt = 0; nt < 16; nt++)
#pragma unroll
            for (int r = 0; r < 4; r++) sacc[nt][r] = 0.f;

#pragma unroll
        for (int ks = 0; ks < 8; ks++) {
#pragma unroll
            for (int nt = 0; nt < 16; nt++) {
                uint2 kq = Ksb[(nt * 8 + lr) * KS_LD2 + ks * 4 + lc];
                uint32_t bf[2] = {kq.x, kq.y};
                mma_tf32(sacc[nt], qf[ks], bf);
            }
        }

        // ---- online softmax ----
        float rm0 = -1e30f, rm1 = -1e30f;
#pragma unroll
        for (int nt = 0; nt < 16; nt++) {
            rm0 = fmaxf(rm0, fmaxf(sacc[nt][0], sacc[nt][1]));
            rm1 = fmaxf(rm1, fmaxf(sacc[nt][2], sacc[nt][3]));
        }
#pragma unroll
        for (int o = 1; o <= 2; o <<= 1) {
            rm0 = fmaxf(rm0, __shfl_xor_sync(0xffffffffu, rm0, o));
            rm1 = fmaxf(rm1, __shfl_xor_sync(0xffffffffu, rm1, o));
        }
        float mn0 = fmaxf(m0, rm0 * scale);
        float mn1 = fmaxf(m1, rm1 * scale);
        float a0 = __expf(m0 - mn0);
        float a1 = __expf(m1 - mn1);
        m0 = mn0; m1 = mn1;

        float ps0 = 0.f, ps1 = 0.f;
#pragma unroll
        for (int nt = 0; nt < 16; nt++) {
            float p0 = __expf(fmaf(sacc[nt][0], scale, -mn0));
            float p1 = __expf(fmaf(sacc[nt][1], scale, -mn0));
            float p2 = __expf(fmaf(sacc[nt][2], scale, -mn1));
            float p3 = __expf(fmaf(sacc[nt][3], scale, -mn1));
            ps0 += p0 + p1;
            ps1 += p2 + p3;
            uint32_t* pp = &Ps[row * PS_LD + nt * 8 + (lc << 1)];
            pp[0] = f2tf32(p0);
            pp[1] = f2tf32(p1);
            pp[8 * PS_LD] = f2tf32(p2);
            pp[8 * PS_LD + 1] = f2tf32(p3);
        }
#pragma unroll
        for (int o = 1; o <= 2; o <<= 1) {
            ps0 += __shfl_xor_sync(0xffffffffu, ps0, o);
            ps1 += __shfl_xor_sync(0xffffffffu, ps1, o);
        }
        l0 = l0 * a0 + ps0;
        l1 = l1 * a1 + ps1;

#pragma unroll
        for (int i = 0; i < 8; i++) {
            oacc[i][0] *= a0; oacc[i][1] *= a0;
            oacc[i][2] *= a1; oacc[i][3] *= a1;
        }
        __syncwarp();

        // ---- (P @ V) and (mask @ V) sharing V fragments ----
#pragma unroll
        for (int ks2 = 0; ks2 < 16; ks2++) {
            uint32_t pa[4], ma[4];
            const uint32_t* pp = &Ps[row * PS_LD + ks2 * 8 + lc];
            pa[0] = pp[0];
            pa[1] = pp[8 * PS_LD];
            pa[2] = pp[4];
            pa[3] = pp[8 * PS_LD + 4];
            uint2 m02 = Mgp[kt * 64 + ks2 * 4 + lc];
            uint2 m13 = Mgp[8 * 512 + kt * 64 + ks2 * 4 + lc];
            ma[0] = m02.x; ma[1] = m13.x;
            ma[2] = m02.y; ma[3] = m13.y;
#pragma unroll
            for (int nt2 = 0; nt2 < 8; nt2++) {
                uint2 vq = Vsb[(nt2 * 8 + lr) * VS_LD2 + ks2 * 4 + lc];
                uint32_t vb[2] = {vq.x, vq.y};
                mma_tf32(oacc[nt2], pa, vb);
                mma_tf32(macc[nt2], ma, vb);
            }
        }
        __syncthreads();
    }

    // ---- epilogue ----
    const float inv0 = 1.0f / l0;
    const float inv1 = 1.0f / l1;
    const int grow = qt * 128 + wm * 16 + lr;
#pragma unroll
    for (int nt2 = 0; nt2 < 8; nt2++) {
        int gn = h * HD + nt2 * 8 + (lc << 1);
        float2 v0 = make_float2(oacc[nt2][0] * inv0 + macc[nt2][0],
                                oacc[nt2][1] * inv0 + macc[nt2][1]);
        float2 v1 = make_float2(oacc[nt2][2] * inv1 + macc[nt2][2],
                                oacc[nt2][3] * inv1 + macc[nt2][3]);
        *(float2*)(out + ((size_t)b * SS + grow) * D_MODEL + gn) = v0;
        *(float2*)(out + ((size_t)b * SS + grow + 8) * D_MODEL + gn) = v1;
    }
}

// ===========================================================================
extern "C" void kernel_launch(void* const* d_in, const int* in_sizes, int n_in,
                              void* d_out, int out_size)
{
    const float* x    = (const float*)d_in[0];
    const float* y    = (const float*)d_in[1];
    const float* z    = (const float*)d_in[2];
    const float* mask = (const float*)d_in[3];
    const float* bq   = (const float*)d_in[5];
    const float* bk   = (const float*)d_in[7];
    const float* bv   = (const float*)d_in[9];
    const float* wq   = (const float*)d_in[4];
    const float* wk   = (const float*)d_in[6];
    const float* wv   = (const float*)d_in[8];
    float* out = (float*)d_out;

    cudaFuncSetAttribute(proj_mma,
                         cudaFuncAttributeMaxDynamicSharedMemorySize, SMEM_PROJ);
    cudaFuncSetAttribute(flash_kernel,
                         cudaFuncAttributeMaxDynamicSharedMemorySize, SMEM_FLASH);

    dim3 g0((MROWS * D_MODEL / 8 + 255) / 256, 7);
    cvt_kernel<<<g0, 256>>>(x, y, z, wq, wk, wv, mask);

    dim3 g1(D_MODEL / 128, MROWS / 128, 3);
    proj_mma<<<g1, 256, SMEM_PROJ>>>(bq, bk, bv);

    kpack_kernel<<<(BB * NH * SS * 32) / 256, 256>>>();
    dim3 gv(SS / 128, BB * NH);
    vpack_kernel<<<gv, 256>>>();

    dim3 g2(SS / 128, BB * NH);
    flash_kernel<<<g2, 256, SMEM_FLASH>>>(out);
}

// round 7
// speedup vs baseline: 3.2475x; 1.0089x over previous
#include <cuda_runtime.h>
#include <cstdint>

#define D_MODEL 1024
#define NH 16
#define HD 64
#define BB 4
#define SS 1024
#define MROWS (BB * SS)   // 4096

// ---- scratch (tf32 bit patterns stored as uint32 / uint2 pairs) ----
__device__ uint32_t g_q[(size_t)BB * NH * SS * HD];     // plain [bh][s][d]
__device__ uint32_t g_k[(size_t)BB * NH * SS * HD];     // plain [bh][s][d]
__device__ uint32_t g_v[(size_t)BB * NH * SS * HD];     // plain [bh][s][d]
__device__ uint2    g_kp[(size_t)BB * NH * SS * (HD / 2)];     // [bh*s][32 pairs along d]
__device__ uint2    g_vtp[(size_t)BB * NH * HD * (SS / 2)];    // [bh*d][512 pairs along s]
__device__ uint2    g_xc[(size_t)MROWS * (D_MODEL / 2)];       // pair-packed along k
__device__ uint2    g_yc[(size_t)MROWS * (D_MODEL / 2)];
__device__ uint2    g_zc[(size_t)MROWS * (D_MODEL / 2)];
__device__ uint2    g_wqc[(size_t)D_MODEL * (D_MODEL / 2)];
__device__ uint2    g_wkc[(size_t)D_MODEL * (D_MODEL / 2)];
__device__ uint2    g_wvc[(size_t)D_MODEL * (D_MODEL / 2)];
__device__ uint2    g_mc[(size_t)SS * (SS / 2)];               // mask pair-packed

// ---------------------------------------------------------------------------
__device__ __forceinline__ uint32_t f2tf32(float x) {
    uint32_t r;
    asm("cvt.rna.tf32.f32 %0, %1;" : "=r"(r) : "f"(x));
    return r;
}

__device__ __forceinline__ void mma_tf32(float c[4], const uint32_t a[4], const uint32_t b[2]) {
    asm("mma.sync.aligned.m16n8k8.row.col.f32.tf32.tf32.f32 "
        "{%0,%1,%2,%3}, {%4,%5,%6,%7}, {%8,%9}, {%0,%1,%2,%3};"
        : "+f"(c[0]), "+f"(c[1]), "+f"(c[2]), "+f"(c[3])
        : "r"(a[0]), "r"(a[1]), "r"(a[2]), "r"(a[3]), "r"(b[0]), "r"(b[1]));
}

__device__ __forceinline__ void cpa16(void* dst, const void* src) {
    uint32_t d = (uint32_t)__cvta_generic_to_shared(dst);
    asm volatile("cp.async.cg.shared.global [%0], [%1], 16;\n" :: "r"(d), "l"(src));
}
#define CP_COMMIT() asm volatile("cp.async.commit_group;\n" ::)
#define CP_WAIT(n)  asm volatile("cp.async.wait_group %0;\n" :: "n"(n))

// ===========================================================================
// Kernel 0: fp32 -> tf32 conversion, pair-packed output. (unchanged)
// ===========================================================================
__global__ __launch_bounds__(256) void cvt_kernel(
    const float* __restrict__ x, const float* __restrict__ y,
    const float* __restrict__ z, const float* __restrict__ wq,
    const float* __restrict__ wk, const float* __restrict__ wv,
    const float* __restrict__ mask)
{
    const float* src;
    uint2* dst;
    size_t ngroups;
    switch (blockIdx.y) {
        case 0: src = x;    dst = g_xc;  ngroups = (size_t)MROWS * 128;   break;
        case 1: src = y;    dst = g_yc;  ngroups = (size_t)MROWS * 128;   break;
        case 2: src = z;    dst = g_zc;  ngroups = (size_t)MROWS * 128;   break;
        case 3: src = wq;   dst = g_wqc; ngroups = (size_t)D_MODEL * 128; break;
        case 4: src = wk;   dst = g_wkc; ngroups = (size_t)D_MODEL * 128; break;
        case 5: src = wv;   dst = g_wvc; ngroups = (size_t)D_MODEL * 128; break;
        default: src = mask; dst = g_mc; ngroups = (size_t)SS * 128;      break;
    }
    size_t gid = (size_t)blockIdx.x * 256 + threadIdx.x;
    if (gid >= ngroups) return;
    size_t row = gid >> 7;
    int g = (int)(gid & 127);
    const float4* s4 = (const float4*)(src + row * 1024 + g * 8);
    float4 a = s4[0], b = s4[1];
    uint4 u0, u1;
    u0.x = f2tf32(a.x); u0.y = f2tf32(b.x);
    u0.z = f2tf32(a.y); u0.w = f2tf32(b.y);
    u1.x = f2tf32(a.z); u1.y = f2tf32(b.z);
    u1.z = f2tf32(a.w); u1.w = f2tf32(b.w);
    uint4* d4 = (uint4*)(dst + row * 512 + g * 4);
    d4[0] = u0;
    d4[1] = u1;
}

// ===========================================================================
// Kernel 1: fused QKV projection (unchanged from R6).
// ===========================================================================
#define PJ_LD2 20
#define SMEM_PROJ (2 * 2 * 128 * PJ_LD2 * 8)   // 81920 B

__global__ __launch_bounds__(256) void proj_mma(
    const float* __restrict__ bq, const float* __restrict__ bk,
    const float* __restrict__ bv)
{
    extern __shared__ uint2 smp2[];
    uint2* Asp = smp2;
    uint2* Bsp = smp2 + 2 * 128 * PJ_LD2;

    const int which = blockIdx.z;
    const uint2* A    = which == 0 ? g_xc  : (which == 1 ? g_yc  : g_zc);
    const uint2* W    = which == 0 ? g_wqc : (which == 1 ? g_wkc : g_wvc);
    const float* bias = which == 0 ? bq    : (which == 1 ? bk    : bv);
    uint32_t* out     = which == 0 ? g_q   : (which == 1 ? g_k   : g_v);

    const int tid  = threadIdx.x;
    const int lane = tid & 31;
    const int wid  = tid >> 5;
    const int wm   = wid >> 2;
    const int wn   = wid & 3;
    const int m0   = blockIdx.y * 128;
    const int n0   = blockIdx.x * 128;
    const int lr   = lane >> 2;
    const int lc   = lane & 3;

    float acc[4][4][4];
#pragma unroll
    for (int i = 0; i < 4; i++)
#pragma unroll
        for (int j = 0; j < 4; j++)
#pragma unroll
            for (int r = 0; r < 4; r++) acc[i][j][r] = 0.f;

    auto stage = [&](int buf, int ch) {
#pragma unroll
        for (int i = 0; i < 4; i++) {
            int idx = tid + i * 256;
            int r = idx >> 3;
            int c = (idx & 7) << 1;
            cpa16(&Asp[buf * 128 * PJ_LD2 + r * PJ_LD2 + c],
                  A + (size_t)(m0 + r) * 512 + ch * 16 + c);
            cpa16(&Bsp[buf * 128 * PJ_LD2 + r * PJ_LD2 + c],
                  W + (size_t)(n0 + r) * 512 + ch * 16 + c);
        }
    };

    stage(0, 0);
    CP_COMMIT();

    for (int ch = 0; ch < 32; ch++) {
        if (ch + 1 < 32) { stage((ch + 1) & 1, ch + 1); CP_COMMIT(); }
        if (ch + 1 < 32) { CP_WAIT(1); } else { CP_WAIT(0); }
        __syncthreads();

        const uint2* Ab = &Asp[(ch & 1) * 128 * PJ_LD2];
        const uint2* Bb = &Bsp[(ch & 1) * 128 * PJ_LD2];
#pragma unroll
        for (int g = 0; g < 4; g++) {
            uint32_t af[4][4], bf[4][2];
#pragma unroll
            for (int ms = 0; ms < 4; ms++) {
                uint2 q0 = Ab[(wm * 64 + ms * 16 + lr) * PJ_LD2 + g * 4 + lc];
                uint2 q1 = Ab[(wm * 64 + ms * 16 + lr + 8) * PJ_LD2 + g * 4 + lc];
                af[ms][0] = q0.x; af[ms][1] = q1.x;
                af[ms][2] = q0.y; af[ms][3] = q1.y;
            }
#pragma unroll
            for (int ns = 0; ns < 4; ns++) {
                uint2 q = Bb[(wn * 32 + ns * 8 + lr) * PJ_LD2 + g * 4 + lc];
                bf[ns][0] = q.x; bf[ns][1] = q.y;
            }
#pragma unroll
            for (int ms = 0; ms < 4; ms++)
#pragma unroll
                for (int ns = 0; ns < 4; ns++)
                    mma_tf32(acc[ms][ns], af[ms], bf[ns]);
        }
        __syncthreads();
    }

#pragma unroll
    for (int ms = 0; ms < 4; ms++) {
#pragma unroll
        for (int ns = 0; ns < 4; ns++) {
            int gm = m0 + wm * 64 + ms * 16 + lr;
            int gn = n0 + wn * 32 + ns * 8 + (lc << 1);
            float bx = bias[gn], by = bias[gn + 1];
            int h = gn >> 6, d = gn & 63;
            {
                int b = gm >> 10, s = gm & 1023;
                uint2 v = make_uint2(f2tf32(acc[ms][ns][0] + bx),
                                     f2tf32(acc[ms][ns][1] + by));
                *(uint2*)(out + (((size_t)(b * NH + h)) * SS + s) * HD + d) = v;
            }
            {
                int gm2 = gm + 8;
                int b = gm2 >> 10, s = gm2 & 1023;
                uint2 v = make_uint2(f2tf32(acc[ms][ns][2] + bx),
                                     f2tf32(acc[ms][ns][3] + by));
                *(uint2*)(out + (((size_t)(b * NH + h)) * SS + s) * HD + d) = v;
            }
        }
    }
}

// ===========================================================================
// Kernel 1b/1c: K/V repacks (unchanged from R6).
// ===========================================================================
__global__ __launch_bounds__(256) void kpack_kernel()
{
    size_t p = (size_t)blockIdx.x * 256 + threadIdx.x;
    size_t row = p >> 5;
    int i = (int)(p & 31);
    int g = i >> 2, j = i & 3;
    uint32_t a = g_k[row * 64 + g * 8 + j];
    uint32_t b = g_k[row * 64 + g * 8 + j + 4];
    g_kp[p] = make_uint2(a, b);
}

__global__ __launch_bounds__(256) void vpack_kernel()
{
    __shared__ uint32_t vt[128 * 65];
    const int st = blockIdx.x;
    const int bh = blockIdx.y;
    const int tid = threadIdx.x;

    const uint32_t* src = g_v + ((size_t)bh * SS + st * 128) * HD;
#pragma unroll
    for (int i = 0; i < 8; i++) {
        int idx = i * 256 + tid;
        int r = idx >> 4;
        int c = (idx & 15) << 2;
        uint4 v = *(const uint4*)(src + (size_t)r * HD + c);
        vt[r * 65 + c + 0] = v.x;
        vt[r * 65 + c + 1] = v.y;
        vt[r * 65 + c + 2] = v.z;
        vt[r * 65 + c + 3] = v.w;
    }
    __syncthreads();

#pragma unroll
    for (int i = 0; i < 16; i++) {
        int idx = i * 256 + tid;
        int d = idx >> 6;
        int i6 = idx & 63;
        int g = i6 >> 2, j = i6 & 3;
        int s = g * 8 + j;
        uint2 o = make_uint2(vt[s * 65 + d], vt[(s + 4) * 65 + d]);
        g_vtp[((size_t)bh * 64 + d) * 512 + st * 64 + i6] = o;
    }
}

// ===========================================================================
// Kernel 2: fused flash attention + mask@V.
// Single-buffered K / V / MASK smem tiles, split-group cp.async pipeline:
//   K[kt+1] staged post-QK (hidden behind softmax+PV)
//   V[kt+1], M[kt+1] staged post-PV (hidden behind next QK)
// Mask is consumed from smem (LDS) instead of per-iteration LDG.
// ===========================================================================
#define KS_LD2 36
#define VS_LD2 68
#define MS_LD2 68
#define PS_LD 132
#define KS_SZ2 (128 * KS_LD2)
#define VS_SZ2 (64 * VS_LD2)
#define MS_SZ2 (128 * MS_LD2)
#define SMEM_FLASH (KS_SZ2 * 8 + VS_SZ2 * 8 + MS_SZ2 * 8 + 128 * PS_LD * 4)  // 208896 B

__global__ __launch_bounds__(256, 1) void flash_kernel(float* __restrict__ out)
{
    extern __shared__ uint2 smf2[];
    uint2* Ksp = smf2;                               // [128][36]
    uint2* Vsp = smf2 + KS_SZ2;                      // [64][68]
    uint2* Msp = smf2 + KS_SZ2 + VS_SZ2;             // [128][68]
    uint32_t* Ps = (uint32_t*)(smf2 + KS_SZ2 + VS_SZ2 + MS_SZ2);  // [128][132]

    const int tid  = threadIdx.x;
    const int lane = tid & 31;
    const int wm   = tid >> 5;
    const int lr   = lane >> 2;
    const int lc   = lane & 3;

    const int qt = blockIdx.x;
    const int bh = blockIdx.y;
    const int b  = bh >> 4, h = bh & 15;

    const uint32_t* Qg = g_q + (size_t)bh * SS * HD + (size_t)qt * 128 * HD;
    const uint2* Kgp = g_kp + (size_t)bh * SS * 32;
    const uint2* Vgp = g_vtp + (size_t)bh * 64 * 512;
    const uint2* Mg0 = g_mc + (size_t)qt * 128 * 512;   // block's 128 mask rows

    auto stageK = [&](int kt) {
#pragma unroll
        for (int i = 0; i < 8; i++) {
            int idx = i * 256 + tid;
            int r = idx >> 4;
            int c = (idx & 15) << 1;
            cpa16(&Ksp[r * KS_LD2 + c], Kgp + (size_t)(kt * 128 + r) * 32 + c);
        }
    };
    auto stageV = [&](int kt) {
#pragma unroll
        for (int i = 0; i < 8; i++) {
            int idx = i * 256 + tid;
            int r = idx >> 5;
            int c = (idx & 31) << 1;
            cpa16(&Vsp[r * VS_LD2 + c], Vgp + (size_t)r * 512 + kt * 64 + c);
        }
    };
    auto stageM = [&](int kt) {
#pragma unroll
        for (int i = 0; i < 16; i++) {
            int idx = i * 256 + tid;
            int r = idx >> 5;
            int c = (idx & 31) << 1;
            cpa16(&Msp[r * MS_LD2 + c], Mg0 + (size_t)r * 512 + kt * 64 + c);
        }
    };

    // ---- prologue: stage K/V/M tile 0 + Q, one group ----
    stageK(0);
    stageV(0);
    stageM(0);
#pragma unroll
    for (int i = 0; i < 2; i++) {
        int idx = i * 256 + tid;
        int r = idx >> 2;
        int c = (idx & 3) << 4;
#pragma unroll
        for (int cc = 0; cc < 16; cc += 4)
            cpa16(&Ps[r * PS_LD + c + cc], Qg + (size_t)r * HD + c + cc);
    }
    CP_COMMIT();
    CP_WAIT(0);
    __syncthreads();

    uint32_t qf[8][4];
#pragma unroll
    for (int ks = 0; ks < 8; ks++) {
        const uint32_t* p = &Ps[(wm * 16 + lr) * PS_LD + ks * 8 + lc];
        qf[ks][0] = p[0];
        qf[ks][1] = p[8 * PS_LD];
        qf[ks][2] = p[4];
        qf[ks][3] = p[8 * PS_LD + 4];
    }
    // qf reads & later P writes touch only this warp's own rows -> no block sync

    float m0 = -1e30f, m1 = -1e30f;
    float l0 = 0.f, l1 = 0.f;
    float oacc[8][4], macc[8][4];
#pragma unroll
    for (int i = 0; i < 8; i++)
#pragma unroll
        for (int r = 0; r < 4; r++) { oacc[i][r] = 0.f; macc[i][r] = 0.f; }

    const float scale = 0.03125f;
    const int row = wm * 16 + lr;

    for (int kt = 0; kt < 8; kt++) {
        // ---- QK^T (reads Ksp; K[kt] guaranteed ready) ----
        float sacc[16][4];
#pragma unroll
        for (int nt = 0; nt < 16; nt++)
#pragma unroll
            for (int r = 0; r < 4; r++) sacc[nt][r] = 0.f;

#pragma unroll
        for (int ks = 0; ks < 8; ks++) {
#pragma unroll
            for (int nt = 0; nt < 16; nt++) {
                uint2 kq = Ksp[(nt * 8 + lr) * KS_LD2 + ks * 4 + lc];
                uint32_t bf[2] = {kq.x, kq.y};
                mma_tf32(sacc[nt], qf[ks], bf);
            }
        }

        // V[kt]/M[kt] group must be complete before PV; also frees K for restage
        CP_WAIT(0);
        __syncthreads();
        if (kt + 1 < 8) { stageK(kt + 1); CP_COMMIT(); }   // hidden behind softmax+PV

        // ---- online softmax ----
        float rm0 = -1e30f, rm1 = -1e30f;
#pragma unroll
        for (int nt = 0; nt < 16; nt++) {
            rm0 = fmaxf(rm0, fmaxf(sacc[nt][0], sacc[nt][1]));
            rm1 = fmaxf(rm1, fmaxf(sacc[nt][2], sacc[nt][3]));
        }
#pragma unroll
        for (int o = 1; o <= 2; o <<= 1) {
            rm0 = fmaxf(rm0, __shfl_xor_sync(0xffffffffu, rm0, o));
            rm1 = fmaxf(rm1, __shfl_xor_sync(0xffffffffu, rm1, o));
        }
        float mn0 = fmaxf(m0, rm0 * scale);
        float mn1 = fmaxf(m1, rm1 * scale);
        float a0 = __expf(m0 - mn0);
        float a1 = __expf(m1 - mn1);
        m0 = mn0; m1 = mn1;

        float ps0 = 0.f, ps1 = 0.f;
#pragma unroll
        for (int nt = 0; nt < 16; nt++) {
            float p0 = __expf(fmaf(sacc[nt][0], scale, -mn0));
            float p1 = __expf(fmaf(sacc[nt][1], scale, -mn0));
            float p2 = __expf(fmaf(sacc[nt][2], scale, -mn1));
            float p3 = __expf(fmaf(sacc[nt][3], scale, -mn1));
            ps0 += p0 + p1;
            ps1 += p2 + p3;
            uint32_t* pp = &Ps[row * PS_LD + nt * 8 + (lc << 1)];
            pp[0] = f2tf32(p0);
            pp[1] = f2tf32(p1);
            pp[8 * PS_LD] = f2tf32(p2);
            pp[8 * PS_LD + 1] = f2tf32(p3);
        }
#pragma unroll
        for (int o = 1; o <= 2; o <<= 1) {
            ps0 += __shfl_xor_sync(0xffffffffu, ps0, o);
            ps1 += __shfl_xor_sync(0xffffffffu, ps1, o);
        }
        l0 = l0 * a0 + ps0;
        l1 = l1 * a1 + ps1;

#pragma unroll
        for (int i = 0; i < 8; i++) {
            oacc[i][0] *= a0; oacc[i][1] *= a0;
            oacc[i][2] *= a1; oacc[i][3] *= a1;
        }
        __syncwarp();

        // ---- (P @ V) and (mask @ V), all operands from smem ----
#pragma unroll
        for (int ks2 = 0; ks2 < 16; ks2++) {
            uint32_t pa[4], ma[4];
            const uint32_t* pp = &Ps[row * PS_LD + ks2 * 8 + lc];
            pa[0] = pp[0];
            pa[1] = pp[8 * PS_LD];
            pa[2] = pp[4];
            pa[3] = pp[8 * PS_LD + 4];
            uint2 m02 = Msp[(wm * 16 + lr) * MS_LD2 + ks2 * 4 + lc];
            uint2 m13 = Msp[(wm * 16 + lr + 8) * MS_LD2 + ks2 * 4 + lc];
            ma[0] = m02.x; ma[1] = m13.x;
            ma[2] = m02.y; ma[3] = m13.y;
#pragma unroll
            for (int nt2 = 0; nt2 < 8; nt2++) {
                uint2 vq = Vsp[(nt2 * 8 + lr) * VS_LD2 + ks2 * 4 + lc];
                uint32_t vb[2] = {vq.x, vq.y};
                mma_tf32(oacc[nt2], pa, vb);
                mma_tf32(macc[nt2], ma, vb);
            }
        }

        if (kt + 1 < 8) {
            __syncthreads();                 // all warps done with V/M tiles
            stageV(kt + 1);
            stageM(kt + 1);
            CP_COMMIT();                     // hidden behind next QK
            CP_WAIT(1);                      // K[kt+1] (older group) done
            __syncthreads();                 // K visible to all warps
        }
    }

    // ---- epilogue ----
    const float inv0 = 1.0f / l0;
    const float inv1 = 1.0f / l1;
    const int grow = qt * 128 + wm * 16 + lr;
#pragma unroll
    for (int nt2 = 0; nt2 < 8; nt2++) {
        int gn = h * HD + nt2 * 8 + (lc << 1);
        float2 v0 = make_float2(oacc[nt2][0] * inv0 + macc[nt2][0],
                                oacc[nt2][1] * inv0 + macc[nt2][1]);
        float2 v1 = make_float2(oacc[nt2][2] * inv1 + macc[nt2][2],
                                oacc[nt2][3] * inv1 + macc[nt2][3]);
        *(float2*)(out + ((size_t)b * SS + grow) * D_MODEL + gn) = v0;
        *(float2*)(out + ((size_t)b * SS + grow + 8) * D_MODEL + gn) = v1;
    }
}

// ===========================================================================
extern "C" void kernel_launch(void* const* d_in, const int* in_sizes, int n_in,
                              void* d_out, int out_size)
{
    const float* x    = (const float*)d_in[0];
    const float* y    = (const float*)d_in[1];
    const float* z    = (const float*)d_in[2];
    const float* mask = (const float*)d_in[3];
    const float* wq   = (const float*)d_in[4];
    const float* bq   = (const float*)d_in[5];
    const float* wk   = (const float*)d_in[6];
    const float* bk   = (const float*)d_in[7];
    const float* wv   = (const float*)d_in[8];
    const float* bv   = (const float*)d_in[9];
    float* out = (float*)d_out;

    cudaFuncSetAttribute(proj_mma,
                         cudaFuncAttributeMaxDynamicSharedMemorySize, SMEM_PROJ);
    cudaFuncSetAttribute(flash_kernel,
                         cudaFuncAttributeMaxDynamicSharedMemorySize, SMEM_FLASH);

    dim3 g0((MROWS * D_MODEL / 8 + 255) / 256, 7);
    cvt_kernel<<<g0, 256>>>(x, y, z, wq, wk, wv, mask);

    dim3 g1(D_MODEL / 128, MROWS / 128, 3);
    proj_mma<<<g1, 256, SMEM_PROJ>>>(bq, bk, bv);

    kpack_kernel<<<(BB * NH * SS * 32) / 256, 256>>>();
    dim3 gv(SS / 128, BB * NH);
    vpack_kernel<<<gv, 256>>>();

    dim3 g2(SS / 128, BB * NH);
    flash_kernel<<<g2, 256, SMEM_FLASH>>>(out);
}

// round 9
// speedup vs baseline: 3.4326x; 1.0570x over previous
#include <cuda_runtime.h>
#include <cstdint>

#define D_MODEL 1024
#define NH 16
#define HD 64
#define BB 4
#define SS 1024
#define MROWS (BB * SS)   // 4096

// ---- scratch (tf32 bit patterns stored as uint32 / uint2 pairs) ----
__device__ uint32_t g_q[(size_t)BB * NH * SS * HD];     // plain [bh][s][d]
__device__ uint32_t g_k[(size_t)BB * NH * SS * HD];     // plain [bh][s][d]
__device__ uint32_t g_v[(size_t)BB * NH * SS * HD];     // plain [bh][s][d]
__device__ uint2    g_kp[(size_t)BB * NH * SS * (HD / 2)];     // [bh*s][32 pairs along d]
__device__ uint2    g_vtp[(size_t)BB * NH * HD * (SS / 2)];    // [bh*d][512 pairs along s]
__device__ uint2    g_xc[(size_t)MROWS * (D_MODEL / 2)];       // pair-packed along k
__device__ uint2    g_yc[(size_t)MROWS * (D_MODEL / 2)];
__device__ uint2    g_zc[(size_t)MROWS * (D_MODEL / 2)];
__device__ uint2    g_wqc[(size_t)D_MODEL * (D_MODEL / 2)];
__device__ uint2    g_wkc[(size_t)D_MODEL * (D_MODEL / 2)];
__device__ uint2    g_wvc[(size_t)D_MODEL * (D_MODEL / 2)];
__device__ uint2    g_mc[(size_t)SS * (SS / 2)];               // mask pair-packed

// ---------------------------------------------------------------------------
__device__ __forceinline__ uint32_t f2tf32(float x) {
    uint32_t r;
    asm("cvt.rna.tf32.f32 %0, %1;" : "=r"(r) : "f"(x));
    return r;
}

__device__ __forceinline__ void mma_tf32(float c[4], const uint32_t a[4], const uint32_t b[2]) {
    asm("mma.sync.aligned.m16n8k8.row.col.f32.tf32.tf32.f32 "
        "{%0,%1,%2,%3}, {%4,%5,%6,%7}, {%8,%9}, {%0,%1,%2,%3};"
        : "+f"(c[0]), "+f"(c[1]), "+f"(c[2]), "+f"(c[3])
        : "r"(a[0]), "r"(a[1]), "r"(a[2]), "r"(a[3]), "r"(b[0]), "r"(b[1]));
}

__device__ __forceinline__ void cpa16(void* dst, const void* src) {
    uint32_t d = (uint32_t)__cvta_generic_to_shared(dst);
    asm volatile("cp.async.cg.shared.global [%0], [%1], 16;\n" :: "r"(d), "l"(src));
}
#define CP_COMMIT() asm volatile("cp.async.commit_group;\n" ::)
#define CP_WAIT(n)  asm volatile("cp.async.wait_group %0;\n" :: "n"(n))

// ===========================================================================
// Kernel 0: fp32 -> tf32 conversion, pair-packed output.
// ===========================================================================
__global__ __launch_bounds__(256) void cvt_kernel(
    const float* __restrict__ x, const float* __restrict__ y,
    const float* __restrict__ z, const float* __restrict__ wq,
    const float* __restrict__ wk, const float* __restrict__ wv,
    const float* __restrict__ mask)
{
    const float* src;
    uint2* dst;
    size_t ngroups;
    switch (blockIdx.y) {
        case 0: src = x;    dst = g_xc;  ngroups = (size_t)MROWS * 128;   break;
        case 1: src = y;    dst = g_yc;  ngroups = (size_t)MROWS * 128;   break;
        case 2: src = z;    dst = g_zc;  ngroups = (size_t)MROWS * 128;   break;
        case 3: src = wq;   dst = g_wqc; ngroups = (size_t)D_MODEL * 128; break;
        case 4: src = wk;   dst = g_wkc; ngroups = (size_t)D_MODEL * 128; break;
        case 5: src = wv;   dst = g_wvc; ngroups = (size_t)D_MODEL * 128; break;
        default: src = mask; dst = g_mc; ngroups = (size_t)SS * 128;      break;
    }
    size_t gid = (size_t)blockIdx.x * 256 + threadIdx.x;
    if (gid >= ngroups) return;
    size_t row = gid >> 7;
    int g = (int)(gid & 127);
    const float4* s4 = (const float4*)(src + row * 1024 + g * 8);
    float4 a = s4[0], b = s4[1];
    uint4 u0, u1;
    u0.x = f2tf32(a.x); u0.y = f2tf32(b.x);
    u0.z = f2tf32(a.y); u0.w = f2tf32(b.y);
    u1.x = f2tf32(a.z); u1.y = f2tf32(b.z);
    u1.z = f2tf32(a.w); u1.w = f2tf32(b.w);
    uint4* d4 = (uint4*)(dst + row * 512 + g * 4);
    d4[0] = u0;
    d4[1] = u1;
}

// ===========================================================================
// Kernel 1: fused QKV projection (pair-packed tf32, cp.async pipeline).
// ===========================================================================
#define PJ_LD2 20
#define SMEM_PROJ (2 * 2 * 128 * PJ_LD2 * 8)   // 81920 B

__global__ __launch_bounds__(256) void proj_mma(
    const float* __restrict__ bq, const float* __restrict__ bk,
    const float* __restrict__ bv)
{
    extern __shared__ uint2 smp2[];
    uint2* Asp = smp2;
    uint2* Bsp = smp2 + 2 * 128 * PJ_LD2;

    const int which = blockIdx.z;
    const uint2* A    = which == 0 ? g_xc  : (which == 1 ? g_yc  : g_zc);
    const uint2* W    = which == 0 ? g_wqc : (which == 1 ? g_wkc : g_wvc);
    const float* bias = which == 0 ? bq    : (which == 1 ? bk    : bv);
    uint32_t* out     = which == 0 ? g_q   : (which == 1 ? g_k   : g_v);

    const int tid  = threadIdx.x;
    const int lane = tid & 31;
    const int wid  = tid >> 5;
    const int wm   = wid >> 2;
    const int wn   = wid & 3;
    const int m0   = blockIdx.y * 128;
    const int n0   = blockIdx.x * 128;
    const int lr   = lane >> 2;
    const int lc   = lane & 3;

    float acc[4][4][4];
#pragma unroll
    for (int i = 0; i < 4; i++)
#pragma unroll
        for (int j = 0; j < 4; j++)
#pragma unroll
            for (int r = 0; r < 4; r++) acc[i][j][r] = 0.f;

    auto stage = [&](int buf, int ch) {
#pragma unroll
        for (int i = 0; i < 4; i++) {
            int idx = tid + i * 256;
            int r = idx >> 3;
            int c = (idx & 7) << 1;
            cpa16(&Asp[buf * 128 * PJ_LD2 + r * PJ_LD2 + c],
                  A + (size_t)(m0 + r) * 512 + ch * 16 + c);
            cpa16(&Bsp[buf * 128 * PJ_LD2 + r * PJ_LD2 + c],
                  W + (size_t)(n0 + r) * 512 + ch * 16 + c);
        }
    };

    stage(0, 0);
    CP_COMMIT();

    for (int ch = 0; ch < 32; ch++) {
        if (ch + 1 < 32) { stage((ch + 1) & 1, ch + 1); CP_COMMIT(); }
        if (ch + 1 < 32) { CP_WAIT(1); } else { CP_WAIT(0); }
        __syncthreads();

        const uint2* Ab = &Asp[(ch & 1) * 128 * PJ_LD2];
        const uint2* Bb = &Bsp[(ch & 1) * 128 * PJ_LD2];
#pragma unroll
        for (int g = 0; g < 4; g++) {
            uint32_t af[4][4], bf[4][2];
#pragma unroll
            for (int ms = 0; ms < 4; ms++) {
                uint2 q0 = Ab[(wm * 64 + ms * 16 + lr) * PJ_LD2 + g * 4 + lc];
                uint2 q1 = Ab[(wm * 64 + ms * 16 + lr + 8) * PJ_LD2 + g * 4 + lc];
                af[ms][0] = q0.x; af[ms][1] = q1.x;
                af[ms][2] = q0.y; af[ms][3] = q1.y;
            }
#pragma unroll
            for (int ns = 0; ns < 4; ns++) {
                uint2 q = Bb[(wn * 32 + ns * 8 + lr) * PJ_LD2 + g * 4 + lc];
                bf[ns][0] = q.x; bf[ns][1] = q.y;
            }
#pragma unroll
            for (int ms = 0; ms < 4; ms++)
#pragma unroll
                for (int ns = 0; ns < 4; ns++)
                    mma_tf32(acc[ms][ns], af[ms], bf[ns]);
        }
        __syncthreads();
    }

#pragma unroll
    for (int ms = 0; ms < 4; ms++) {
#pragma unroll
        for (int ns = 0; ns < 4; ns++) {
            int gm = m0 + wm * 64 + ms * 16 + lr;
            int gn = n0 + wn * 32 + ns * 8 + (lc << 1);
            float bx = bias[gn], by = bias[gn + 1];
            int h = gn >> 6, d = gn & 63;
            {
                int b = gm >> 10, s = gm & 1023;
                uint2 v = make_uint2(f2tf32(acc[ms][ns][0] + bx),
                                     f2tf32(acc[ms][ns][1] + by));
                *(uint2*)(out + (((size_t)(b * NH + h)) * SS + s) * HD + d) = v;
            }
            {
                int gm2 = gm + 8;
                int b = gm2 >> 10, s = gm2 & 1023;
                uint2 v = make_uint2(f2tf32(acc[ms][ns][2] + bx),
                                     f2tf32(acc[ms][ns][3] + by));
                *(uint2*)(out + (((size_t)(b * NH + h)) * SS + s) * HD + d) = v;
            }
        }
    }
}

// ===========================================================================
// Kernel 1b/1c: K/V repacks (unchanged).
// ===========================================================================
__global__ __launch_bounds__(256) void kpack_kernel()
{
    size_t p = (size_t)blockIdx.x * 256 + threadIdx.x;
    size_t row = p >> 5;
    int i = (int)(p & 31);
    int g = i >> 2, j = i & 3;
    uint32_t a = g_k[row * 64 + g * 8 + j];
    uint32_t b = g_k[row * 64 + g * 8 + j + 4];
    g_kp[p] = make_uint2(a, b);
}

__global__ __launch_bounds__(256) void vpack_kernel()
{
    __shared__ uint32_t vt[128 * 65];
    const int st = blockIdx.x;
    const int bh = blockIdx.y;
    const int tid = threadIdx.x;

    const uint32_t* src = g_v + ((size_t)bh * SS + st * 128) * HD;
#pragma unroll
    for (int i = 0; i < 8; i++) {
        int idx = i * 256 + tid;
        int r = idx >> 4;
        int c = (idx & 15) << 2;
        uint4 v = *(const uint4*)(src + (size_t)r * HD + c);
        vt[r * 65 + c + 0] = v.x;
        vt[r * 65 + c + 1] = v.y;
        vt[r * 65 + c + 2] = v.z;
        vt[r * 65 + c + 3] = v.w;
    }
    __syncthreads();

#pragma unroll
    for (int i = 0; i < 16; i++) {
        int idx = i * 256 + tid;
        int d = idx >> 6;
        int i6 = idx & 63;
        int g = i6 >> 2, j = i6 & 3;
        int s = g * 8 + j;
        uint2 o = make_uint2(vt[s * 65 + d], vt[(s + 4) * 65 + d]);
        g_vtp[((size_t)bh * 64 + d) * 512 + st * 64 + i6] = o;
    }
}

// ===========================================================================
// Kernel 2: fused flash attention + mask@V.
// 4 warps, 64 q-rows per CTA, smem 105.5 KB -> 2 CTAs/SM (phase overlap).
// Single-buffered K/V, split-group cp.async pipeline; mask from gmem (L2-hot).
// ===========================================================================
#define KS_LD2 36
#define VS_LD2 68
#define PS_LD 132
#define KS_SZ2 (128 * KS_LD2)      // 128 keys x 36 uint2
#define VS_SZ2 (64 * VS_LD2)       // 64 d-rows x 68 uint2
#define SMEM_FLASH (KS_SZ2 * 8 + VS_SZ2 * 8 + 64 * PS_LD * 4)  // 105472 B

__global__ __launch_bounds__(128, 2) void flash_kernel(float* __restrict__ out)
{
    extern __shared__ uint2 smf2[];
    uint2* Ksp = smf2;                               // [128][36]
    uint2* Vsp = smf2 + KS_SZ2;                      // [64][68]
    uint32_t* Ps = (uint32_t*)(smf2 + KS_SZ2 + VS_SZ2);  // [64][132]

    const int tid  = threadIdx.x;
    const int lane = tid & 31;
    const int wm   = tid >> 5;        // 0..3
    const int lr   = lane >> 2;
    const int lc   = lane & 3;

    const int qt = blockIdx.x;        // 0..15 (64-row tiles)
    const int bh = blockIdx.y;        // 0..63
    const int b  = bh >> 4, h = bh & 15;

    const uint32_t* Qg = g_q + (size_t)bh * SS * HD + (size_t)qt * 64 * HD;
    const uint2* Kgp = g_kp + (size_t)bh * SS * 32;
    const uint2* Vgp = g_vtp + (size_t)bh * 64 * 512;
    const uint2* Mgp = g_mc + (size_t)(qt * 64 + wm * 16 + lr) * 512;

    auto stageK = [&](int kt) {
#pragma unroll
        for (int i = 0; i < 16; i++) {
            int idx = i * 128 + tid;          // 0..2047
            int r = idx >> 4;                 // 0..127
            int c = (idx & 15) << 1;
            cpa16(&Ksp[r * KS_LD2 + c], Kgp + (size_t)(kt * 128 + r) * 32 + c);
        }
    };
    auto stageV = [&](int kt) {
#pragma unroll
        for (int i = 0; i < 16; i++) {
            int idx = i * 128 + tid;          // 0..2047
            int r = idx >> 5;                 // 0..63
            int c = (idx & 31) << 1;
            cpa16(&Vsp[r * VS_LD2 + c], Vgp + (size_t)r * 512 + kt * 64 + c);
        }
    };

    // ---- prologue: stage K/V tile 0 + Q (plain), one group ----
    stageK(0);
    stageV(0);
#pragma unroll
    for (int i = 0; i < 8; i++) {
        int idx = i * 128 + tid;          // 0..1023
        int r = idx >> 4;                 // 0..63
        int c = (idx & 15) << 2;          // 0..60
        cpa16(&Ps[r * PS_LD + c], Qg + (size_t)r * HD + c);
    }
    CP_COMMIT();
    CP_WAIT(0);
    __syncthreads();

    uint32_t qf[8][4];
#pragma unroll
    for (int ks = 0; ks < 8; ks++) {
        const uint32_t* p = &Ps[(wm * 16 + lr) * PS_LD + ks * 8 + lc];
        qf[ks][0] = p[0];
        qf[ks][1] = p[8 * PS_LD];
        qf[ks][2] = p[4];
        qf[ks][3] = p[8 * PS_LD + 4];
    }
    // qf reads & later P writes touch only this warp's own rows

    float m0 = -1e30f, m1 = -1e30f;
    float l0 = 0.f, l1 = 0.f;
    float oacc[8][4], macc[8][4];
#pragma unroll
    for (int i = 0; i < 8; i++)
#pragma unroll
        for (int r = 0; r < 4; r++) { oacc[i][r] = 0.f; macc[i][r] = 0.f; }

    const float scale = 0.03125f;
    const int row = wm * 16 + lr;

    for (int kt = 0; kt < 8; kt++) {
        // ---- QK^T (K[kt] ready on entry) ----
        float sacc[16][4];
#pragma unroll
        for (int nt = 0; nt < 16; nt++)
#pragma unroll
            for (int r = 0; r < 4; r++) sacc[nt][r] = 0.f;

#pragma unroll
        for (int ks = 0; ks < 8; ks++) {
#pragma unroll
            for (int nt = 0; nt < 16; nt++) {
                uint2 kq = Ksp[(nt * 8 + lr) * KS_LD2 + ks * 4 + lc];
                uint32_t bf[2] = {kq.x, kq.y};
                mma_tf32(sacc[nt], qf[ks], bf);
            }
        }

        // V[kt] group complete before PV; K tile now free for restage
        CP_WAIT(0);
        __syncthreads();
        if (kt + 1 < 8) { stageK(kt + 1); CP_COMMIT(); }   // hidden behind softmax+PV

        // ---- online softmax ----
        float rm0 = -1e30f, rm1 = -1e30f;
#pragma unroll
        for (int nt = 0; nt < 16; nt++) {
            rm0 = fmaxf(rm0, fmaxf(sacc[nt][0], sacc[nt][1]));
            rm1 = fmaxf(rm1, fmaxf(sacc[nt][2], sacc[nt][3]));
        }
#pragma unroll
        for (int o = 1; o <= 2; o <<= 1) {
            rm0 = fmaxf(rm0, __shfl_xor_sync(0xffffffffu, rm0, o));
            rm1 = fmaxf(rm1, __shfl_xor_sync(0xffffffffu, rm1, o));
        }
        float mn0 = fmaxf(m0, rm0 * scale);
        float mn1 = fmaxf(m1, rm1 * scale);
        float a0 = __expf(m0 - mn0);
        float a1 = __expf(m1 - mn1);
        m0 = mn0; m1 = mn1;

        float ps0 = 0.f, ps1 = 0.f;
#pragma unroll
        for (int nt = 0; nt < 16; nt++) {
            float p0 = __expf(fmaf(sacc[nt][0], scale, -mn0));
            float p1 = __expf(fmaf(sacc[nt][1], scale, -mn0));
            float p2 = __expf(fmaf(sacc[nt][2], scale, -mn1));
            float p3 = __expf(fmaf(sacc[nt][3], scale, -mn1));
            ps0 += p0 + p1;
            ps1 += p2 + p3;
            uint32_t* pp = &Ps[row * PS_LD + nt * 8 + (lc << 1)];
            pp[0] = f2tf32(p0);
            pp[1] = f2tf32(p1);
            pp[8 * PS_LD] = f2tf32(p2);
            pp[8 * PS_LD + 1] = f2tf32(p3);
        }
#pragma unroll
        for (int o = 1; o <= 2; o <<= 1) {
            ps0 += __shfl_xor_sync(0xffffffffu, ps0, o);
            ps1 += __shfl_xor_sync(0xffffffffu, ps1, o);
        }
        l0 = l0 * a0 + ps0;
        l1 = l1 * a1 + ps1;

#pragma unroll
        for (int i = 0; i < 8; i++) {
            oacc[i][0] *= a0; oacc[i][1] *= a0;
            oacc[i][2] *= a1; oacc[i][3] *= a1;
        }
        __syncwarp();

        // ---- (P @ V) and (mask @ V); mask pairs from gmem (L2-resident) ----
#pragma unroll
        for (int ks2 = 0; ks2 < 16; ks2++) {
            uint32_t pa[4], ma[4];
            const uint32_t* pp = &Ps[row * PS_LD + ks2 * 8 + lc];
            pa[0] = pp[0];
            pa[1] = pp[8 * PS_LD];
            pa[2] = pp[4];
            pa[3] = pp[8 * PS_LD + 4];
            uint2 m02 = Mgp[kt * 64 + ks2 * 4 + lc];
            uint2 m13 = Mgp[8 * 512 + kt * 64 + ks2 * 4 + lc];
            ma[0] = m02.x; ma[1] = m13.x;
            ma[2] = m02.y; ma[3] = m13.y;
#pragma unroll
            for (int nt2 = 0; nt2 < 8; nt2++) {
                uint2 vq = Vsp[(nt2 * 8 + lr) * VS_LD2 + ks2 * 4 + lc];
                uint32_t vb[2] = {vq.x, vq.y};
                mma_tf32(oacc[nt2], pa, vb);
                mma_tf32(macc[nt2], ma, vb);
            }
        }

        if (kt + 1 < 8) {
            __syncthreads();                 // all warps done with V tile
            stageV(kt + 1);
            CP_COMMIT();                     // hidden behind next QK
            CP_WAIT(1);                      // K[kt+1] (older group) done
            __syncthreads();
        }
    }

    // ---- epilogue ----
    const float inv0 = 1.0f / l0;
    const float inv1 = 1.0f / l1;
    const int grow = qt * 64 + wm * 16 + lr;
#pragma unroll
    for (int nt2 = 0; nt2 < 8; nt2++) {
        int gn = h * HD + nt2 * 8 + (lc << 1);
        float2 v0 = make_float2(oacc[nt2][0] * inv0 + macc[nt2][0],
                                oacc[nt2][1] * inv0 + macc[nt2][1]);
        float2 v1 = make_float2(oacc[nt2][2] * inv1 + macc[nt2][2],
                                oacc[nt2][3] * inv1 + macc[nt2][3]);
        *(float2*)(out + ((size_t)b * SS + grow) * D_MODEL + gn) = v0;
        *(float2*)(out + ((size_t)b * SS + grow + 8) * D_MODEL + gn) = v1;
    }
}

// ===========================================================================
extern "C" void kernel_launch(void* const* d_in, const int* in_sizes, int n_in,
                              void* d_out, int out_size)
{
    const float* x    = (const float*)d_in[0];
    const float* y    = (const float*)d_in[1];
    const float* z    = (const float*)d_in[2];
    const float* mask = (const float*)d_in[3];
    const float* wq   = (const float*)d_in[4];
    const float* bq   = (const float*)d_in[5];
    const float* wk   = (const float*)d_in[6];
    const float* bk   = (const float*)d_in[7];
    const float* wv   = (const float*)d_in[8];
    const float* bv   = (const float*)d_in[9];
    float* out = (float*)d_out;

    cudaFuncSetAttribute(proj_mma,
                         cudaFuncAttributeMaxDynamicSharedMemorySize, SMEM_PROJ);
    cudaFuncSetAttribute(flash_kernel,
                         cudaFuncAttributeMaxDynamicSharedMemorySize, SMEM_FLASH);

    dim3 g0((MROWS * D_MODEL / 8 + 255) / 256, 7);
    cvt_kernel<<<g0, 256>>>(x, y, z, wq, wk, wv, mask);

    dim3 g1(D_MODEL / 128, MROWS / 128, 3);
    proj_mma<<<g1, 256, SMEM_PROJ>>>(bq, bk, bv);

    kpack_kernel<<<(BB * NH * SS * 32) / 256, 256>>>();
    dim3 gv(SS / 128, BB * NH);
    vpack_kernel<<<gv, 256>>>();

    dim3 g2(SS / 64, BB * NH);
    flash_kernel<<<g2, 128, SMEM_FLASH>>>(out);
}

// round 10
// speedup vs baseline: 4.9194x; 1.4331x over previous
#include <cuda_runtime.h>
#include <cuda_fp16.h>
#include <cstdint>

#define D_MODEL 1024
#define NH 16
#define HD 64
#define BB 4
#define SS 1024
#define MROWS (BB * SS)   // 4096

// ---- scratch: fp16 bit patterns packed in b32 (2 halves each) ----
__device__ uint32_t g_q[(size_t)BB * NH * SS * HD / 2];    // [bh][s][d/2]
__device__ uint32_t g_k[(size_t)BB * NH * SS * HD / 2];    // [bh][s][d/2]
__device__ uint32_t g_v[(size_t)BB * NH * SS * HD / 2];    // [bh][s][d/2]
__device__ uint32_t g_vt[(size_t)BB * NH * HD * SS / 2];   // [bh][d][s/2]
__device__ uint32_t g_xc[(size_t)MROWS * D_MODEL / 2];
__device__ uint32_t g_yc[(size_t)MROWS * D_MODEL / 2];
__device__ uint32_t g_zc[(size_t)MROWS * D_MODEL / 2];
__device__ uint32_t g_wqc[(size_t)D_MODEL * D_MODEL / 2];
__device__ uint32_t g_wkc[(size_t)D_MODEL * D_MODEL / 2];
__device__ uint32_t g_wvc[(size_t)D_MODEL * D_MODEL / 2];
__device__ uint2    g_mc[(size_t)SS * 256];   // mask: b32-pair packed per row

// ---------------------------------------------------------------------------
__device__ __forceinline__ uint32_t f2h2(float a, float b) {
    __half2 h = __floats2half2_rn(a, b);
    return *(uint32_t*)&h;
}

// m16n8k16 fp16 MMA, fp32 accumulate.
// a regs: {(lr,2lc),(lr+8,2lc),(lr,2lc+8),(lr+8,2lc+8)} b32 (k-adjacent half2)
// b regs: {(k=2lc,n=lr),(k=2lc+8,n=lr)} b32
__device__ __forceinline__ void mma_f16(float c[4], const uint32_t a[4], const uint32_t b[2]) {
    asm("mma.sync.aligned.m16n8k16.row.col.f32.f16.f16.f32 "
        "{%0,%1,%2,%3}, {%4,%5,%6,%7}, {%8,%9}, {%0,%1,%2,%3};"
        : "+f"(c[0]), "+f"(c[1]), "+f"(c[2]), "+f"(c[3])
        : "r"(a[0]), "r"(a[1]), "r"(a[2]), "r"(a[3]), "r"(b[0]), "r"(b[1]));
}

__device__ __forceinline__ void cpa16(void* dst, const void* src) {
    uint32_t d = (uint32_t)__cvta_generic_to_shared(dst);
    asm volatile("cp.async.cg.shared.global [%0], [%1], 16;\n" :: "r"(d), "l"(src));
}
#define CP_COMMIT() asm volatile("cp.async.commit_group;\n" ::)
#define CP_WAIT(n)  asm volatile("cp.async.wait_group %0;\n" :: "n"(n))

// ===========================================================================
// Kernel 0: fp32 -> fp16. Plain b32-packed for x/y/z/W; mask pair-packed.
// ===========================================================================
__global__ __launch_bounds__(256) void cvt_kernel(
    const float* __restrict__ x, const float* __restrict__ y,
    const float* __restrict__ z, const float* __restrict__ wq,
    const float* __restrict__ wk, const float* __restrict__ wv,
    const float* __restrict__ mask)
{
    size_t gid = (size_t)blockIdx.x * 256 + threadIdx.x;
    if (blockIdx.y < 6) {
        const float* src;
        uint32_t* dst;
        size_t n;
        switch (blockIdx.y) {
            case 0: src = x;  dst = g_xc;  n = (size_t)MROWS * D_MODEL; break;
            case 1: src = y;  dst = g_yc;  n = (size_t)MROWS * D_MODEL; break;
            case 2: src = z;  dst = g_zc;  n = (size_t)MROWS * D_MODEL; break;
            case 3: src = wq; dst = g_wqc; n = (size_t)D_MODEL * D_MODEL; break;
            case 4: src = wk; dst = g_wkc; n = (size_t)D_MODEL * D_MODEL; break;
            default: src = wv; dst = g_wvc; n = (size_t)D_MODEL * D_MODEL; break;
        }
        size_t i = gid * 8;
        if (i >= n) return;
        float4 a = *(const float4*)(src + i);
        float4 b = *(const float4*)(src + i + 4);
        uint4 o;
        o.x = f2h2(a.x, a.y); o.y = f2h2(a.z, a.w);
        o.z = f2h2(b.x, b.y); o.w = f2h2(b.z, b.w);
        *(uint4*)(dst + i / 2) = o;
    } else {
        // mask: per row, pair p=g*4+j holds b32 cols {8g+j, 8g+j+4}
        if (gid >= (size_t)SS * 256) return;
        size_t row = gid >> 8;
        int p = (int)(gid & 255);
        int g = p >> 2, j = p & 3;
        const float* mrow = mask + row * 1024;
        float f0 = mrow[16 * g + 2 * j];
        float f1 = mrow[16 * g + 2 * j + 1];
        float f2 = mrow[16 * g + 2 * j + 8];
        float f3 = mrow[16 * g + 2 * j + 9];
        g_mc[row * 256 + p] = make_uint2(f2h2(f0, f1), f2h2(f2, f3));
    }
}

// ===========================================================================
// Kernel 1: fused QKV projection, fp16 m16n8k16, cp.async double buffer.
// Block tile 128x128, 8 warps (2x4), warp 64x32, K chunk = 32 halves.
// ===========================================================================
#define PJ_LD 20                     // b32 row stride (16 used + 4 pad)
#define PJ_SZ (128 * PJ_LD)
#define SMEM_PROJ (4 * PJ_SZ * 4)    // A x2 + B x2 = 40960 B

__global__ __launch_bounds__(256) void proj_mma(
    const float* __restrict__ bq, const float* __restrict__ bk,
    const float* __restrict__ bv)
{
    extern __shared__ uint32_t smp[];
    uint32_t* Asp = smp;                 // [2][128][20]
    uint32_t* Bsp = smp + 2 * PJ_SZ;     // [2][128][20]

    const int which = blockIdx.z;
    const uint32_t* A  = which == 0 ? g_xc  : (which == 1 ? g_yc  : g_zc);
    const uint32_t* W  = which == 0 ? g_wqc : (which == 1 ? g_wkc : g_wvc);
    const float* bias  = which == 0 ? bq    : (which == 1 ? bk    : bv);
    uint32_t* out      = which == 0 ? g_q   : (which == 1 ? g_k   : g_v);

    const int tid  = threadIdx.x;
    const int lane = tid & 31;
    const int wid  = tid >> 5;
    const int wm   = wid >> 2;
    const int wn   = wid & 3;
    const int m0   = blockIdx.y * 128;
    const int n0   = blockIdx.x * 128;
    const int lr   = lane >> 2;
    const int lc   = lane & 3;

    float acc[4][4][4];
#pragma unroll
    for (int i = 0; i < 4; i++)
#pragma unroll
        for (int j = 0; j < 4; j++)
#pragma unroll
            for (int r = 0; r < 4; r++) acc[i][j][r] = 0.f;

    auto stage = [&](int buf, int ch) {
        // chunk ch = 16 b32 per row
#pragma unroll
        for (int i = 0; i < 2; i++) {
            int idx = tid + i * 256;      // 0..511
            int r = idx >> 2;             // 0..127
            int c4 = (idx & 3) << 2;      // 0,4,8,12
            cpa16(&Asp[buf * PJ_SZ + r * PJ_LD + c4],
                  A + (size_t)(m0 + r) * 512 + ch * 16 + c4);
            cpa16(&Bsp[buf * PJ_SZ + r * PJ_LD + c4],
                  W + (size_t)(n0 + r) * 512 + ch * 16 + c4);
        }
    };

    stage(0, 0);
    CP_COMMIT();

    for (int ch = 0; ch < 32; ch++) {
        if (ch + 1 < 32) { stage((ch + 1) & 1, ch + 1); CP_COMMIT(); }
        if (ch + 1 < 32) { CP_WAIT(1); } else { CP_WAIT(0); }
        __syncthreads();

        const uint32_t* Ab = &Asp[(ch & 1) * PJ_SZ];
        const uint32_t* Bb = &Bsp[(ch & 1) * PJ_SZ];
#pragma unroll
        for (int st = 0; st < 2; st++) {    // 2 MMA k-steps of 16
            uint32_t af[4][4], bf[4][2];
#pragma unroll
            for (int ms = 0; ms < 4; ms++) {
                const uint32_t* p = &Ab[(wm * 64 + ms * 16 + lr) * PJ_LD + st * 8 + lc];
                af[ms][0] = p[0];
                af[ms][1] = p[8 * PJ_LD];
                af[ms][2] = p[4];
                af[ms][3] = p[8 * PJ_LD + 4];
            }
#pragma unroll
            for (int ns = 0; ns < 4; ns++) {
                const uint32_t* p = &Bb[(wn * 32 + ns * 8 + lr) * PJ_LD + st * 8 + lc];
                bf[ns][0] = p[0];
                bf[ns][1] = p[4];
            }
#pragma unroll
            for (int ms = 0; ms < 4; ms++)
#pragma unroll
                for (int ns = 0; ns < 4; ns++)
                    mma_f16(acc[ms][ns], af[ms], bf[ns]);
        }
        __syncthreads();
    }

    // epilogue: +bias, fp16-pack, head-major write
#pragma unroll
    for (int ms = 0; ms < 4; ms++) {
#pragma unroll
        for (int ns = 0; ns < 4; ns++) {
            int gm = m0 + wm * 64 + ms * 16 + lr;
            int gn = n0 + wn * 32 + ns * 8 + (lc << 1);
            float bx = bias[gn], by = bias[gn + 1];
            int h = gn >> 6, d = gn & 63;
            {
                int b = gm >> 10, s = gm & 1023;
                out[(((size_t)(b * NH + h)) * SS + s) * 32 + (d >> 1)] =
                    f2h2(acc[ms][ns][0] + bx, acc[ms][ns][1] + by);
            }
            {
                int gm2 = gm + 8;
                int b = gm2 >> 10, s = gm2 & 1023;
                out[(((size_t)(b * NH + h)) * SS + s) * 32 + (d >> 1)] =
                    f2h2(acc[ms][ns][2] + bx, acc[ms][ns][3] + by);
            }
        }
    }
}

// ===========================================================================
// Kernel 1b: V transpose -> g_vt [bh][d][s/2 b32] (half2 along s).
// ===========================================================================
__global__ __launch_bounds__(256) void vpack_kernel()
{
    __shared__ uint32_t vt32[128 * 33];
    const int st = blockIdx.x;     // 0..7 (128-key tiles)
    const int bh = blockIdx.y;     // 0..63
    const int tid = threadIdx.x;

    const uint32_t* src = g_v + ((size_t)bh * SS + st * 128) * 32;
#pragma unroll
    for (int i = 0; i < 16; i++) {
        int idx = i * 256 + tid;       // 0..4095
        int r = idx >> 5;              // 0..127
        int c = idx & 31;
        vt32[r * 33 + c] = src[(size_t)r * 32 + c];
    }
    __syncthreads();

#pragma unroll
    for (int i = 0; i < 16; i++) {
        int idx = i * 256 + tid;       // 0..4095
        int d = idx >> 6;              // 0..63
        int j = idx & 63;              // s-pair within tile
        uint32_t lo = vt32[(2 * j) * 33 + (d >> 1)];
        uint32_t hi = vt32[(2 * j + 1) * 33 + (d >> 1)];
        uint32_t h0 = (d & 1) ? (lo >> 16) : (lo & 0xffffu);
        uint32_t h1 = (d & 1) ? (hi >> 16) : (hi & 0xffffu);
        g_vt[((size_t)bh * 64 + d) * 512 + st * 64 + j] = h0 | (h1 << 16);
    }
}

// ===========================================================================
// Kernel 2: fused flash attention + mask@V, fp16 m16n8k16.
// 4 warps / 64 q-rows per CTA, K/V double-buffered, 2 CTAs/SM.
// ===========================================================================
#define KF_LD 36                   // b32 stride (32 used)
#define VF_LD 68                   // b32 stride (64 used)
#define PF_LD 68
#define KF_SZ (128 * KF_LD)        // 4608 b32
#define VF_SZ (64 * VF_LD)         // 4352 b32
#define SMEM_FLASH ((2 * KF_SZ + 2 * VF_SZ + 64 * PF_LD) * 4)   // 89088 B

__global__ __launch_bounds__(128, 2) void flash_kernel(float* __restrict__ out)
{
    extern __shared__ uint32_t smf[];
    uint32_t* Ksp = smf;                         // [2][128][36]
    uint32_t* Vsp = smf + 2 * KF_SZ;             // [2][64][68]
    uint32_t* Ps  = smf + 2 * KF_SZ + 2 * VF_SZ; // [64][68] (Q staging, then P)

    const int tid  = threadIdx.x;
    const int lane = tid & 31;
    const int wm   = tid >> 5;        // 0..3
    const int lr   = lane >> 2;
    const int lc   = lane & 3;

    const int qt = blockIdx.x;        // 0..15
    const int bh = blockIdx.y;        // 0..63
    const int b  = bh >> 4, h = bh & 15;

    const uint32_t* Qg = g_q + ((size_t)bh * SS + qt * 64) * 32;
    const uint32_t* Kg = g_k + (size_t)bh * SS * 32;
    const uint32_t* Vg = g_vt + (size_t)bh * 64 * 512;
    const uint2* Mgp = g_mc + (size_t)(qt * 64 + wm * 16 + lr) * 256;

    auto stageKV = [&](int kt, int buf) {
#pragma unroll
        for (int i = 0; i < 8; i++) {            // K: 128 rows x 8 cpa16
            int idx = i * 128 + tid;             // 0..1023
            int r = idx >> 3;
            int c4 = (idx & 7) << 2;
            cpa16(&Ksp[buf * KF_SZ + r * KF_LD + c4],
                  Kg + (size_t)(kt * 128 + r) * 32 + c4);
        }
#pragma unroll
        for (int i = 0; i < 8; i++) {            // V: 64 rows x 16 cpa16
            int idx = i * 128 + tid;             // 0..1023
            int r = idx >> 4;
            int c4 = (idx & 15) << 2;
            cpa16(&Vsp[buf * VF_SZ + r * VF_LD + c4],
                  Vg + (size_t)r * 512 + kt * 64 + c4);
        }
    };

    // ---- prologue: K/V tile 0 + Q, one group ----
    stageKV(0, 0);
#pragma unroll
    for (int i = 0; i < 4; i++) {
        int idx = i * 128 + tid;          // 0..511
        int r = idx >> 3;                 // 0..63
        int c4 = (idx & 7) << 2;
        cpa16(&Ps[r * PF_LD + c4], Qg + (size_t)r * 32 + c4);
    }
    CP_COMMIT();
    CP_WAIT(0);
    __syncthreads();

    uint32_t qf[4][4];
#pragma unroll
    for (int st = 0; st < 4; st++) {
        const uint32_t* p = &Ps[(wm * 16 + lr) * PF_LD + st * 8 + lc];
        qf[st][0] = p[0];
        qf[st][1] = p[8 * PF_LD];
        qf[st][2] = p[4];
        qf[st][3] = p[8 * PF_LD + 4];
    }
    // Ps rows are warp-private; safe to overwrite with P after this point.

    float m0 = -1e30f, m1 = -1e30f;
    float l0 = 0.f, l1 = 0.f;
    float oacc[8][4], macc[8][4];
#pragma unroll
    for (int i = 0; i < 8; i++)
#pragma unroll
        for (int r = 0; r < 4; r++) { oacc[i][r] = 0.f; macc[i][r] = 0.f; }

    const float scale = 0.03125f;
    const int row = wm * 16 + lr;

    for (int kt = 0; kt < 8; kt++) {
        const int bf_ = kt & 1;
        if (kt + 1 < 8) { stageKV(kt + 1, bf_ ^ 1); CP_COMMIT(); }

        const uint32_t* Ksb = &Ksp[bf_ * KF_SZ];
        const uint32_t* Vsb = &Vsp[bf_ * VF_SZ];

        // ---- QK^T: 4 k-steps x 16 key-tiles ----
        float sacc[16][4];
#pragma unroll
        for (int nt = 0; nt < 16; nt++)
#pragma unroll
            for (int r = 0; r < 4; r++) sacc[nt][r] = 0.f;

#pragma unroll
        for (int st = 0; st < 4; st++) {
#pragma unroll
            for (int nt = 0; nt < 16; nt++) {
                uint32_t bf2[2];
                const uint32_t* p = &Ksb[(nt * 8 + lr) * KF_LD + st * 8 + lc];
                bf2[0] = p[0];
                bf2[1] = p[4];
                mma_f16(sacc[nt], qf[st], bf2);
            }
        }

        // ---- online softmax ----
        float rm0 = -1e30f, rm1 = -1e30f;
#pragma unroll
        for (int nt = 0; nt < 16; nt++) {
            rm0 = fmaxf(rm0, fmaxf(sacc[nt][0], sacc[nt][1]));
            rm1 = fmaxf(rm1, fmaxf(sacc[nt][2], sacc[nt][3]));
        }
#pragma unroll
        for (int o = 1; o <= 2; o <<= 1) {
            rm0 = fmaxf(rm0, __shfl_xor_sync(0xffffffffu, rm0, o));
            rm1 = fmaxf(rm1, __shfl_xor_sync(0xffffffffu, rm1, o));
        }
        float mn0 = fmaxf(m0, rm0 * scale);
        float mn1 = fmaxf(m1, rm1 * scale);
        float a0 = __expf(m0 - mn0);
        float a1 = __expf(m1 - mn1);
        m0 = mn0; m1 = mn1;

        float ps0 = 0.f, ps1 = 0.f;
#pragma unroll
        for (int nt = 0; nt < 16; nt++) {
            float p0 = __expf(fmaf(sacc[nt][0], scale, -mn0));
            float p1 = __expf(fmaf(sacc[nt][1], scale, -mn0));
            float p2 = __expf(fmaf(sacc[nt][2], scale, -mn1));
            float p3 = __expf(fmaf(sacc[nt][3], scale, -mn1));
            ps0 += p0 + p1;
            ps1 += p2 + p3;
            uint32_t* pp = &Ps[row * PF_LD + nt * 4 + lc];
            pp[0] = f2h2(p0, p1);
            pp[8 * PF_LD] = f2h2(p2, p3);
        }
#pragma unroll
        for (int o = 1; o <= 2; o <<= 1) {
            ps0 += __shfl_xor_sync(0xffffffffu, ps0, o);
            ps1 += __shfl_xor_sync(0xffffffffu, ps1, o);
        }
        l0 = l0 * a0 + ps0;
        l1 = l1 * a1 + ps1;

#pragma unroll
        for (int i = 0; i < 8; i++) {
            oacc[i][0] *= a0; oacc[i][1] *= a0;
            oacc[i][2] *= a1; oacc[i][3] *= a1;
        }
        __syncwarp();

        // ---- (P @ V) + (mask @ V), shared V fragments ----
#pragma unroll
        for (int ks2 = 0; ks2 < 8; ks2++) {
            uint32_t pa[4], ma[4];
            const uint32_t* pp = &Ps[row * PF_LD + ks2 * 8 + lc];
            pa[0] = pp[0];
            pa[1] = pp[8 * PF_LD];
            pa[2] = pp[4];
            pa[3] = pp[8 * PF_LD + 4];
            uint2 m02 = Mgp[kt * 32 + ks2 * 4 + lc];
            uint2 m13 = Mgp[8 * 256 + kt * 32 + ks2 * 4 + lc];
            ma[0] = m02.x; ma[1] = m13.x;
            ma[2] = m02.y; ma[3] = m13.y;
#pragma unroll
            for (int nt2 = 0; nt2 < 8; nt2++) {
                uint32_t vb[2];
                const uint32_t* vp = &Vsb[(nt2 * 8 + lr) * VF_LD + ks2 * 8 + lc];
                vb[0] = vp[0];
                vb[1] = vp[4];
                mma_f16(oacc[nt2], pa, vb);
                mma_f16(macc[nt2], ma, vb);
            }
        }

        if (kt + 1 < 8) {
            CP_WAIT(0);        // next K/V staged
            __syncthreads();   // all warps done with current buffers
        }
    }

    // ---- epilogue ----
    const float inv0 = 1.0f / l0;
    const float inv1 = 1.0f / l1;
    const int grow = qt * 64 + wm * 16 + lr;
#pragma unroll
    for (int nt2 = 0; nt2 < 8; nt2++) {
        int gn = h * HD + nt2 * 8 + (lc << 1);
        float2 v0 = make_float2(oacc[nt2][0] * inv0 + macc[nt2][0],
                                oacc[nt2][1] * inv0 + macc[nt2][1]);
        float2 v1 = make_float2(oacc[nt2][2] * inv1 + macc[nt2][2],
                                oacc[nt2][3] * inv1 + macc[nt2][3]);
        *(float2*)(out + ((size_t)b * SS + grow) * D_MODEL + gn) = v0;
        *(float2*)(out + ((size_t)b * SS + grow + 8) * D_MODEL + gn) = v1;
    }
}

// ===========================================================================
extern "C" void kernel_launch(void* const* d_in, const int* in_sizes, int n_in,
                              void* d_out, int out_size)
{
    const float* x    = (const float*)d_in[0];
    const float* y    = (const float*)d_in[1];
    const float* z    = (const float*)d_in[2];
    const float* mask = (const float*)d_in[3];
    const float* wq   = (const float*)d_in[4];
    const float* bq   = (const float*)d_in[5];
    const float* wk   = (const float*)d_in[6];
    const float* bk   = (const float*)d_in[7];
    const float* wv   = (const float*)d_in[8];
    const float* bv   = (const float*)d_in[9];
    float* out = (float*)d_out;

    cudaFuncSetAttribute(proj_mma,
                         cudaFuncAttributeMaxDynamicSharedMemorySize, SMEM_PROJ);
    cudaFuncSetAttribute(flash_kernel,
                         cudaFuncAttributeMaxDynamicSharedMemorySize, SMEM_FLASH);

    dim3 g0((MROWS * D_MODEL / 8 + 255) / 256, 7);
    cvt_kernel<<<g0, 256>>>(x, y, z, wq, wk, wv, mask);

    dim3 g1(D_MODEL / 128, MROWS / 128, 3);
    proj_mma<<<g1, 256, SMEM_PROJ>>>(bq, bk, bv);

    dim3 gv(SS / 128, BB * NH);
    vpack_kernel<<<gv, 256>>>();

    dim3 g2(SS / 64, BB * NH);
    flash_kernel<<<g2, 128, SMEM_FLASH>>>(out);
}

// round 11
// speedup vs baseline: 5.3859x; 1.0948x over previous
#include <cuda_runtime.h>
#include <cuda_fp16.h>
#include <cstdint>

#define D_MODEL 1024
#define NH 16
#define HD 64
#define BB 4
#define SS 1024
#define MROWS (BB * SS)   // 4096

// ---- scratch: fp16 packed b32 pairs. Pair p=g*4+j of a row of N b32 holds
// {b32[g*8+j], b32[g*8+j+4]} (so fragment elements {c, c+4} are one uint2). ----
__device__ uint2 g_q[(size_t)BB * NH * SS * 16];     // [bh][s][16 pairs]
__device__ uint2 g_k[(size_t)BB * NH * SS * 16];     // [bh][s][16 pairs]
__device__ uint2 g_v[(size_t)BB * NH * SS * 16];     // [bh][s][16 pairs]
__device__ uint2 g_vt[(size_t)BB * NH * HD * 256];   // [bh][d][256 pairs along s]
__device__ uint2 g_xc[(size_t)MROWS * 256];
__device__ uint2 g_yc[(size_t)MROWS * 256];
__device__ uint2 g_zc[(size_t)MROWS * 256];
__device__ uint2 g_wqc[(size_t)D_MODEL * 256];
__device__ uint2 g_wkc[(size_t)D_MODEL * 256];
__device__ uint2 g_wvc[(size_t)D_MODEL * 256];
__device__ uint2 g_mc[(size_t)SS * 256];

// ---------------------------------------------------------------------------
__device__ __forceinline__ uint32_t f2h2(float a, float b) {
    __half2 h = __floats2half2_rn(a, b);
    return *(uint32_t*)&h;
}

__device__ __forceinline__ void mma_f16(float c[4], const uint32_t a[4], const uint32_t b[2]) {
    asm("mma.sync.aligned.m16n8k16.row.col.f32.f16.f16.f32 "
        "{%0,%1,%2,%3}, {%4,%5,%6,%7}, {%8,%9}, {%0,%1,%2,%3};"
        : "+f"(c[0]), "+f"(c[1]), "+f"(c[2]), "+f"(c[3])
        : "r"(a[0]), "r"(a[1]), "r"(a[2]), "r"(a[3]), "r"(b[0]), "r"(b[1]));
}

__device__ __forceinline__ void cpa16(void* dst, const void* src) {
    uint32_t d = (uint32_t)__cvta_generic_to_shared(dst);
    asm volatile("cp.async.cg.shared.global [%0], [%1], 16;\n" :: "r"(d), "l"(src));
}
#define CP_COMMIT() asm volatile("cp.async.commit_group;\n" ::)
#define CP_WAIT(n)  asm volatile("cp.async.wait_group %0;\n" :: "n"(n))

// ===========================================================================
// Kernel 0: fp32 -> fp16, pair-packed, all 7 tensors (rows of 1024 floats).
// ===========================================================================
__global__ __launch_bounds__(256) void cvt_kernel(
    const float* __restrict__ x, const float* __restrict__ y,
    const float* __restrict__ z, const float* __restrict__ wq,
    const float* __restrict__ wk, const float* __restrict__ wv,
    const float* __restrict__ mask)
{
    const float* src;
    uint2* dst;
    size_t ngroups;
    switch (blockIdx.y) {
        case 0: src = x;    dst = g_xc;  ngroups = (size_t)MROWS * 256;   break;
        case 1: src = y;    dst = g_yc;  ngroups = (size_t)MROWS * 256;   break;
        case 2: src = z;    dst = g_zc;  ngroups = (size_t)MROWS * 256;   break;
        case 3: src = wq;   dst = g_wqc; ngroups = (size_t)D_MODEL * 256; break;
        case 4: src = wk;   dst = g_wkc; ngroups = (size_t)D_MODEL * 256; break;
        case 5: src = wv;   dst = g_wvc; ngroups = (size_t)D_MODEL * 256; break;
        default: src = mask; dst = g_mc; ngroups = (size_t)SS * 256;      break;
    }
    size_t gid = (size_t)blockIdx.x * 256 + threadIdx.x;
    if (gid >= ngroups) return;
    size_t row = gid >> 8;
    int p = (int)(gid & 255);
    int g = p >> 2, j = p & 3;
    const float* mrow = src + row * 1024;
    float f0 = mrow[16 * g + 2 * j];
    float f1 = mrow[16 * g + 2 * j + 1];
    float f2 = mrow[16 * g + 2 * j + 8];
    float f3 = mrow[16 * g + 2 * j + 9];
    dst[row * 256 + p] = make_uint2(f2h2(f0, f1), f2h2(f2, f3));
}

// ===========================================================================
// Kernel 1: fused QKV projection, fp16 m16n8k16, pair-packed operands,
// cp.async double buffer. Output Q/K/V pair-packed head-major.
// ===========================================================================
#define PJ_LD 12                       // uint2 stride (8 used + 4 pad)
#define PJ_SZ (128 * PJ_LD)            // uint2 per buffer
#define SMEM_PROJ (4 * PJ_SZ * 8)      // 49152 B

__global__ __launch_bounds__(256) void proj_mma(
    const float* __restrict__ bq, const float* __restrict__ bk,
    const float* __restrict__ bv)
{
    extern __shared__ uint2 smp[];
    uint2* Asp = smp;                  // [2][128][12]
    uint2* Bsp = smp + 2 * PJ_SZ;      // [2][128][12]

    const int which = blockIdx.z;
    const uint2* A    = which == 0 ? g_xc  : (which == 1 ? g_yc  : g_zc);
    const uint2* W    = which == 0 ? g_wqc : (which == 1 ? g_wkc : g_wvc);
    const float* bias = which == 0 ? bq    : (which == 1 ? bk    : bv);
    uint2* out        = which == 0 ? g_q   : (which == 1 ? g_k   : g_v);

    const int tid  = threadIdx.x;
    const int lane = tid & 31;
    const int wid  = tid >> 5;
    const int wm   = wid >> 2;
    const int wn   = wid & 3;
    const int m0   = blockIdx.y * 128;
    const int n0   = blockIdx.x * 128;
    const int lr   = lane >> 2;
    const int lc   = lane & 3;

    float acc[4][4][4];
#pragma unroll
    for (int i = 0; i < 4; i++)
#pragma unroll
        for (int j = 0; j < 4; j++)
#pragma unroll
            for (int r = 0; r < 4; r++) acc[i][j][r] = 0.f;

    auto stage = [&](int buf, int ch) {
        // chunk = 8 uint2 per row = 4 cpa16
#pragma unroll
        for (int i = 0; i < 2; i++) {
            int idx = tid + i * 256;      // 0..511
            int r = idx >> 2;             // 0..127
            int sg = (idx & 3) << 1;      // uint2 seg 0,2,4,6
            cpa16(&Asp[buf * PJ_SZ + r * PJ_LD + sg],
                  A + (size_t)(m0 + r) * 256 + ch * 8 + sg);
            cpa16(&Bsp[buf * PJ_SZ + r * PJ_LD + sg],
                  W + (size_t)(n0 + r) * 256 + ch * 8 + sg);
        }
    };

    stage(0, 0);
    CP_COMMIT();

    for (int ch = 0; ch < 32; ch++) {
        if (ch + 1 < 32) { stage((ch + 1) & 1, ch + 1); CP_COMMIT(); }
        if (ch + 1 < 32) { CP_WAIT(1); } else { CP_WAIT(0); }
        __syncthreads();

        const uint2* Ab = &Asp[(ch & 1) * PJ_SZ];
        const uint2* Bb = &Bsp[(ch & 1) * PJ_SZ];
#pragma unroll
        for (int st = 0; st < 2; st++) {
            uint32_t af[4][4], bf[4][2];
#pragma unroll
            for (int ms = 0; ms < 4; ms++) {
                uint2 u0 = Ab[(wm * 64 + ms * 16 + lr) * PJ_LD + st * 4 + lc];
                uint2 u1 = Ab[(wm * 64 + ms * 16 + lr + 8) * PJ_LD + st * 4 + lc];
                af[ms][0] = u0.x; af[ms][1] = u1.x;
                af[ms][2] = u0.y; af[ms][3] = u1.y;
            }
#pragma unroll
            for (int ns = 0; ns < 4; ns++) {
                uint2 u = Bb[(wn * 32 + ns * 8 + lr) * PJ_LD + st * 4 + lc];
                bf[ns][0] = u.x; bf[ns][1] = u.y;
            }
#pragma unroll
            for (int ms = 0; ms < 4; ms++)
#pragma unroll
                for (int ns = 0; ns < 4; ns++)
                    mma_f16(acc[ms][ns], af[ms], bf[ns]);
        }
        __syncthreads();
    }

    // epilogue: +bias, pack pair uint2, head-major write
#pragma unroll
    for (int ms = 0; ms < 4; ms++) {
        int gm = m0 + wm * 64 + ms * 16 + lr;
#pragma unroll
        for (int pg = 0; pg < 2; pg++) {
            int ns0 = 2 * pg;
            int gn = n0 + wn * 32 + ns0 * 8 + (lc << 1);
            float b0x = bias[gn],     b0y = bias[gn + 1];
            float b1x = bias[gn + 8], b1y = bias[gn + 9];
            int h = gn >> 6;
            int c = (gn & 63) >> 1;
            int p = (c >> 3) * 4 + lc;
            {
                int b = gm >> 10, s = gm & 1023;
                uint2 v = make_uint2(
                    f2h2(acc[ms][ns0][0] + b0x, acc[ms][ns0][1] + b0y),
                    f2h2(acc[ms][ns0 + 1][0] + b1x, acc[ms][ns0 + 1][1] + b1y));
                out[(((size_t)(b * NH + h)) * SS + s) * 16 + p] = v;
            }
            {
                int gm2 = gm + 8;
                int b = gm2 >> 10, s = gm2 & 1023;
                uint2 v = make_uint2(
                    f2h2(acc[ms][ns0][2] + b0x, acc[ms][ns0][3] + b0y),
                    f2h2(acc[ms][ns0 + 1][2] + b1x, acc[ms][ns0 + 1][3] + b1y));
                out[(((size_t)(b * NH + h)) * SS + s) * 16 + p] = v;
            }
        }
    }
}

// ===========================================================================
// Kernel 1b: V transpose -> g_vt [bh][d][pairs along s-b32].
// ===========================================================================
__global__ __launch_bounds__(256) void vpack_kernel()
{
    __shared__ uint32_t vt32[128 * 33];   // [s within tile][d/2 b32]
    const int st = blockIdx.x;     // 0..7
    const int bh = blockIdx.y;     // 0..63
    const int tid = threadIdx.x;

    const uint2* src = g_v + ((size_t)bh * SS + st * 128) * 16;
#pragma unroll
    for (int i = 0; i < 8; i++) {
        int idx = i * 256 + tid;       // 0..2047
        int r = idx >> 4;              // 0..127
        int p = idx & 15;
        uint2 u = src[(size_t)r * 16 + p];
        int g = p >> 2, j = p & 3;
        vt32[r * 33 + g * 8 + j] = u.x;
        vt32[r * 33 + g * 8 + j + 4] = u.y;
    }
    __syncthreads();

#pragma unroll
    for (int i = 0; i < 8; i++) {
        int idx = i * 256 + tid;       // 0..2047
        int d = idx >> 5;              // 0..63
        int p = idx & 31;              // output pair within tile
        int g = p >> 2, j = p & 3;
        int c = g * 8 + j;             // s-b32 col (low); pair partner c+4
        uint32_t lo0 = vt32[(2 * c) * 33 + (d >> 1)];
        uint32_t hi0 = vt32[(2 * c + 1) * 33 + (d >> 1)];
        uint32_t lo1 = vt32[(2 * (c + 4)) * 33 + (d >> 1)];
        uint32_t hi1 = vt32[(2 * (c + 4) + 1) * 33 + (d >> 1)];
        uint32_t e0, e1;
        if (d & 1) {
            e0 = (lo0 >> 16) | (hi0 & 0xffff0000u);
            e1 = (lo1 >> 16) | (hi1 & 0xffff0000u);
        } else {
            e0 = (lo0 & 0xffffu) | (hi0 << 16);
            e1 = (lo1 & 0xffffu) | (hi1 << 16);
        }
        g_vt[((size_t)bh * 64 + d) * 256 + st * 32 + p] = make_uint2(e0, e1);
    }
}

// ===========================================================================
// Kernel 2: fused flash attention + mask@V, fp16, pair-packed everything.
// 4 warps / 64 q-rows, K/V double-buffered, 2 CTAs/SM.
// ===========================================================================
#define KF_LD 20                   // uint2 stride (16 used + 4 pad)
#define VF_LD 36                   // uint2 stride (32 used + 4 pad)
#define PF_LD 36                   // uint2 stride (32 used + 4 pad)
#define KF_SZ (128 * KF_LD)
#define VF_SZ (64 * VF_LD)
#define SMEM_FLASH ((2 * KF_SZ + 2 * VF_SZ + 64 * PF_LD) * 8)   // 96256 B

__global__ __launch_bounds__(128, 2) void flash_kernel(float* __restrict__ out)
{
    extern __shared__ uint2 smf[];
    uint2* Ksp = smf;                          // [2][128][20]
    uint2* Vsp = smf + 2 * KF_SZ;              // [2][64][36]
    uint2* Pp  = smf + 2 * KF_SZ + 2 * VF_SZ;  // [64][36] (Q staging, then P)

    const int tid  = threadIdx.x;
    const int lane = tid & 31;
    const int wm   = tid >> 5;
    const int lr   = lane >> 2;
    const int lc   = lane & 3;

    const int qt = blockIdx.x;
    const int bh = blockIdx.y;
    const int b  = bh >> 4, h = bh & 15;

    const uint2* Qg = g_q + ((size_t)bh * SS + qt * 64) * 16;
    const uint2* Kg = g_k + (size_t)bh * SS * 16;
    const uint2* Vg = g_vt + (size_t)bh * 64 * 256;
    const uint2* Mgp = g_mc + (size_t)(qt * 64 + wm * 16 + lr) * 256;

    auto stageKV = [&](int kt, int buf) {
#pragma unroll
        for (int i = 0; i < 8; i++) {            // K: 128 rows x 8 cpa16
            int idx = i * 128 + tid;
            int r = idx >> 3;                    // 0..127
            int sg = (idx & 7) << 1;             // uint2 seg
            cpa16(&Ksp[buf * KF_SZ + r * KF_LD + sg],
                  Kg + (size_t)(kt * 128 + r) * 16 + sg);
        }
#pragma unroll
        for (int i = 0; i < 8; i++) {            // V: 64 rows x 16 cpa16
            int idx = i * 128 + tid;
            int r = idx >> 4;                    // 0..63
            int sg = (idx & 15) << 1;
            cpa16(&Vsp[buf * VF_SZ + r * VF_LD + sg],
                  Vg + (size_t)r * 256 + kt * 32 + sg);
        }
    };

    // ---- prologue: K/V tile 0 + Q, one group ----
    stageKV(0, 0);
#pragma unroll
    for (int i = 0; i < 4; i++) {
        int idx = i * 128 + tid;          // 0..511
        int r = idx >> 3;                 // 0..63
        int sg = (idx & 7) << 1;
        cpa16(&Pp[r * PF_LD + sg], Qg + (size_t)r * 16 + sg);
    }
    CP_COMMIT();
    CP_WAIT(0);
    __syncthreads();

    uint32_t qf[4][4];
#pragma unroll
    for (int st = 0; st < 4; st++) {
        uint2 u0 = Pp[(wm * 16 + lr) * PF_LD + st * 4 + lc];
        uint2 u1 = Pp[(wm * 16 + lr + 8) * PF_LD + st * 4 + lc];
        qf[st][0] = u0.x; qf[st][1] = u1.x;
        qf[st][2] = u0.y; qf[st][3] = u1.y;
    }
    // Pp rows are warp-private; safe to overwrite with P after this point.

    float m0 = -1e30f, m1 = -1e30f;
    float l0 = 0.f, l1 = 0.f;
    float oacc[8][4], macc[8][4];
#pragma unroll
    for (int i = 0; i < 8; i++)
#pragma unroll
        for (int r = 0; r < 4; r++) { oacc[i][r] = 0.f; macc[i][r] = 0.f; }

    const float scale = 0.03125f;
    const int row = wm * 16 + lr;

    for (int kt = 0; kt < 8; kt++) {
        const int bf_ = kt & 1;
        if (kt + 1 < 8) { stageKV(kt + 1, bf_ ^ 1); CP_COMMIT(); }

        const uint2* Ksb = &Ksp[bf_ * KF_SZ];
        const uint2* Vsb = &Vsp[bf_ * VF_SZ];

        // ---- QK^T ----
        float sacc[16][4];
#pragma unroll
        for (int nt = 0; nt < 16; nt++)
#pragma unroll
            for (int r = 0; r < 4; r++) sacc[nt][r] = 0.f;

#pragma unroll
        for (int st = 0; st < 4; st++) {
#pragma unroll
            for (int nt = 0; nt < 16; nt++) {
                uint2 u = Ksb[(nt * 8 + lr) * KF_LD + st * 4 + lc];
                uint32_t bf2[2] = {u.x, u.y};
                mma_f16(sacc[nt], qf[st], bf2);
            }
        }

        // ---- online softmax ----
        float rm0 = -1e30f, rm1 = -1e30f;
#pragma unroll
        for (int nt = 0; nt < 16; nt++) {
            rm0 = fmaxf(rm0, fmaxf(sacc[nt][0], sacc[nt][1]));
            rm1 = fmaxf(rm1, fmaxf(sacc[nt][2], sacc[nt][3]));
        }
#pragma unroll
        for (int o = 1; o <= 2; o <<= 1) {
            rm0 = fmaxf(rm0, __shfl_xor_sync(0xffffffffu, rm0, o));
            rm1 = fmaxf(rm1, __shfl_xor_sync(0xffffffffu, rm1, o));
        }
        float mn0 = fmaxf(m0, rm0 * scale);
        float mn1 = fmaxf(m1, rm1 * scale);
        float a0 = __expf(m0 - mn0);
        float a1 = __expf(m1 - mn1);
        m0 = mn0; m1 = mn1;

        float ps0 = 0.f, ps1 = 0.f;
#pragma unroll
        for (int nt2 = 0; nt2 < 8; nt2++) {
            int ntA = 2 * nt2, ntB = 2 * nt2 + 1;
            float a_p0 = __expf(fmaf(sacc[ntA][0], scale, -mn0));
            float a_p1 = __expf(fmaf(sacc[ntA][1], scale, -mn0));
            float a_p2 = __expf(fmaf(sacc[ntA][2], scale, -mn1));
            float a_p3 = __expf(fmaf(sacc[ntA][3], scale, -mn1));
            float b_p0 = __expf(fmaf(sacc[ntB][0], scale, -mn0));
            float b_p1 = __expf(fmaf(sacc[ntB][1], scale, -mn0));
            float b_p2 = __expf(fmaf(sacc[ntB][2], scale, -mn1));
            float b_p3 = __expf(fmaf(sacc[ntB][3], scale, -mn1));
            ps0 += a_p0 + a_p1 + b_p0 + b_p1;
            ps1 += a_p2 + a_p3 + b_p2 + b_p3;
            Pp[row * PF_LD + nt2 * 4 + lc] =
                make_uint2(f2h2(a_p0, a_p1), f2h2(b_p0, b_p1));
            Pp[(row + 8) * PF_LD + nt2 * 4 + lc] =
                make_uint2(f2h2(a_p2, a_p3), f2h2(b_p2, b_p3));
        }
#pragma unroll
        for (int o = 1; o <= 2; o <<= 1) {
            ps0 += __shfl_xor_sync(0xffffffffu, ps0, o);
            ps1 += __shfl_xor_sync(0xffffffffu, ps1, o);
        }
        l0 = l0 * a0 + ps0;
        l1 = l1 * a1 + ps1;

#pragma unroll
        for (int i = 0; i < 8; i++) {
            oacc[i][0] *= a0; oacc[i][1] *= a0;
            oacc[i][2] *= a1; oacc[i][3] *= a1;
        }
        __syncwarp();

        // ---- (P @ V) + (mask @ V), shared V fragments ----
#pragma unroll
        for (int ks2 = 0; ks2 < 8; ks2++) {
            uint32_t pa[4], ma[4];
            uint2 u0 = Pp[row * PF_LD + ks2 * 4 + lc];
            uint2 u1 = Pp[(row + 8) * PF_LD + ks2 * 4 + lc];
            pa[0] = u0.x; pa[1] = u1.x;
            pa[2] = u0.y; pa[3] = u1.y;
            uint2 m02 = Mgp[kt * 32 + ks2 * 4 + lc];
            uint2 m13 = Mgp[8 * 256 + kt * 32 + ks2 * 4 + lc];
            ma[0] = m02.x; ma[1] = m13.x;
            ma[2] = m02.y; ma[3] = m13.y;
#pragma unroll
            for (int nt2 = 0; nt2 < 8; nt2++) {
                uint2 uv = Vsb[(nt2 * 8 + lr) * VF_LD + ks2 * 4 + lc];
                uint32_t vb[2] = {uv.x, uv.y};
                mma_f16(oacc[nt2], pa, vb);
                mma_f16(macc[nt2], ma, vb);
            }
        }

        if (kt + 1 < 8) {
            CP_WAIT(0);
            __syncthreads();
        }
    }

    // ---- epilogue ----
    const float inv0 = 1.0f / l0;
    const float inv1 = 1.0f / l1;
    const int grow = qt * 64 + wm * 16 + lr;
#pragma unroll
    for (int nt2 = 0; nt2 < 8; nt2++) {
        int gn = h * HD + nt2 * 8 + (lc << 1);
        float2 v0 = make_float2(oacc[nt2][0] * inv0 + macc[nt2][0],
                                oacc[nt2][1] * inv0 + macc[nt2][1]);
        float2 v1 = make_float2(oacc[nt2][2] * inv1 + macc[nt2][2],
                                oacc[nt2][3] * inv1 + macc[nt2][3]);
        *(float2*)(out + ((size_t)b * SS + grow) * D_MODEL + gn) = v0;
        *(float2*)(out + ((size_t)b * SS + grow + 8) * D_MODEL + gn) = v1;
    }
}

// ===========================================================================
extern "C" void kernel_launch(void* const* d_in, const int* in_sizes, int n_in,
                              void* d_out, int out_size)
{
    const float* x    = (const float*)d_in[0];
    const float* y    = (const float*)d_in[1];
    const float* z    = (const float*)d_in[2];
    const float* mask = (const float*)d_in[3];
    const float* wq   = (const float*)d_in[4];
    const float* bq   = (const float*)d_in[5];
    const float* wk   = (const float*)d_in[6];
    const float* bk   = (const float*)d_in[7];
    const float* wv   = (const float*)d_in[8];
    const float* bv   = (const float*)d_in[9];
    float* out = (float*)d_out;

    cudaFuncSetAttribute(proj_mma,
                         cudaFuncAttributeMaxDynamicSharedMemorySize, SMEM_PROJ);
    cudaFuncSetAttribute(flash_kernel,
                         cudaFuncAttributeMaxDynamicSharedMemorySize, SMEM_FLASH);

    dim3 g0((MROWS * 256 + 255) / 256, 7);
    cvt_kernel<<<g0, 256>>>(x, y, z, wq, wk, wv, mask);

    dim3 g1(D_MODEL / 128, MROWS / 128, 3);
    proj_mma<<<g1, 256, SMEM_PROJ>>>(bq, bk, bv);

    dim3 gv(SS / 128, BB * NH);
    vpack_kernel<<<gv, 256>>>();

    dim3 g2(SS / 64, BB * NH);
    flash_kernel<<<g2, 128, SMEM_FLASH>>>(out);
}

// round 12
// speedup vs baseline: 6.5067x; 1.2081x over previous
#include <cuda_runtime.h>
#include <cuda_fp16.h>
#include <cstdint>

#define D_MODEL 1024
#define NH 16
#define HD 64
#define BB 4
#define SS 1024
#define MROWS (BB * SS)   // 4096

// ---- scratch: fp16 packed b32 pairs. Pair p=g*4+j of a row of N b32 holds
// {b32[g*8+j], b32[g*8+j+4]}. ----
__device__ uint2 g_q[(size_t)BB * NH * SS * 16];     // [bh][s][16 pairs] (pre-scaled by log2e/32)
__device__ uint2 g_k[(size_t)BB * NH * SS * 16];
__device__ uint2 g_v[(size_t)BB * NH * SS * 16];
__device__ uint2 g_vt[(size_t)BB * NH * HD * 256];   // [bh][d][pairs along s]
__device__ uint2 g_xc[(size_t)MROWS * 256];
__device__ uint2 g_yc[(size_t)MROWS * 256];
__device__ uint2 g_zc[(size_t)MROWS * 256];
__device__ uint2 g_wqc[(size_t)D_MODEL * 256];
__device__ uint2 g_wkc[(size_t)D_MODEL * 256];
__device__ uint2 g_wvc[(size_t)D_MODEL * 256];
__device__ uint2 g_mc[(size_t)SS * 256];

// ---------------------------------------------------------------------------
__device__ __forceinline__ uint32_t f2h2(float a, float b) {
    __half2 h = __floats2half2_rn(a, b);
    return *(uint32_t*)&h;
}

// exp2 of two fp32 values -> fp16x2 (lo = 2^a, hi = 2^b)
__device__ __forceinline__ uint32_t ex2h2(float a, float b) {
    uint32_t r;
    asm("{\n\t.reg .b32 t;\n\t"
        "cvt.rn.f16x2.f32 t, %2, %1;\n\t"     // hi=%2(b), lo=%1(a)
        "ex2.approx.f16x2 %0, t;\n\t}"
        : "=r"(r) : "f"(a), "f"(b));
    return r;
}

__device__ __forceinline__ void mma_f16(float c[4], const uint32_t a[4], const uint32_t b[2]) {
    asm("mma.sync.aligned.m16n8k16.row.col.f32.f16.f16.f32 "
        "{%0,%1,%2,%3}, {%4,%5,%6,%7}, {%8,%9}, {%0,%1,%2,%3};"
        : "+f"(c[0]), "+f"(c[1]), "+f"(c[2]), "+f"(c[3])
        : "r"(a[0]), "r"(a[1]), "r"(a[2]), "r"(a[3]), "r"(b[0]), "r"(b[1]));
}

__device__ __forceinline__ void cpa16(void* dst, const void* src) {
    uint32_t d = (uint32_t)__cvta_generic_to_shared(dst);
    asm volatile("cp.async.cg.shared.global [%0], [%1], 16;\n" :: "r"(d), "l"(src));
}
#define CP_COMMIT() asm volatile("cp.async.commit_group;\n" ::)
#define CP_WAIT(n)  asm volatile("cp.async.wait_group %0;\n" :: "n"(n))

// log2(e) / 32  (folded into Q so QK^T is directly in log2 domain)
#define QSCALE 0.045084220027780106f

// ===========================================================================
// Kernel 0: fp32 -> fp16, pair-packed, all 7 tensors (rows of 1024 floats).
// ===========================================================================
__global__ __launch_bounds__(256) void cvt_kernel(
    const float* __restrict__ x, const float* __restrict__ y,
    const float* __restrict__ z, const float* __restrict__ wq,
    const float* __restrict__ wk, const float* __restrict__ wv,
    const float* __restrict__ mask)
{
    const float* src;
    uint2* dst;
    size_t ngroups;
    switch (blockIdx.y) {
        case 0: src = x;    dst = g_xc;  ngroups = (size_t)MROWS * 256;   break;
        case 1: src = y;    dst = g_yc;  ngroups = (size_t)MROWS * 256;   break;
        case 2: src = z;    dst = g_zc;  ngroups = (size_t)MROWS * 256;   break;
        case 3: src = wq;   dst = g_wqc; ngroups = (size_t)D_MODEL * 256; break;
        case 4: src = wk;   dst = g_wkc; ngroups = (size_t)D_MODEL * 256; break;
        case 5: src = wv;   dst = g_wvc; ngroups = (size_t)D_MODEL * 256; break;
        default: src = mask; dst = g_mc; ngroups = (size_t)SS * 256;      break;
    }
    size_t gid = (size_t)blockIdx.x * 256 + threadIdx.x;
    if (gid >= ngroups) return;
    size_t row = gid >> 8;
    int p = (int)(gid & 255);
    int g = p >> 2, j = p & 3;
    const float* mrow = src + row * 1024;
    float f0 = mrow[16 * g + 2 * j];
    float f1 = mrow[16 * g + 2 * j + 1];
    float f2 = mrow[16 * g + 2 * j + 8];
    float f3 = mrow[16 * g + 2 * j + 9];
    dst[row * 256 + p] = make_uint2(f2h2(f0, f1), f2h2(f2, f3));
}

// ===========================================================================
// Kernel 1: fused QKV projection, fp16 m16n8k16, pair-packed, double buffer.
// Q output is pre-scaled by log2(e)/32.
// ===========================================================================
#define PJ_LD 12
#define PJ_SZ (128 * PJ_LD)
#define SMEM_PROJ (4 * PJ_SZ * 8)      // 49152 B

__global__ __launch_bounds__(256) void proj_mma(
    const float* __restrict__ bq, const float* __restrict__ bk,
    const float* __restrict__ bv)
{
    extern __shared__ uint2 smp[];
    uint2* Asp = smp;
    uint2* Bsp = smp + 2 * PJ_SZ;

    const int which = blockIdx.z;
    const uint2* A    = which == 0 ? g_xc  : (which == 1 ? g_yc  : g_zc);
    const uint2* W    = which == 0 ? g_wqc : (which == 1 ? g_wkc : g_wvc);
    const float* bias = which == 0 ? bq    : (which == 1 ? bk    : bv);
    uint2* out        = which == 0 ? g_q   : (which == 1 ? g_k   : g_v);
    const float oscale = which == 0 ? QSCALE : 1.0f;

    const int tid  = threadIdx.x;
    const int lane = tid & 31;
    const int wid  = tid >> 5;
    const int wm   = wid >> 2;
    const int wn   = wid & 3;
    const int m0   = blockIdx.y * 128;
    const int n0   = blockIdx.x * 128;
    const int lr   = lane >> 2;
    const int lc   = lane & 3;

    float acc[4][4][4];
#pragma unroll
    for (int i = 0; i < 4; i++)
#pragma unroll
        for (int j = 0; j < 4; j++)
#pragma unroll
            for (int r = 0; r < 4; r++) acc[i][j][r] = 0.f;

    auto stage = [&](int buf, int ch) {
#pragma unroll
        for (int i = 0; i < 2; i++) {
            int idx = tid + i * 256;
            int r = idx >> 2;
            int sg = (idx & 3) << 1;
            cpa16(&Asp[buf * PJ_SZ + r * PJ_LD + sg],
                  A + (size_t)(m0 + r) * 256 + ch * 8 + sg);
            cpa16(&Bsp[buf * PJ_SZ + r * PJ_LD + sg],
                  W + (size_t)(n0 + r) * 256 + ch * 8 + sg);
        }
    };

    stage(0, 0);
    CP_COMMIT();

    for (int ch = 0; ch < 32; ch++) {
        if (ch + 1 < 32) { stage((ch + 1) & 1, ch + 1); CP_COMMIT(); }
        if (ch + 1 < 32) { CP_WAIT(1); } else { CP_WAIT(0); }
        __syncthreads();

        const uint2* Ab = &Asp[(ch & 1) * PJ_SZ];
        const uint2* Bb = &Bsp[(ch & 1) * PJ_SZ];
#pragma unroll
        for (int st = 0; st < 2; st++) {
            uint32_t af[4][4], bf[4][2];
#pragma unroll
            for (int ms = 0; ms < 4; ms++) {
                uint2 u0 = Ab[(wm * 64 + ms * 16 + lr) * PJ_LD + st * 4 + lc];
                uint2 u1 = Ab[(wm * 64 + ms * 16 + lr + 8) * PJ_LD + st * 4 + lc];
                af[ms][0] = u0.x; af[ms][1] = u1.x;
                af[ms][2] = u0.y; af[ms][3] = u1.y;
            }
#pragma unroll
            for (int ns = 0; ns < 4; ns++) {
                uint2 u = Bb[(wn * 32 + ns * 8 + lr) * PJ_LD + st * 4 + lc];
                bf[ns][0] = u.x; bf[ns][1] = u.y;
            }
#pragma unroll
            for (int ms = 0; ms < 4; ms++)
#pragma unroll
                for (int ns = 0; ns < 4; ns++)
                    mma_f16(acc[ms][ns], af[ms], bf[ns]);
        }
        __syncthreads();
    }

#pragma unroll
    for (int ms = 0; ms < 4; ms++) {
        int gm = m0 + wm * 64 + ms * 16 + lr;
#pragma unroll
        for (int pg = 0; pg < 2; pg++) {
            int ns0 = 2 * pg;
            int gn = n0 + wn * 32 + ns0 * 8 + (lc << 1);
            float b0x = bias[gn],     b0y = bias[gn + 1];
            float b1x = bias[gn + 8], b1y = bias[gn + 9];
            int h = gn >> 6;
            int c = (gn & 63) >> 1;
            int p = (c >> 3) * 4 + lc;
            {
                int b = gm >> 10, s = gm & 1023;
                uint2 v = make_uint2(
                    f2h2((acc[ms][ns0][0] + b0x) * oscale, (acc[ms][ns0][1] + b0y) * oscale),
                    f2h2((acc[ms][ns0 + 1][0] + b1x) * oscale, (acc[ms][ns0 + 1][1] + b1y) * oscale));
                out[(((size_t)(b * NH + h)) * SS + s) * 16 + p] = v;
            }
            {
                int gm2 = gm + 8;
                int b = gm2 >> 10, s = gm2 & 1023;
                uint2 v = make_uint2(
                    f2h2((acc[ms][ns0][2] + b0x) * oscale, (acc[ms][ns0][3] + b0y) * oscale),
                    f2h2((acc[ms][ns0 + 1][2] + b1x) * oscale, (acc[ms][ns0 + 1][3] + b1y) * oscale));
                out[(((size_t)(b * NH + h)) * SS + s) * 16 + p] = v;
            }
        }
    }
}

// ===========================================================================
// Kernel 1b: V transpose -> g_vt [bh][d][pairs along s-b32].
// ===========================================================================
__global__ __launch_bounds__(256) void vpack_kernel()
{
    __shared__ uint32_t vt32[128 * 33];
    const int st = blockIdx.x;
    const int bh = blockIdx.y;
    const int tid = threadIdx.x;

    const uint2* src = g_v + ((size_t)bh * SS + st * 128) * 16;
#pragma unroll
    for (int i = 0; i < 8; i++) {
        int idx = i * 256 + tid;
        int r = idx >> 4;
        int p = idx & 15;
        uint2 u = src[(size_t)r * 16 + p];
        int g = p >> 2, j = p & 3;
        vt32[r * 33 + g * 8 + j] = u.x;
        vt32[r * 33 + g * 8 + j + 4] = u.y;
    }
    __syncthreads();

#pragma unroll
    for (int i = 0; i < 8; i++) {
        int idx = i * 256 + tid;
        int d = idx >> 5;
        int p = idx & 31;
        int g = p >> 2, j = p & 3;
        int c = g * 8 + j;
        uint32_t lo0 = vt32[(2 * c) * 33 + (d >> 1)];
        uint32_t hi0 = vt32[(2 * c + 1) * 33 + (d >> 1)];
        uint32_t lo1 = vt32[(2 * (c + 4)) * 33 + (d >> 1)];
        uint32_t hi1 = vt32[(2 * (c + 4) + 1) * 33 + (d >> 1)];
        uint32_t e0, e1;
        if (d & 1) {
            e0 = (lo0 >> 16) | (hi0 & 0xffff0000u);
            e1 = (lo1 >> 16) | (hi1 & 0xffff0000u);
        } else {
            e0 = (lo0 & 0xffffu) | (hi0 << 16);
            e1 = (lo1 & 0xffffu) | (hi1 << 16);
        }
        g_vt[((size_t)bh * 64 + d) * 256 + st * 32 + p] = make_uint2(e0, e1);
    }
}

// ===========================================================================
// Kernel 2: fused flash attention + mask@V.
// Register-resident P (QK C-frag == PV A-frag), no-max softmax in log2 domain,
// ex2.approx.f16x2, row sums via ones-MMA. 4 warps / 64 q-rows, 2 CTAs/SM.
// ===========================================================================
#define KF_LD 20
#define VF_LD 36
#define QS_LD 20
#define KF_SZ (128 * KF_LD)
#define VF_SZ (64 * VF_LD)
#define SMEM_FLASH ((2 * KF_SZ + 2 * VF_SZ + 64 * QS_LD) * 8)   // 88064 B

__global__ __launch_bounds__(128, 2) void flash_kernel(float* __restrict__ out)
{
    extern __shared__ uint2 smf[];
    uint2* Ksp = smf;                          // [2][128][20]
    uint2* Vsp = smf + 2 * KF_SZ;              // [2][64][36]
    uint2* Qs  = smf + 2 * KF_SZ + 2 * VF_SZ;  // [64][20]

    const int tid  = threadIdx.x;
    const int lane = tid & 31;
    const int wm   = tid >> 5;
    const int lr   = lane >> 2;
    const int lc   = lane & 3;

    const int qt = blockIdx.x;
    const int bh = blockIdx.y;
    const int b  = bh >> 4, h = bh & 15;

    const uint2* Qg = g_q + ((size_t)bh * SS + qt * 64) * 16;
    const uint2* Kg = g_k + (size_t)bh * SS * 16;
    const uint2* Vg = g_vt + (size_t)bh * 64 * 256;
    const uint2* Mgp = g_mc + (size_t)(qt * 64 + wm * 16 + lr) * 256;

    auto stageKV = [&](int kt, int buf) {
#pragma unroll
        for (int i = 0; i < 8; i++) {
            int idx = i * 128 + tid;
            int r = idx >> 3;
            int sg = (idx & 7) << 1;
            cpa16(&Ksp[buf * KF_SZ + r * KF_LD + sg],
                  Kg + (size_t)(kt * 128 + r) * 16 + sg);
        }
#pragma unroll
        for (int i = 0; i < 8; i++) {
            int idx = i * 128 + tid;
            int r = idx >> 4;
            int sg = (idx & 15) << 1;
            cpa16(&Vsp[buf * VF_SZ + r * VF_LD + sg],
                  Vg + (size_t)r * 256 + kt * 32 + sg);
        }
    };

    // ---- prologue ----
    stageKV(0, 0);
#pragma unroll
    for (int i = 0; i < 4; i++) {
        int idx = i * 128 + tid;
        int r = idx >> 3;
        int sg = (idx & 7) << 1;
        cpa16(&Qs[r * QS_LD + sg], Qg + (size_t)r * 16 + sg);
    }
    CP_COMMIT();
    CP_WAIT(0);
    __syncthreads();

    uint32_t qf[4][4];
#pragma unroll
    for (int st = 0; st < 4; st++) {
        uint2 u0 = Qs[(wm * 16 + lr) * QS_LD + st * 4 + lc];
        uint2 u1 = Qs[(wm * 16 + lr + 8) * QS_LD + st * 4 + lc];
        qf[st][0] = u0.x; qf[st][1] = u1.x;
        qf[st][2] = u0.y; qf[st][3] = u1.y;
    }

    float oacc[8][4], macc[8][4], lacc[4];
#pragma unroll
    for (int i = 0; i < 8; i++)
#pragma unroll
        for (int r = 0; r < 4; r++) { oacc[i][r] = 0.f; macc[i][r] = 0.f; }
#pragma unroll
    for (int r = 0; r < 4; r++) lacc[r] = 0.f;

    const uint32_t ONE2 = 0x3C003C00u;   // half2(1.0, 1.0)

    for (int kt = 0; kt < 8; kt++) {
        const int bf_ = kt & 1;
        if (kt + 1 < 8) { stageKV(kt + 1, bf_ ^ 1); CP_COMMIT(); }

        const uint2* Ksb = &Ksp[bf_ * KF_SZ];
        const uint2* Vsb = &Vsp[bf_ * VF_SZ];

        // prefetch this tile's mask fragments (latency hidden behind QK)
        uint2 m02r[8], m13r[8];
#pragma unroll
        for (int ks2 = 0; ks2 < 8; ks2++) {
            m02r[ks2] = Mgp[kt * 32 + ks2 * 4 + lc];
            m13r[ks2] = Mgp[8 * 256 + kt * 32 + ks2 * 4 + lc];
        }

        // ---- QK^T (log2-domain logits: Q pre-scaled by log2e/32) ----
        float sacc[16][4];
#pragma unroll
        for (int nt = 0; nt < 16; nt++)
#pragma unroll
            for (int r = 0; r < 4; r++) sacc[nt][r] = 0.f;

#pragma unroll
        for (int st = 0; st < 4; st++) {
#pragma unroll
            for (int nt = 0; nt < 16; nt++) {
                uint2 u = Ksb[(nt * 8 + lr) * KF_LD + st * 4 + lc];
                uint32_t bf2[2] = {u.x, u.y};
                mma_f16(sacc[nt], qf[st], bf2);
            }
        }

        // ---- P = 2^sacc (register-resident), l += P@1, PV + MV ----
#pragma unroll
        for (int ks2 = 0; ks2 < 8; ks2++) {
            uint32_t pa[4], ma[4];
            pa[0] = ex2h2(sacc[2 * ks2][0], sacc[2 * ks2][1]);
            pa[1] = ex2h2(sacc[2 * ks2][2], sacc[2 * ks2][3]);
            pa[2] = ex2h2(sacc[2 * ks2 + 1][0], sacc[2 * ks2 + 1][1]);
            pa[3] = ex2h2(sacc[2 * ks2 + 1][2], sacc[2 * ks2 + 1][3]);

            uint32_t ones[2] = {ONE2, ONE2};
            mma_f16(lacc, pa, ones);

            ma[0] = m02r[ks2].x; ma[1] = m13r[ks2].x;
            ma[2] = m02r[ks2].y; ma[3] = m13r[ks2].y;
#pragma unroll
            for (int nt2 = 0; nt2 < 8; nt2++) {
                uint2 uv = Vsb[(nt2 * 8 + lr) * VF_LD + ks2 * 4 + lc];
                uint32_t vb[2] = {uv.x, uv.y};
                mma_f16(oacc[nt2], pa, vb);
                mma_f16(macc[nt2], ma, vb);
            }
        }

        if (kt + 1 < 8) {
            CP_WAIT(0);
            __syncthreads();
        }
    }

    // ---- epilogue ----
    const float inv0 = 1.0f / lacc[0];
    const float inv1 = 1.0f / lacc[2];
    const int grow = qt * 64 + wm * 16 + lr;
#pragma unroll
    for (int nt2 = 0; nt2 < 8; nt2++) {
        int gn = h * HD + nt2 * 8 + (lc << 1);
        float2 v0 = make_float2(oacc[nt2][0] * inv0 + macc[nt2][0],
                                oacc[nt2][1] * inv0 + macc[nt2][1]);
        float2 v1 = make_float2(oacc[nt2][2] * inv1 + macc[nt2][2],
                                oacc[nt2][3] * inv1 + macc[nt2][3]);
        *(float2*)(out + ((size_t)b * SS + grow) * D_MODEL + gn) = v0;
        *(float2*)(out + ((size_t)b * SS + grow + 8) * D_MODEL + gn) = v1;
    }
}

// ===========================================================================
extern "C" void kernel_launch(void* const* d_in, const int* in_sizes, int n_in,
                              void* d_out, int out_size)
{
    const float* x    = (const float*)d_in[0];
    const float* y    = (const float*)d_in[1];
    const float* z    = (const float*)d_in[2];
    const float* mask = (const float*)d_in[3];
    const float* wq   = (const float*)d_in[4];
    const float* bq   = (const float*)d_in[5];
    const float* wk   = (const float*)d_in[6];
    const float* bk   = (const float*)d_in[7];
    const float* wv   = (const float*)d_in[8];
    const float* bv   = (const float*)d_in[9];
    float* out = (float*)d_out;

    cudaFuncSetAttribute(proj_mma,
                         cudaFuncAttributeMaxDynamicSharedMemorySize, SMEM_PROJ);
    cudaFuncSetAttribute(flash_kernel,
                         cudaFuncAttributeMaxDynamicSharedMemorySize, SMEM_FLASH);

    dim3 g0((MROWS * 256 + 255) / 256, 7);
    cvt_kernel<<<g0, 256>>>(x, y, z, wq, wk, wv, mask);

    dim3 g1(D_MODEL / 128, MROWS / 128, 3);
    proj_mma<<<g1, 256, SMEM_PROJ>>>(bq, bk, bv);

    dim3 gv(SS / 128, BB * NH);
    vpack_kernel<<<gv, 256>>>();

    dim3 g2(SS / 64, BB * NH);
    flash_kernel<<<g2, 128, SMEM_FLASH>>>(out);
}